// round 3
// baseline (speedup 1.0000x reference)
#include <cuda_runtime.h>
#include <cuda_bf16.h>
#include <math.h>

// Problem constants
#define T_ 2048
#define B_ 2
#define E_ 768
#define H_ 12
#define D_ 64
#define F_ 3072
#define M_ (T_ * B_)   // 4096 rows

// ---------------------------------------------------------------------------
// Scratch (device globals — no cudaMalloc allowed)
// ---------------------------------------------------------------------------
__device__ float g_q[M_ * E_];
__device__ float g_k[M_ * E_];
__device__ float g_v[M_ * E_];
__device__ float g_ctx[M_ * E_];
__device__ float g_t0[M_ * E_];   // attn_out, later h2
__device__ float g_x1[M_ * E_];
__device__ float g_h1[M_ * F_];

// ---------------------------------------------------------------------------
// Generic SGEMM: C[M,N] = A[M,K] @ B[K,N] + bias[N], optional ReLU
// BM=128 BN=128 BK=16, 256 threads, 8x8 per-thread tile.
// All shapes used are exact multiples of the tile -> no bounds checks.
// ---------------------------------------------------------------------------
__global__ void __launch_bounds__(256)
sgemm_bias_kernel(const float* __restrict__ A, const float* __restrict__ Bm,
                  const float* __restrict__ bias, float* __restrict__ C,
                  int Mdim, int Ndim, int Kdim, int relu)
{
    __shared__ float As[16][128];
    __shared__ float Bs[16][128];

    const int tid = threadIdx.x;
    const int by = blockIdx.y * 128;
    const int bx = blockIdx.x * 128;

    const int aRow = tid >> 2;            // 0..63 (plus +64)
    const int aCol = (tid & 3) << 2;      // 0,4,8,12
    const int bRow = tid >> 5;            // 0..7 (plus +8)
    const int bCol = (tid & 31) << 2;     // 0..124

    const int ty = tid >> 4;              // 0..15
    const int tx = tid & 15;              // 0..15

    float acc[8][8];
#pragma unroll
    for (int m = 0; m < 8; m++)
#pragma unroll
        for (int n = 0; n < 8; n++) acc[m][n] = 0.f;

    for (int k0 = 0; k0 < Kdim; k0 += 16) {
#pragma unroll
        for (int i = 0; i < 2; i++) {
            float4 v = *(const float4*)&A[(size_t)(by + aRow + i * 64) * Kdim + k0 + aCol];
            As[aCol + 0][aRow + i * 64] = v.x;
            As[aCol + 1][aRow + i * 64] = v.y;
            As[aCol + 2][aRow + i * 64] = v.z;
            As[aCol + 3][aRow + i * 64] = v.w;
        }
#pragma unroll
        for (int i = 0; i < 2; i++) {
            *(float4*)&Bs[bRow + i * 8][bCol] =
                *(const float4*)&Bm[(size_t)(k0 + bRow + i * 8) * Ndim + bx + bCol];
        }
        __syncthreads();

#pragma unroll
        for (int kk = 0; kk < 16; kk++) {
            float ar[8], br[8];
#pragma unroll
            for (int m = 0; m < 8; m++) ar[m] = As[kk][ty * 8 + m];
#pragma unroll
            for (int n = 0; n < 8; n++) br[n] = Bs[kk][tx * 8 + n];
#pragma unroll
            for (int m = 0; m < 8; m++)
#pragma unroll
                for (int n = 0; n < 8; n++)
                    acc[m][n] += ar[m] * br[n];
        }
        __syncthreads();
    }

#pragma unroll
    for (int m = 0; m < 8; m++) {
        const int row = by + ty * 8 + m;
#pragma unroll
        for (int n = 0; n < 8; n += 4) {
            const int col = bx + tx * 8 + n;
            float4 bv = *(const float4*)&bias[col];
            float4 w;
            w.x = acc[m][n + 0] + bv.x;
            w.y = acc[m][n + 1] + bv.y;
            w.z = acc[m][n + 2] + bv.z;
            w.w = acc[m][n + 3] + bv.w;
            if (relu) {
                w.x = fmaxf(w.x, 0.f); w.y = fmaxf(w.y, 0.f);
                w.z = fmaxf(w.z, 0.f); w.w = fmaxf(w.w, 0.f);
            }
            *(float4*)&C[(size_t)row * Ndim + col] = w;
        }
    }
}

// ---------------------------------------------------------------------------
// Flash attention: per block = one (b,h) and 64 query rows. Bc=32 key cols
// per iteration, online softmax, mask read from key_padding_mask [B,T] (int32).
// ctx layout matches [T,B,H,D] == matrix [4096, 768] with col = h*64+d.
// ---------------------------------------------------------------------------
__global__ void __launch_bounds__(256)
flash_attn_kernel(const float* __restrict__ Q, const float* __restrict__ K,
                  const float* __restrict__ V, const int* __restrict__ mask,
                  float* __restrict__ ctx)
{
    const int t0 = blockIdx.x * 64;
    const int bh = blockIdx.y;
    const int b = bh / H_;
    const int h = bh % H_;
    const int tid = threadIdx.x;

    __shared__ float Qs[64][65];
    __shared__ float Ks[32][65];
    __shared__ float Vs[32][65];
    __shared__ float Ss[64][33];
    __shared__ float mrow[64], lrow[64], arow[64];
    __shared__ int mk[32];

    // load Q tile (64 x 64)
#pragma unroll
    for (int i = 0; i < 4; i++) {
        int id = tid + 256 * i;
        int r = id >> 4;
        int c = (id & 15) * 4;
        float4 v = *(const float4*)&Q[((size_t)(t0 + r) * B_ + b) * E_ + h * 64 + c];
        Qs[r][c + 0] = v.x; Qs[r][c + 1] = v.y; Qs[r][c + 2] = v.z; Qs[r][c + 3] = v.w;
    }
    if (tid < 64) { mrow[tid] = -INFINITY; lrow[tid] = 0.f; }

    float o[4][4];
#pragma unroll
    for (int m = 0; m < 4; m++)
#pragma unroll
        for (int n = 0; n < 4; n++) o[m][n] = 0.f;

    const int ty = tid >> 4;   // 0..15 -> rows ty*4..+3
    const int tx = tid & 15;   // 0..15 -> S cols tx*2..+1, O cols tx*4..+3

    for (int s0 = 0; s0 < T_; s0 += 32) {
        __syncthreads();  // previous iter consumers done before overwriting smem
        // load K, V tiles (32 x 64)
#pragma unroll
        for (int i = 0; i < 2; i++) {
            int id = tid + 256 * i;
            int r = id >> 4;
            int c = (id & 15) * 4;
            size_t gofs = ((size_t)(s0 + r) * B_ + b) * E_ + h * 64 + c;
            float4 kv = *(const float4*)&K[gofs];
            Ks[r][c + 0] = kv.x; Ks[r][c + 1] = kv.y; Ks[r][c + 2] = kv.z; Ks[r][c + 3] = kv.w;
            float4 vv = *(const float4*)&V[gofs];
            Vs[r][c + 0] = vv.x; Vs[r][c + 1] = vv.y; Vs[r][c + 2] = vv.z; Vs[r][c + 3] = vv.w;
        }
        if (tid < 32) mk[tid] = mask[(size_t)b * T_ + s0 + tid];
        __syncthreads();

        // S = Q K^T * scale  (64 x 32), each thread 4x2
        float s2[4][2];
#pragma unroll
        for (int m = 0; m < 4; m++) { s2[m][0] = 0.f; s2[m][1] = 0.f; }
#pragma unroll
        for (int d = 0; d < 64; d++) {
            float q0 = Qs[ty * 4 + 0][d];
            float q1 = Qs[ty * 4 + 1][d];
            float q2 = Qs[ty * 4 + 2][d];
            float q3 = Qs[ty * 4 + 3][d];
            float k0 = Ks[tx * 2 + 0][d];
            float k1 = Ks[tx * 2 + 1][d];
            s2[0][0] += q0 * k0; s2[0][1] += q0 * k1;
            s2[1][0] += q1 * k0; s2[1][1] += q1 * k1;
            s2[2][0] += q2 * k0; s2[2][1] += q2 * k1;
            s2[3][0] += q3 * k0; s2[3][1] += q3 * k1;
        }
#pragma unroll
        for (int m = 0; m < 4; m++)
#pragma unroll
            for (int n = 0; n < 2; n++) {
                float val = s2[m][n] * 0.125f;  // 1/sqrt(64)
                if (mk[tx * 2 + n]) val = -INFINITY;
                Ss[ty * 4 + m][tx * 2 + n] = val;
            }
        __syncthreads();

        // online softmax row stats (one thread per row)
        if (tid < 64) {
            float mo = mrow[tid];
            float mx = mo;
#pragma unroll
            for (int c = 0; c < 32; c++) mx = fmaxf(mx, Ss[tid][c]);
            float alpha = 1.f, sum = 0.f;
            if (mx > -INFINITY) {
                alpha = __expf(mo - mx);   // mo=-inf -> 0
#pragma unroll
                for (int c = 0; c < 32; c++) {
                    float p = __expf(Ss[tid][c] - mx);
                    Ss[tid][c] = p;
                    sum += p;
                }
            } else {
#pragma unroll
                for (int c = 0; c < 32; c++) Ss[tid][c] = 0.f;
            }
            lrow[tid] = lrow[tid] * alpha + sum;
            mrow[tid] = mx;
            arow[tid] = alpha;
        }
        __syncthreads();

        // O = O*alpha + P @ V  (64 x 64), each thread 4x4
        float a0 = arow[ty * 4 + 0], a1 = arow[ty * 4 + 1];
        float a2 = arow[ty * 4 + 2], a3 = arow[ty * 4 + 3];
#pragma unroll
        for (int n = 0; n < 4; n++) {
            o[0][n] *= a0; o[1][n] *= a1; o[2][n] *= a2; o[3][n] *= a3;
        }
#pragma unroll
        for (int s = 0; s < 32; s++) {
            float p0 = Ss[ty * 4 + 0][s];
            float p1 = Ss[ty * 4 + 1][s];
            float p2 = Ss[ty * 4 + 2][s];
            float p3 = Ss[ty * 4 + 3][s];
            float v0 = Vs[s][tx * 4 + 0];
            float v1 = Vs[s][tx * 4 + 1];
            float v2 = Vs[s][tx * 4 + 2];
            float v3 = Vs[s][tx * 4 + 3];
            o[0][0] += p0 * v0; o[0][1] += p0 * v1; o[0][2] += p0 * v2; o[0][3] += p0 * v3;
            o[1][0] += p1 * v0; o[1][1] += p1 * v1; o[1][2] += p1 * v2; o[1][3] += p1 * v3;
            o[2][0] += p2 * v0; o[2][1] += p2 * v1; o[2][2] += p2 * v2; o[2][3] += p2 * v3;
            o[3][0] += p3 * v0; o[3][1] += p3 * v1; o[3][2] += p3 * v2; o[3][3] += p3 * v3;
        }
    }

    // writeout: ctx[(t,b), h*64 + col] = O / l
#pragma unroll
    for (int m = 0; m < 4; m++) {
        float inv = 1.f / lrow[ty * 4 + m];
        float4 w;
        w.x = o[m][0] * inv; w.y = o[m][1] * inv;
        w.z = o[m][2] * inv; w.w = o[m][3] * inv;
        *(float4*)&ctx[((size_t)(t0 + ty * 4 + m) * B_ + b) * E_ + h * 64 + tx * 4] = w;
    }
}

// ---------------------------------------------------------------------------
// Fused add-residual + LayerNorm. One block (256 thr) per row, E=768.
// ---------------------------------------------------------------------------
__device__ __forceinline__ float warpReduceSum(float v) {
#pragma unroll
    for (int o = 16; o; o >>= 1) v += __shfl_xor_sync(0xffffffffu, v, o);
    return v;
}

__global__ void __launch_bounds__(256)
add_ln_kernel(const float* __restrict__ a, const float* __restrict__ r,
              const float* __restrict__ g, const float* __restrict__ be,
              float* __restrict__ out)
{
    const int row = blockIdx.x;
    const int tid = threadIdx.x;
    const float* pa = a + (size_t)row * E_;
    const float* pr = r + (size_t)row * E_;

    float v0 = pa[tid] + pr[tid];
    float v1 = pa[tid + 256] + pr[tid + 256];
    float v2 = pa[tid + 512] + pr[tid + 512];

    __shared__ float red[8];
    const int wid = tid >> 5, lane = tid & 31;

    float s = warpReduceSum(v0 + v1 + v2);
    if (lane == 0) red[wid] = s;
    __syncthreads();
    float tot = 0.f;
#pragma unroll
    for (int i = 0; i < 8; i++) tot += red[i];
    const float mean = tot * (1.f / (float)E_);

    float d0 = v0 - mean, d1 = v1 - mean, d2 = v2 - mean;
    float sq = warpReduceSum(d0 * d0 + d1 * d1 + d2 * d2);
    __syncthreads();
    if (lane == 0) red[wid] = sq;
    __syncthreads();
    tot = 0.f;
#pragma unroll
    for (int i = 0; i < 8; i++) tot += red[i];
    const float inv = rsqrtf(tot * (1.f / (float)E_) + 1e-5f);

    float* po = out + (size_t)row * E_;
    po[tid]       = d0 * inv * g[tid]       + be[tid];
    po[tid + 256] = d1 * inv * g[tid + 256] + be[tid + 256];
    po[tid + 512] = d2 * inv * g[tid + 512] + be[tid + 512];
}

// ---------------------------------------------------------------------------
// Launch
// ---------------------------------------------------------------------------
extern "C" void kernel_launch(void* const* d_in, const int* in_sizes, int n_in,
                              void* d_out, int out_size)
{
    const float* state = (const float*)d_in[0];
    const int* mask = (const int*)d_in[1];
    const float* Wq = (const float*)d_in[2];
    const float* bq = (const float*)d_in[3];
    const float* Wk = (const float*)d_in[4];
    const float* bk = (const float*)d_in[5];
    const float* Wv = (const float*)d_in[6];
    const float* bv = (const float*)d_in[7];
    const float* Wo = (const float*)d_in[8];
    const float* bo = (const float*)d_in[9];
    const float* ln1g = (const float*)d_in[10];
    const float* ln1b = (const float*)d_in[11];
    const float* W1 = (const float*)d_in[12];
    const float* b1 = (const float*)d_in[13];
    const float* W2 = (const float*)d_in[14];
    const float* b2 = (const float*)d_in[15];
    const float* ln2g = (const float*)d_in[16];
    const float* ln2b = (const float*)d_in[17];
    float* out = (float*)d_out;

    float *qp, *kp, *vp, *ctxp, *t0p, *x1p, *h1p;
    cudaGetSymbolAddress((void**)&qp,  g_q);
    cudaGetSymbolAddress((void**)&kp,  g_k);
    cudaGetSymbolAddress((void**)&vp,  g_v);
    cudaGetSymbolAddress((void**)&ctxp, g_ctx);
    cudaGetSymbolAddress((void**)&t0p, g_t0);
    cudaGetSymbolAddress((void**)&x1p, g_x1);
    cudaGetSymbolAddress((void**)&h1p, g_h1);

    dim3 gemmE(E_ / 128, M_ / 128);   // (6, 32)
    dim3 gemmF(F_ / 128, M_ / 128);   // (24, 32)

    // QKV projections
    sgemm_bias_kernel<<<gemmE, 256>>>(state, Wq, bq, qp, M_, E_, E_, 0);
    sgemm_bias_kernel<<<gemmE, 256>>>(state, Wk, bk, kp, M_, E_, E_, 0);
    sgemm_bias_kernel<<<gemmE, 256>>>(state, Wv, bv, vp, M_, E_, E_, 0);

    // attention
    flash_attn_kernel<<<dim3(T_ / 64, B_ * H_), 256>>>(qp, kp, vp, mask, ctxp);

    // output projection + LN1
    sgemm_bias_kernel<<<gemmE, 256>>>(ctxp, Wo, bo, t0p, M_, E_, E_, 0);
    add_ln_kernel<<<M_, 256>>>(t0p, state, ln1g, ln1b, x1p);

    // FFN + LN2
    sgemm_bias_kernel<<<gemmF, 256>>>(x1p, W1, b1, h1p, M_, F_, E_, 1);
    sgemm_bias_kernel<<<gemmE, 256>>>(h1p, W2, b2, t0p, M_, E_, F_, 0);
    add_ln_kernel<<<M_, 256>>>(t0p, x1p, ln2g, ln2b, out);
}

// round 7
// speedup vs baseline: 1.1908x; 1.1908x over previous
#include <cuda_runtime.h>
#include <cuda_bf16.h>
#include <math.h>
#include <stdint.h>

// Problem constants
#define T_ 2048
#define B_ 2
#define E_ 768
#define H_ 12
#define D_ 64
#define F_ 3072
#define M_ (T_ * B_)   // 4096 rows

// ---------------------------------------------------------------------------
// Scratch (device globals — no cudaMalloc allowed)
// ---------------------------------------------------------------------------
__device__ float g_q[M_ * E_];
__device__ float g_k[M_ * E_];
__device__ float g_v[M_ * E_];
__device__ float g_ctx[M_ * E_];
__device__ float g_t0[M_ * E_];
__device__ float g_x1[M_ * E_];
__device__ float g_h1[M_ * F_];
// transposed weights (B operand must be [N,K] row-major = K-contiguous)
__device__ float g_wqT[E_ * E_];
__device__ float g_wkT[E_ * E_];
__device__ float g_wvT[E_ * E_];
__device__ float g_woT[E_ * E_];
__device__ float g_w1T[E_ * F_];
__device__ float g_w2T[E_ * F_];

// ---------------------------------------------------------------------------
// Helpers (baseline PTX only — compute_103 virtual arch, no tcgen05/TMA-a)
// ---------------------------------------------------------------------------
__device__ __forceinline__ uint32_t smem_u32(const void* p) {
    uint32_t a;
    asm("{ .reg .u64 t; cvta.to.shared.u64 t, %1; cvt.u32.u64 %0, t; }" : "=r"(a) : "l"(p));
    return a;
}
__device__ __forceinline__ uint32_t f2tf32(float x) {
    uint32_t r;
    asm("cvt.rna.tf32.f32 %0, %1;" : "=r"(r) : "f"(x));
    return r;
}
__device__ __forceinline__ void cp16(uint32_t dst, const void* src) {
    asm volatile("cp.async.cg.shared.global [%0], [%1], 16;" :: "r"(dst), "l"(src));
}
#define CP_COMMIT() asm volatile("cp.async.commit_group;" ::: "memory")
#define CP_WAIT(n)  asm volatile("cp.async.wait_group %0;" :: "n"(n) : "memory")

// mma.sync m16n8k8 tf32: D += A*B (fp32 accumulate in registers)
__device__ __forceinline__ void mma_tf32(float* d, const uint32_t* a, const uint32_t* b) {
    asm volatile("mma.sync.aligned.m16n8k8.row.col.f32.tf32.tf32.f32 "
                 "{%0,%1,%2,%3}, {%4,%5,%6,%7}, {%8,%9}, {%0,%1,%2,%3};"
                 : "+f"(d[0]), "+f"(d[1]), "+f"(d[2]), "+f"(d[3])
                 : "r"(a[0]), "r"(a[1]), "r"(a[2]), "r"(a[3]), "r"(b[0]), "r"(b[1]));
}

// ---------------------------------------------------------------------------
// Weight transpose: out[C,R] = in[R,C]^T. All dims multiples of 32.
// ---------------------------------------------------------------------------
__global__ void __launch_bounds__(256)
transpose_kernel(const float* __restrict__ in, float* __restrict__ out, int R, int C)
{
    __shared__ float t[32][33];
    const int bx = blockIdx.x * 32, by = blockIdx.y * 32;
    const int x = bx + threadIdx.x;
#pragma unroll
    for (int j = 0; j < 32; j += 8)
        t[threadIdx.y + j][threadIdx.x] = in[(size_t)(by + threadIdx.y + j) * C + x];
    __syncthreads();
    const int ox = by + threadIdx.x;
#pragma unroll
    for (int j = 0; j < 32; j += 8)
        out[(size_t)(bx + threadIdx.y + j) * R + ox] = t[threadIdx.x][threadIdx.y + j];
}

// ---------------------------------------------------------------------------
// HMMA 3xTF32 GEMM: C[M,N] = A[M,K] @ Bt[N,K]^T + bias, optional ReLU.
// CTA tile 128x128x32, 256 threads (8 warps, 2x4), warp tile 64x32.
// SMEM holds raw fp32 (stride-36 padded rows, conflict-free frag loads);
// hi/lo tf32 split happens in registers. cp.async double buffering.
// fp32-equivalent precision: AhiBhi + AhiBlo + AloBhi.
// ---------------------------------------------------------------------------
#define GS_STRIDE 36                    // floats per smem row (128B+pad -> 4g+c banks)
#define GS_TILE   (128 * GS_STRIDE)     // 4608 floats per matrix per stage
#define GS_STAGE  (2 * GS_TILE)         // A + B
#define GEMM_SMEM (2 * GS_STAGE * 4)    // 2 stages, bytes = 73728

__global__ void __launch_bounds__(256)
gemm_tf32_kernel(const float* __restrict__ A, const float* __restrict__ Bt,
                 const float* __restrict__ bias, float* __restrict__ C,
                 int Kdim, int Ndim, int relu)
{
    extern __shared__ float sm[];
    const uint32_t sb = smem_u32(sm);
    const int tid = threadIdx.x;
    const int wid = tid >> 5;
    const int lane = tid & 31;
    const int by = blockIdx.y * 128;
    const int bx = blockIdx.x * 128;
    const int warp_m = (wid >> 2) * 64;   // 0 or 64
    const int warp_n = (wid & 3) * 32;    // 0,32,64,96
    const int g = lane >> 2;              // 0..7
    const int c = lane & 3;               // 0..3

    float acc[4][4][4];
#pragma unroll
    for (int mt = 0; mt < 4; mt++)
#pragma unroll
        for (int nt = 0; nt < 4; nt++)
#pragma unroll
            for (int i = 0; i < 4; i++) acc[mt][nt][i] = 0.f;

    const int NT = Kdim / 32;

    // stage loader: 128x32 fp32 tile each for A and B
    auto load_stage = [&](int buf, int k0) {
        const uint32_t sA = sb + (uint32_t)(buf * GS_STAGE) * 4u;
        const uint32_t sB = sA + (uint32_t)GS_TILE * 4u;
#pragma unroll
        for (int i = 0; i < 4; i++) {
            const int id = tid + i * 256;       // 0..1023
            const int row = id >> 3;            // 0..127
            const int c4 = id & 7;              // 0..7
            const uint32_t so = (uint32_t)(row * GS_STRIDE + c4 * 4) * 4u;
            cp16(sA + so, &A[(size_t)(by + row) * Kdim + k0 + c4 * 4]);
            cp16(sB + so, &Bt[(size_t)(bx + row) * Kdim + k0 + c4 * 4]);
        }
        CP_COMMIT();
    };

    load_stage(0, 0);

    for (int kt = 0; kt < NT; kt++) {
        if (kt + 1 < NT) {
            load_stage((kt + 1) & 1, (kt + 1) * 32);
            CP_WAIT(1);
        } else {
            CP_WAIT(0);
        }
        __syncthreads();

        const float* As = sm + (kt & 1) * GS_STAGE;
        const float* Bs = As + GS_TILE;

#pragma unroll
        for (int k8 = 0; k8 < 4; k8++) {
            const int kb = k8 * 8;
            uint32_t ahi[4][4], alo[4][4];
#pragma unroll
            for (int mt = 0; mt < 4; mt++) {
                const int r = warp_m + mt * 16 + g;
                const float x0 = As[r * GS_STRIDE + kb + c];
                const float x1 = As[(r + 8) * GS_STRIDE + kb + c];
                const float x2 = As[r * GS_STRIDE + kb + c + 4];
                const float x3 = As[(r + 8) * GS_STRIDE + kb + c + 4];
                ahi[mt][0] = f2tf32(x0); alo[mt][0] = f2tf32(x0 - __uint_as_float(ahi[mt][0]));
                ahi[mt][1] = f2tf32(x1); alo[mt][1] = f2tf32(x1 - __uint_as_float(ahi[mt][1]));
                ahi[mt][2] = f2tf32(x2); alo[mt][2] = f2tf32(x2 - __uint_as_float(ahi[mt][2]));
                ahi[mt][3] = f2tf32(x3); alo[mt][3] = f2tf32(x3 - __uint_as_float(ahi[mt][3]));
            }
            uint32_t bhi[4][2], blo[4][2];
#pragma unroll
            for (int nt = 0; nt < 4; nt++) {
                const int n = warp_n + nt * 8 + g;
                const float y0 = Bs[n * GS_STRIDE + kb + c];
                const float y1 = Bs[n * GS_STRIDE + kb + c + 4];
                bhi[nt][0] = f2tf32(y0); blo[nt][0] = f2tf32(y0 - __uint_as_float(bhi[nt][0]));
                bhi[nt][1] = f2tf32(y1); blo[nt][1] = f2tf32(y1 - __uint_as_float(bhi[nt][1]));
            }
#pragma unroll
            for (int mt = 0; mt < 4; mt++)
#pragma unroll
                for (int nt = 0; nt < 4; nt++) {
                    mma_tf32(acc[mt][nt], ahi[mt], bhi[nt]);
                    mma_tf32(acc[mt][nt], ahi[mt], blo[nt]);
                    mma_tf32(acc[mt][nt], alo[mt], bhi[nt]);
                }
        }
        __syncthreads();   // compute done before next load overwrites this buffer
    }

    // epilogue: registers -> gmem with bias (+ReLU)
#pragma unroll
    for (int mt = 0; mt < 4; mt++) {
        const int r0 = by + warp_m + mt * 16 + g;
#pragma unroll
        for (int nt = 0; nt < 4; nt++) {
            const int c0 = bx + warp_n + nt * 8 + 2 * c;
            const float b0 = bias[c0], b1 = bias[c0 + 1];
            float2 v0, v1;
            v0.x = acc[mt][nt][0] + b0; v0.y = acc[mt][nt][1] + b1;
            v1.x = acc[mt][nt][2] + b0; v1.y = acc[mt][nt][3] + b1;
            if (relu) {
                v0.x = fmaxf(v0.x, 0.f); v0.y = fmaxf(v0.y, 0.f);
                v1.x = fmaxf(v1.x, 0.f); v1.y = fmaxf(v1.y, 0.f);
            }
            *(float2*)&C[(size_t)r0 * Ndim + c0] = v0;
            *(float2*)&C[(size_t)(r0 + 8) * Ndim + c0] = v1;
        }
    }
}

// ---------------------------------------------------------------------------
// Flash attention (unchanged from R3-passing version)
// ---------------------------------------------------------------------------
__global__ void __launch_bounds__(256)
flash_attn_kernel(const float* __restrict__ Q, const float* __restrict__ K,
                  const float* __restrict__ V, const int* __restrict__ mask,
                  float* __restrict__ ctx)
{
    const int t0 = blockIdx.x * 64;
    const int bh = blockIdx.y;
    const int b = bh / H_;
    const int h = bh % H_;
    const int tid = threadIdx.x;

    __shared__ float Qs[64][65];
    __shared__ float Ks[32][65];
    __shared__ float Vs[32][65];
    __shared__ float Ss[64][33];
    __shared__ float mrow[64], lrow[64], arow[64];
    __shared__ int mk[32];

#pragma unroll
    for (int i = 0; i < 4; i++) {
        int id = tid + 256 * i;
        int r = id >> 4;
        int c = (id & 15) * 4;
        float4 v = *(const float4*)&Q[((size_t)(t0 + r) * B_ + b) * E_ + h * 64 + c];
        Qs[r][c + 0] = v.x; Qs[r][c + 1] = v.y; Qs[r][c + 2] = v.z; Qs[r][c + 3] = v.w;
    }
    if (tid < 64) { mrow[tid] = -INFINITY; lrow[tid] = 0.f; }

    float o[4][4];
#pragma unroll
    for (int m = 0; m < 4; m++)
#pragma unroll
        for (int n = 0; n < 4; n++) o[m][n] = 0.f;

    const int ty = tid >> 4;
    const int tx = tid & 15;

    for (int s0 = 0; s0 < T_; s0 += 32) {
        __syncthreads();
#pragma unroll
        for (int i = 0; i < 2; i++) {
            int id = tid + 256 * i;
            int r = id >> 4;
            int c = (id & 15) * 4;
            size_t gofs = ((size_t)(s0 + r) * B_ + b) * E_ + h * 64 + c;
            float4 kv = *(const float4*)&K[gofs];
            Ks[r][c + 0] = kv.x; Ks[r][c + 1] = kv.y; Ks[r][c + 2] = kv.z; Ks[r][c + 3] = kv.w;
            float4 vv = *(const float4*)&V[gofs];
            Vs[r][c + 0] = vv.x; Vs[r][c + 1] = vv.y; Vs[r][c + 2] = vv.z; Vs[r][c + 3] = vv.w;
        }
        if (tid < 32) mk[tid] = mask[(size_t)b * T_ + s0 + tid];
        __syncthreads();

        float s2[4][2];
#pragma unroll
        for (int m = 0; m < 4; m++) { s2[m][0] = 0.f; s2[m][1] = 0.f; }
#pragma unroll
        for (int d = 0; d < 64; d++) {
            float q0 = Qs[ty * 4 + 0][d];
            float q1 = Qs[ty * 4 + 1][d];
            float q2 = Qs[ty * 4 + 2][d];
            float q3 = Qs[ty * 4 + 3][d];
            float k0 = Ks[tx * 2 + 0][d];
            float k1 = Ks[tx * 2 + 1][d];
            s2[0][0] += q0 * k0; s2[0][1] += q0 * k1;
            s2[1][0] += q1 * k0; s2[1][1] += q1 * k1;
            s2[2][0] += q2 * k0; s2[2][1] += q2 * k1;
            s2[3][0] += q3 * k0; s2[3][1] += q3 * k1;
        }
#pragma unroll
        for (int m = 0; m < 4; m++)
#pragma unroll
            for (int n = 0; n < 2; n++) {
                float val = s2[m][n] * 0.125f;
                if (mk[tx * 2 + n]) val = -INFINITY;
                Ss[ty * 4 + m][tx * 2 + n] = val;
            }
        __syncthreads();

        if (tid < 64) {
            float mo = mrow[tid];
            float mx = mo;
#pragma unroll
            for (int c = 0; c < 32; c++) mx = fmaxf(mx, Ss[tid][c]);
            float alpha = 1.f, sum = 0.f;
            if (mx > -INFINITY) {
                alpha = __expf(mo - mx);
#pragma unroll
                for (int c = 0; c < 32; c++) {
                    float p = __expf(Ss[tid][c] - mx);
                    Ss[tid][c] = p;
                    sum += p;
                }
            } else {
#pragma unroll
                for (int c = 0; c < 32; c++) Ss[tid][c] = 0.f;
            }
            lrow[tid] = lrow[tid] * alpha + sum;
            mrow[tid] = mx;
            arow[tid] = alpha;
        }
        __syncthreads();

        float a0 = arow[ty * 4 + 0], a1 = arow[ty * 4 + 1];
        float a2 = arow[ty * 4 + 2], a3 = arow[ty * 4 + 3];
#pragma unroll
        for (int n = 0; n < 4; n++) {
            o[0][n] *= a0; o[1][n] *= a1; o[2][n] *= a2; o[3][n] *= a3;
        }
#pragma unroll
        for (int s = 0; s < 32; s++) {
            float p0 = Ss[ty * 4 + 0][s];
            float p1 = Ss[ty * 4 + 1][s];
            float p2 = Ss[ty * 4 + 2][s];
            float p3 = Ss[ty * 4 + 3][s];
            float v0 = Vs[s][tx * 4 + 0];
            float v1 = Vs[s][tx * 4 + 1];
            float v2 = Vs[s][tx * 4 + 2];
            float v3 = Vs[s][tx * 4 + 3];
            o[0][0] += p0 * v0; o[0][1] += p0 * v1; o[0][2] += p0 * v2; o[0][3] += p0 * v3;
            o[1][0] += p1 * v0; o[1][1] += p1 * v1; o[1][2] += p1 * v2; o[1][3] += p1 * v3;
            o[2][0] += p2 * v0; o[2][1] += p2 * v1; o[2][2] += p2 * v2; o[2][3] += p2 * v3;
            o[3][0] += p3 * v0; o[3][1] += p3 * v1; o[3][2] += p3 * v2; o[3][3] += p3 * v3;
        }
    }

#pragma unroll
    for (int m = 0; m < 4; m++) {
        float inv = 1.f / lrow[ty * 4 + m];
        float4 w;
        w.x = o[m][0] * inv; w.y = o[m][1] * inv;
        w.z = o[m][2] * inv; w.w = o[m][3] * inv;
        *(float4*)&ctx[((size_t)(t0 + ty * 4 + m) * B_ + b) * E_ + h * 64 + tx * 4] = w;
    }
}

// ---------------------------------------------------------------------------
// Fused add-residual + LayerNorm (unchanged)
// ---------------------------------------------------------------------------
__device__ __forceinline__ float warpReduceSum(float v) {
#pragma unroll
    for (int o = 16; o; o >>= 1) v += __shfl_xor_sync(0xffffffffu, v, o);
    return v;
}

__global__ void __launch_bounds__(256)
add_ln_kernel(const float* __restrict__ a, const float* __restrict__ r,
              const float* __restrict__ g, const float* __restrict__ be,
              float* __restrict__ out)
{
    const int row = blockIdx.x;
    const int tid = threadIdx.x;
    const float* pa = a + (size_t)row * E_;
    const float* pr = r + (size_t)row * E_;

    float v0 = pa[tid] + pr[tid];
    float v1 = pa[tid + 256] + pr[tid + 256];
    float v2 = pa[tid + 512] + pr[tid + 512];

    __shared__ float red[8];
    const int wid = tid >> 5, lane = tid & 31;

    float s = warpReduceSum(v0 + v1 + v2);
    if (lane == 0) red[wid] = s;
    __syncthreads();
    float tot = 0.f;
#pragma unroll
    for (int i = 0; i < 8; i++) tot += red[i];
    const float mean = tot * (1.f / (float)E_);

    float d0 = v0 - mean, d1 = v1 - mean, d2 = v2 - mean;
    float sq = warpReduceSum(d0 * d0 + d1 * d1 + d2 * d2);
    __syncthreads();
    if (lane == 0) red[wid] = sq;
    __syncthreads();
    tot = 0.f;
#pragma unroll
    for (int i = 0; i < 8; i++) tot += red[i];
    const float inv = rsqrtf(tot * (1.f / (float)E_) + 1e-5f);

    float* po = out + (size_t)row * E_;
    po[tid]       = d0 * inv * g[tid]       + be[tid];
    po[tid + 256] = d1 * inv * g[tid + 256] + be[tid + 256];
    po[tid + 512] = d2 * inv * g[tid + 512] + be[tid + 512];
}

// ---------------------------------------------------------------------------
// Launch
// ---------------------------------------------------------------------------
extern "C" void kernel_launch(void* const* d_in, const int* in_sizes, int n_in,
                              void* d_out, int out_size)
{
    const float* state = (const float*)d_in[0];
    const int* mask = (const int*)d_in[1];
    const float* Wq = (const float*)d_in[2];
    const float* bq = (const float*)d_in[3];
    const float* Wk = (const float*)d_in[4];
    const float* bk = (const float*)d_in[5];
    const float* Wv = (const float*)d_in[6];
    const float* bv = (const float*)d_in[7];
    const float* Wo = (const float*)d_in[8];
    const float* bo = (const float*)d_in[9];
    const float* ln1g = (const float*)d_in[10];
    const float* ln1b = (const float*)d_in[11];
    const float* W1 = (const float*)d_in[12];
    const float* b1 = (const float*)d_in[13];
    const float* W2 = (const float*)d_in[14];
    const float* b2 = (const float*)d_in[15];
    const float* ln2g = (const float*)d_in[16];
    const float* ln2b = (const float*)d_in[17];
    float* out = (float*)d_out;

    float *qp, *kp, *vp, *ctxp, *t0p, *x1p, *h1p;
    float *wqT, *wkT, *wvT, *woT, *w1T, *w2T;
    cudaGetSymbolAddress((void**)&qp,  g_q);
    cudaGetSymbolAddress((void**)&kp,  g_k);
    cudaGetSymbolAddress((void**)&vp,  g_v);
    cudaGetSymbolAddress((void**)&ctxp, g_ctx);
    cudaGetSymbolAddress((void**)&t0p, g_t0);
    cudaGetSymbolAddress((void**)&x1p, g_x1);
    cudaGetSymbolAddress((void**)&h1p, g_h1);
    cudaGetSymbolAddress((void**)&wqT, g_wqT);
    cudaGetSymbolAddress((void**)&wkT, g_wkT);
    cudaGetSymbolAddress((void**)&wvT, g_wvT);
    cudaGetSymbolAddress((void**)&woT, g_woT);
    cudaGetSymbolAddress((void**)&w1T, g_w1T);
    cudaGetSymbolAddress((void**)&w2T, g_w2T);

    cudaFuncSetAttribute(gemm_tf32_kernel, cudaFuncAttributeMaxDynamicSharedMemorySize, GEMM_SMEM);

    // transpose weights so B operand is [N,K] K-contiguous
    dim3 tb(32, 8);
    transpose_kernel<<<dim3(E_ / 32, E_ / 32), tb>>>(Wq, wqT, E_, E_);
    transpose_kernel<<<dim3(E_ / 32, E_ / 32), tb>>>(Wk, wkT, E_, E_);
    transpose_kernel<<<dim3(E_ / 32, E_ / 32), tb>>>(Wv, wvT, E_, E_);
    transpose_kernel<<<dim3(E_ / 32, E_ / 32), tb>>>(Wo, woT, E_, E_);
    transpose_kernel<<<dim3(F_ / 32, E_ / 32), tb>>>(W1, w1T, E_, F_);
    transpose_kernel<<<dim3(E_ / 32, F_ / 32), tb>>>(W2, w2T, F_, E_);

    dim3 gE(E_ / 128, M_ / 128);   // (6, 32)
    dim3 gF(F_ / 128, M_ / 128);   // (24, 32)

    // QKV projections (HMMA 3xTF32)
    gemm_tf32_kernel<<<gE, 256, GEMM_SMEM>>>(state, wqT, bq, qp, E_, E_, 0);
    gemm_tf32_kernel<<<gE, 256, GEMM_SMEM>>>(state, wkT, bk, kp, E_, E_, 0);
    gemm_tf32_kernel<<<gE, 256, GEMM_SMEM>>>(state, wvT, bv, vp, E_, E_, 0);

    // attention
    flash_attn_kernel<<<dim3(T_ / 64, B_ * H_), 256>>>(qp, kp, vp, mask, ctxp);

    // output projection + LN1
    gemm_tf32_kernel<<<gE, 256, GEMM_SMEM>>>(ctxp, woT, bo, t0p, E_, E_, 0);
    add_ln_kernel<<<M_, 256>>>(t0p, state, ln1g, ln1b, x1p);

    // FFN + LN2
    gemm_tf32_kernel<<<gF, 256, GEMM_SMEM>>>(x1p, w1T, b1, h1p, E_, F_, 1);
    gemm_tf32_kernel<<<gE, 256, GEMM_SMEM>>>(h1p, w2T, b2, t0p, F_, E_, 0);
    add_ln_kernel<<<M_, 256>>>(t0p, x1p, ln2g, ln2b, out);
}

// round 8
// speedup vs baseline: 1.5387x; 1.2921x over previous
#include <cuda_runtime.h>
#include <cuda_bf16.h>
#include <math.h>
#include <stdint.h>

// Problem constants
#define T_ 2048
#define B_ 2
#define E_ 768
#define H_ 12
#define D_ 64
#define F_ 3072
#define M_ (T_ * B_)   // 4096 rows

// ---------------------------------------------------------------------------
// Scratch (device globals — no cudaMalloc allowed)
// ---------------------------------------------------------------------------
__device__ float g_q[M_ * E_];
__device__ float g_k[M_ * E_];
__device__ float g_v[M_ * E_];
__device__ float g_ctx[M_ * E_];
__device__ float g_t0[M_ * E_];
__device__ float g_x1[M_ * E_];
__device__ float g_h1[M_ * F_];
// transposed weights (B operand must be [N,K] row-major = K-contiguous)
__device__ float g_wqT[E_ * E_];
__device__ float g_wkT[E_ * E_];
__device__ float g_wvT[E_ * E_];
__device__ float g_woT[E_ * E_];
__device__ float g_w1T[E_ * F_];
__device__ float g_w2T[E_ * F_];

// ---------------------------------------------------------------------------
// Helpers (baseline PTX only — compute_103 virtual arch, no tcgen05)
// ---------------------------------------------------------------------------
__device__ __forceinline__ uint32_t f2tf32(float x) {
    uint32_t r;
    asm("cvt.rna.tf32.f32 %0, %1;" : "=r"(r) : "f"(x));
    return r;
}
__device__ __forceinline__ void cp16(uint32_t dst, const void* src) {
    asm volatile("cp.async.cg.shared.global [%0], [%1], 16;" :: "r"(dst), "l"(src));
}
__device__ __forceinline__ uint32_t smem_u32(const void* p) {
    uint32_t a;
    asm("{ .reg .u64 t; cvta.to.shared.u64 t, %1; cvt.u32.u64 %0, t; }" : "=r"(a) : "l"(p));
    return a;
}
#define CP_COMMIT() asm volatile("cp.async.commit_group;" ::: "memory")
#define CP_WAIT(n)  asm volatile("cp.async.wait_group %0;" :: "n"(n) : "memory")

// mma.sync m16n8k8 tf32: D += A*B (fp32 accumulate in registers)
__device__ __forceinline__ void mma_tf32(float* d, const uint32_t* a, const uint32_t* b) {
    asm volatile("mma.sync.aligned.m16n8k8.row.col.f32.tf32.tf32.f32 "
                 "{%0,%1,%2,%3}, {%4,%5,%6,%7}, {%8,%9}, {%0,%1,%2,%3};"
                 : "+f"(d[0]), "+f"(d[1]), "+f"(d[2]), "+f"(d[3])
                 : "r"(a[0]), "r"(a[1]), "r"(a[2]), "r"(a[3]), "r"(b[0]), "r"(b[1]));
}

// ---------------------------------------------------------------------------
// Weight transpose: out[C,R] = in[R,C]^T. All dims multiples of 32.
// ---------------------------------------------------------------------------
__global__ void __launch_bounds__(256)
transpose_kernel(const float* __restrict__ in, float* __restrict__ out, int R, int C)
{
    __shared__ float t[32][33];
    const int bx = blockIdx.x * 32, by = blockIdx.y * 32;
    const int x = bx + threadIdx.x;
#pragma unroll
    for (int j = 0; j < 32; j += 8)
        t[threadIdx.y + j][threadIdx.x] = in[(size_t)(by + threadIdx.y + j) * C + x];
    __syncthreads();
    const int ox = by + threadIdx.x;
#pragma unroll
    for (int j = 0; j < 32; j += 8)
        out[(size_t)(bx + threadIdx.y + j) * R + ox] = t[threadIdx.x][threadIdx.y + j];
}

// ---------------------------------------------------------------------------
// HMMA 3xTF32 GEMM (unchanged from R7-passing version)
// ---------------------------------------------------------------------------
#define GS_STRIDE 36
#define GS_TILE   (128 * GS_STRIDE)
#define GS_STAGE  (2 * GS_TILE)
#define GEMM_SMEM (2 * GS_STAGE * 4)

__global__ void __launch_bounds__(256)
gemm_tf32_kernel(const float* __restrict__ A, const float* __restrict__ Bt,
                 const float* __restrict__ bias, float* __restrict__ C,
                 int Kdim, int Ndim, int relu)
{
    extern __shared__ float sm[];
    const uint32_t sb = smem_u32(sm);
    const int tid = threadIdx.x;
    const int wid = tid >> 5;
    const int lane = tid & 31;
    const int by = blockIdx.y * 128;
    const int bx = blockIdx.x * 128;
    const int warp_m = (wid >> 2) * 64;
    const int warp_n = (wid & 3) * 32;
    const int g = lane >> 2;
    const int c = lane & 3;

    float acc[4][4][4];
#pragma unroll
    for (int mt = 0; mt < 4; mt++)
#pragma unroll
        for (int nt = 0; nt < 4; nt++)
#pragma unroll
            for (int i = 0; i < 4; i++) acc[mt][nt][i] = 0.f;

    const int NT = Kdim / 32;

    auto load_stage = [&](int buf, int k0) {
        const uint32_t sA = sb + (uint32_t)(buf * GS_STAGE) * 4u;
        const uint32_t sB = sA + (uint32_t)GS_TILE * 4u;
#pragma unroll
        for (int i = 0; i < 4; i++) {
            const int id = tid + i * 256;
            const int row = id >> 3;
            const int c4 = id & 7;
            const uint32_t so = (uint32_t)(row * GS_STRIDE + c4 * 4) * 4u;
            cp16(sA + so, &A[(size_t)(by + row) * Kdim + k0 + c4 * 4]);
            cp16(sB + so, &Bt[(size_t)(bx + row) * Kdim + k0 + c4 * 4]);
        }
        CP_COMMIT();
    };

    load_stage(0, 0);

    for (int kt = 0; kt < NT; kt++) {
        if (kt + 1 < NT) {
            load_stage((kt + 1) & 1, (kt + 1) * 32);
            CP_WAIT(1);
        } else {
            CP_WAIT(0);
        }
        __syncthreads();

        const float* As = sm + (kt & 1) * GS_STAGE;
        const float* Bs = As + GS_TILE;

#pragma unroll
        for (int k8 = 0; k8 < 4; k8++) {
            const int kb = k8 * 8;
            uint32_t ahi[4][4], alo[4][4];
#pragma unroll
            for (int mt = 0; mt < 4; mt++) {
                const int r = warp_m + mt * 16 + g;
                const float x0 = As[r * GS_STRIDE + kb + c];
                const float x1 = As[(r + 8) * GS_STRIDE + kb + c];
                const float x2 = As[r * GS_STRIDE + kb + c + 4];
                const float x3 = As[(r + 8) * GS_STRIDE + kb + c + 4];
                ahi[mt][0] = f2tf32(x0); alo[mt][0] = f2tf32(x0 - __uint_as_float(ahi[mt][0]));
                ahi[mt][1] = f2tf32(x1); alo[mt][1] = f2tf32(x1 - __uint_as_float(ahi[mt][1]));
                ahi[mt][2] = f2tf32(x2); alo[mt][2] = f2tf32(x2 - __uint_as_float(ahi[mt][2]));
                ahi[mt][3] = f2tf32(x3); alo[mt][3] = f2tf32(x3 - __uint_as_float(ahi[mt][3]));
            }
            uint32_t bhi[4][2], blo[4][2];
#pragma unroll
            for (int nt = 0; nt < 4; nt++) {
                const int n = warp_n + nt * 8 + g;
                const float y0 = Bs[n * GS_STRIDE + kb + c];
                const float y1 = Bs[n * GS_STRIDE + kb + c + 4];
                bhi[nt][0] = f2tf32(y0); blo[nt][0] = f2tf32(y0 - __uint_as_float(bhi[nt][0]));
                bhi[nt][1] = f2tf32(y1); blo[nt][1] = f2tf32(y1 - __uint_as_float(bhi[nt][1]));
            }
#pragma unroll
            for (int mt = 0; mt < 4; mt++)
#pragma unroll
                for (int nt = 0; nt < 4; nt++) {
                    mma_tf32(acc[mt][nt], ahi[mt], bhi[nt]);
                    mma_tf32(acc[mt][nt], ahi[mt], blo[nt]);
                    mma_tf32(acc[mt][nt], alo[mt], bhi[nt]);
                }
        }
        __syncthreads();
    }

#pragma unroll
    for (int mt = 0; mt < 4; mt++) {
        const int r0 = by + warp_m + mt * 16 + g;
#pragma unroll
        for (int nt = 0; nt < 4; nt++) {
            const int c0 = bx + warp_n + nt * 8 + 2 * c;
            const float b0 = bias[c0], b1 = bias[c0 + 1];
            float2 v0, v1;
            v0.x = acc[mt][nt][0] + b0; v0.y = acc[mt][nt][1] + b1;
            v1.x = acc[mt][nt][2] + b0; v1.y = acc[mt][nt][3] + b1;
            if (relu) {
                v0.x = fmaxf(v0.x, 0.f); v0.y = fmaxf(v0.y, 0.f);
                v1.x = fmaxf(v1.x, 0.f); v1.y = fmaxf(v1.y, 0.f);
            }
            *(float2*)&C[(size_t)r0 * Ndim + c0] = v0;
            *(float2*)&C[(size_t)(r0 + 8) * Ndim + c0] = v1;
        }
    }
}

// ---------------------------------------------------------------------------
// Tensor-core flash attention (3xTF32 mma.sync), Br=128, Bc=64.
// 8 warps; warp w owns query rows [w*16, w*16+16).
// smem (floats, stride 68 => banks 4g+c, conflict-free fragments):
//   Qs[128][68], Ks[64][68] (key-major), Vt[64][68] (d-major = V^T),
//   P[warp][16][68], mask ints [64], skip flag.
// Online softmax in registers; fully-masked key tiles skipped at runtime.
// ---------------------------------------------------------------------------
#define FA_STR 68
#define FA_QS  0
#define FA_KS  (128 * FA_STR)
#define FA_VT  (FA_KS + 64 * FA_STR)
#define FA_P   (FA_VT + 64 * FA_STR)
#define FA_MK  (FA_P + 8 * 16 * FA_STR)
#define FA_SMEM ((FA_MK + 68) * 4)

__global__ void __launch_bounds__(256, 2)
flash_attn_tc_kernel(const float* __restrict__ Q, const float* __restrict__ K,
                     const float* __restrict__ V, const int* __restrict__ mask,
                     float* __restrict__ ctx)
{
    extern __shared__ float fs[];
    int* mks = (int*)(fs + FA_MK);
    int* flg = mks + 64;

    const int t0 = blockIdx.x * 128;
    const int b = blockIdx.y / H_;
    const int h = blockIdx.y % H_;
    const int tid = threadIdx.x;
    const int w = tid >> 5, lane = tid & 31;
    const int g = lane >> 2, c = lane & 3;
    const int wm = w * 16;
    float* Pw = fs + FA_P + w * 16 * FA_STR;

    // load Q tile [128 x 64] into Qs
#pragma unroll
    for (int i = 0; i < 8; i++) {
        const int id = tid + i * 256;
        const int r = id >> 4, c4 = (id & 15) * 4;
        float4 v = *(const float4*)&Q[((size_t)(t0 + r) * B_ + b) * E_ + h * 64 + c4];
        *(float4*)&fs[FA_QS + r * FA_STR + c4] = v;
    }

    float o[8][4];
#pragma unroll
    for (int nt = 0; nt < 8; nt++)
#pragma unroll
        for (int i = 0; i < 4; i++) o[nt][i] = 0.f;
    float m0 = -INFINITY, m1 = -INFINITY, l0 = 0.f, l1 = 0.f;

    for (int s0 = 0; s0 < T_; s0 += 64) {
        __syncthreads();   // prev iter done with Ks/Vt/mks (first iter: Q visible)
        if (tid < 64) mks[tid] = mask[(size_t)b * T_ + s0 + tid];
        __syncthreads();
        if (tid < 32) {
            const int un = (mks[tid] == 0) || (mks[tid + 32] == 0);
            const unsigned bal = __ballot_sync(0xffffffffu, un);
            if (lane == 0) flg[0] = (bal == 0u);
        }
        __syncthreads();
        if (flg[0]) continue;   // whole tile masked -> zero weight -> skip

        // load K tile [64 keys x 64 d] (key-major)
#pragma unroll
        for (int i = 0; i < 4; i++) {
            const int id = tid + i * 256;
            const int r = id >> 4, c4 = (id & 15) * 4;
            float4 v = *(const float4*)&K[((size_t)(s0 + r) * B_ + b) * E_ + h * 64 + c4];
            *(float4*)&fs[FA_KS + r * FA_STR + c4] = v;
        }
        // load V tile transposed: Vt[d][key]
        {
            const int key = tid & 63;
            const int dblk = (tid >> 6) * 16;
#pragma unroll
            for (int ii = 0; ii < 4; ii++) {
                const int d0 = dblk + ii * 4;
                float4 v = *(const float4*)&V[((size_t)(s0 + key) * B_ + b) * E_ + h * 64 + d0];
                fs[FA_VT + (d0 + 0) * FA_STR + key] = v.x;
                fs[FA_VT + (d0 + 1) * FA_STR + key] = v.y;
                fs[FA_VT + (d0 + 2) * FA_STR + key] = v.z;
                fs[FA_VT + (d0 + 3) * FA_STR + key] = v.w;
            }
        }
        __syncthreads();

        // ---- S = Q K^T (16 x 64 per warp), 3xTF32 ----
        float sa[8][4];
#pragma unroll
        for (int nt = 0; nt < 8; nt++)
#pragma unroll
            for (int i = 0; i < 4; i++) sa[nt][i] = 0.f;

#pragma unroll
        for (int kk = 0; kk < 8; kk++) {
            const int kb = kk * 8;
            const float q0 = fs[FA_QS + (wm + g) * FA_STR + kb + c];
            const float q1 = fs[FA_QS + (wm + g + 8) * FA_STR + kb + c];
            const float q2 = fs[FA_QS + (wm + g) * FA_STR + kb + c + 4];
            const float q3 = fs[FA_QS + (wm + g + 8) * FA_STR + kb + c + 4];
            uint32_t qh[4], ql[4];
            qh[0] = f2tf32(q0); ql[0] = f2tf32(q0 - __uint_as_float(qh[0]));
            qh[1] = f2tf32(q1); ql[1] = f2tf32(q1 - __uint_as_float(qh[1]));
            qh[2] = f2tf32(q2); ql[2] = f2tf32(q2 - __uint_as_float(qh[2]));
            qh[3] = f2tf32(q3); ql[3] = f2tf32(q3 - __uint_as_float(qh[3]));
#pragma unroll
            for (int nt = 0; nt < 8; nt++) {
                const float y0 = fs[FA_KS + (nt * 8 + g) * FA_STR + kb + c];
                const float y1 = fs[FA_KS + (nt * 8 + g) * FA_STR + kb + c + 4];
                uint32_t bh2[2], bl2[2];
                bh2[0] = f2tf32(y0); bl2[0] = f2tf32(y0 - __uint_as_float(bh2[0]));
                bh2[1] = f2tf32(y1); bl2[1] = f2tf32(y1 - __uint_as_float(bh2[1]));
                mma_tf32(sa[nt], qh, bh2);
                mma_tf32(sa[nt], qh, bl2);
                mma_tf32(sa[nt], ql, bh2);
            }
        }

        // ---- online softmax ----
        float mx0 = -INFINITY, mx1 = -INFINITY;
#pragma unroll
        for (int nt = 0; nt < 8; nt++) {
            const int col0 = nt * 8 + 2 * c, col1 = col0 + 1;
            const bool k0m = mks[col0] != 0, k1m = mks[col1] != 0;
            float s0v = sa[nt][0] * 0.125f; if (k0m) s0v = -INFINITY;
            float s1v = sa[nt][1] * 0.125f; if (k1m) s1v = -INFINITY;
            float s2v = sa[nt][2] * 0.125f; if (k0m) s2v = -INFINITY;
            float s3v = sa[nt][3] * 0.125f; if (k1m) s3v = -INFINITY;
            sa[nt][0] = s0v; sa[nt][1] = s1v; sa[nt][2] = s2v; sa[nt][3] = s3v;
            mx0 = fmaxf(mx0, fmaxf(s0v, s1v));
            mx1 = fmaxf(mx1, fmaxf(s2v, s3v));
        }
        mx0 = fmaxf(mx0, __shfl_xor_sync(0xffffffffu, mx0, 1));
        mx0 = fmaxf(mx0, __shfl_xor_sync(0xffffffffu, mx0, 2));
        mx1 = fmaxf(mx1, __shfl_xor_sync(0xffffffffu, mx1, 1));
        mx1 = fmaxf(mx1, __shfl_xor_sync(0xffffffffu, mx1, 2));

        const float mn0 = fmaxf(m0, mx0), mn1 = fmaxf(m1, mx1);
        const float al0 = __expf(m0 - mn0), al1 = __expf(m1 - mn1);
        m0 = mn0; m1 = mn1;

        float su0 = 0.f, su1 = 0.f;
#pragma unroll
        for (int nt = 0; nt < 8; nt++) {
            const float p0 = __expf(sa[nt][0] - mn0);
            const float p1 = __expf(sa[nt][1] - mn0);
            const float p2 = __expf(sa[nt][2] - mn1);
            const float p3 = __expf(sa[nt][3] - mn1);
            su0 += p0 + p1; su1 += p2 + p3;
            float2 lo; lo.x = p0; lo.y = p1;
            float2 hi; hi.x = p2; hi.y = p3;
            *(float2*)&Pw[g * FA_STR + nt * 8 + 2 * c] = lo;
            *(float2*)&Pw[(g + 8) * FA_STR + nt * 8 + 2 * c] = hi;
        }
        su0 += __shfl_xor_sync(0xffffffffu, su0, 1);
        su0 += __shfl_xor_sync(0xffffffffu, su0, 2);
        su1 += __shfl_xor_sync(0xffffffffu, su1, 1);
        su1 += __shfl_xor_sync(0xffffffffu, su1, 2);
        l0 = l0 * al0 + su0;
        l1 = l1 * al1 + su1;
#pragma unroll
        for (int nt = 0; nt < 8; nt++) {
            o[nt][0] *= al0; o[nt][1] *= al0;
            o[nt][2] *= al1; o[nt][3] *= al1;
        }
        __syncwarp();

        // ---- O += P V (16 x 64 per warp), 3xTF32 ----
#pragma unroll
        for (int kk = 0; kk < 8; kk++) {
            const int kb = kk * 8;
            const float p0 = Pw[g * FA_STR + kb + c];
            const float p1 = Pw[(g + 8) * FA_STR + kb + c];
            const float p2 = Pw[g * FA_STR + kb + c + 4];
            const float p3 = Pw[(g + 8) * FA_STR + kb + c + 4];
            uint32_t ph[4], pl[4];
            ph[0] = f2tf32(p0); pl[0] = f2tf32(p0 - __uint_as_float(ph[0]));
            ph[1] = f2tf32(p1); pl[1] = f2tf32(p1 - __uint_as_float(ph[1]));
            ph[2] = f2tf32(p2); pl[2] = f2tf32(p2 - __uint_as_float(ph[2]));
            ph[3] = f2tf32(p3); pl[3] = f2tf32(p3 - __uint_as_float(ph[3]));
#pragma unroll
            for (int nt = 0; nt < 8; nt++) {
                const float y0 = fs[FA_VT + (nt * 8 + g) * FA_STR + kb + c];
                const float y1 = fs[FA_VT + (nt * 8 + g) * FA_STR + kb + c + 4];
                uint32_t bh2[2], bl2[2];
                bh2[0] = f2tf32(y0); bl2[0] = f2tf32(y0 - __uint_as_float(bh2[0]));
                bh2[1] = f2tf32(y1); bl2[1] = f2tf32(y1 - __uint_as_float(bh2[1]));
                mma_tf32(o[nt], ph, bh2);
                mma_tf32(o[nt], ph, bl2);
                mma_tf32(o[nt], pl, bh2);
            }
        }
    }

    // writeout: ctx[(t,b), h*64+d] = O / l
    const float i0 = 1.f / l0, i1 = 1.f / l1;
#pragma unroll
    for (int nt = 0; nt < 8; nt++) {
        const int col = h * 64 + nt * 8 + 2 * c;
        float2 a; a.x = o[nt][0] * i0; a.y = o[nt][1] * i0;
        float2 d; d.x = o[nt][2] * i1; d.y = o[nt][3] * i1;
        *(float2*)&ctx[((size_t)(t0 + wm + g) * B_ + b) * E_ + col] = a;
        *(float2*)&ctx[((size_t)(t0 + wm + g + 8) * B_ + b) * E_ + col] = d;
    }
}

// ---------------------------------------------------------------------------
// Fused add-residual + LayerNorm (unchanged)
// ---------------------------------------------------------------------------
__device__ __forceinline__ float warpReduceSum(float v) {
#pragma unroll
    for (int o = 16; o; o >>= 1) v += __shfl_xor_sync(0xffffffffu, v, o);
    return v;
}

__global__ void __launch_bounds__(256)
add_ln_kernel(const float* __restrict__ a, const float* __restrict__ r,
              const float* __restrict__ g, const float* __restrict__ be,
              float* __restrict__ out)
{
    const int row = blockIdx.x;
    const int tid = threadIdx.x;
    const float* pa = a + (size_t)row * E_;
    const float* pr = r + (size_t)row * E_;

    float v0 = pa[tid] + pr[tid];
    float v1 = pa[tid + 256] + pr[tid + 256];
    float v2 = pa[tid + 512] + pr[tid + 512];

    __shared__ float red[8];
    const int wid = tid >> 5, lane = tid & 31;

    float s = warpReduceSum(v0 + v1 + v2);
    if (lane == 0) red[wid] = s;
    __syncthreads();
    float tot = 0.f;
#pragma unroll
    for (int i = 0; i < 8; i++) tot += red[i];
    const float mean = tot * (1.f / (float)E_);

    float d0 = v0 - mean, d1 = v1 - mean, d2 = v2 - mean;
    float sq = warpReduceSum(d0 * d0 + d1 * d1 + d2 * d2);
    __syncthreads();
    if (lane == 0) red[wid] = sq;
    __syncthreads();
    tot = 0.f;
#pragma unroll
    for (int i = 0; i < 8; i++) tot += red[i];
    const float inv = rsqrtf(tot * (1.f / (float)E_) + 1e-5f);

    float* po = out + (size_t)row * E_;
    po[tid]       = d0 * inv * g[tid]       + be[tid];
    po[tid + 256] = d1 * inv * g[tid + 256] + be[tid + 256];
    po[tid + 512] = d2 * inv * g[tid + 512] + be[tid + 512];
}

// ---------------------------------------------------------------------------
// Launch
// ---------------------------------------------------------------------------
extern "C" void kernel_launch(void* const* d_in, const int* in_sizes, int n_in,
                              void* d_out, int out_size)
{
    const float* state = (const float*)d_in[0];
    const int* mask = (const int*)d_in[1];
    const float* Wq = (const float*)d_in[2];
    const float* bq = (const float*)d_in[3];
    const float* Wk = (const float*)d_in[4];
    const float* bk = (const float*)d_in[5];
    const float* Wv = (const float*)d_in[6];
    const float* bv = (const float*)d_in[7];
    const float* Wo = (const float*)d_in[8];
    const float* bo = (const float*)d_in[9];
    const float* ln1g = (const float*)d_in[10];
    const float* ln1b = (const float*)d_in[11];
    const float* W1 = (const float*)d_in[12];
    const float* b1 = (const float*)d_in[13];
    const float* W2 = (const float*)d_in[14];
    const float* b2 = (const float*)d_in[15];
    const float* ln2g = (const float*)d_in[16];
    const float* ln2b = (const float*)d_in[17];
    float* out = (float*)d_out;

    float *qp, *kp, *vp, *ctxp, *t0p, *x1p, *h1p;
    float *wqT, *wkT, *wvT, *woT, *w1T, *w2T;
    cudaGetSymbolAddress((void**)&qp,  g_q);
    cudaGetSymbolAddress((void**)&kp,  g_k);
    cudaGetSymbolAddress((void**)&vp,  g_v);
    cudaGetSymbolAddress((void**)&ctxp, g_ctx);
    cudaGetSymbolAddress((void**)&t0p, g_t0);
    cudaGetSymbolAddress((void**)&x1p, g_x1);
    cudaGetSymbolAddress((void**)&h1p, g_h1);
    cudaGetSymbolAddress((void**)&wqT, g_wqT);
    cudaGetSymbolAddress((void**)&wkT, g_wkT);
    cudaGetSymbolAddress((void**)&wvT, g_wvT);
    cudaGetSymbolAddress((void**)&woT, g_woT);
    cudaGetSymbolAddress((void**)&w1T, g_w1T);
    cudaGetSymbolAddress((void**)&w2T, g_w2T);

    cudaFuncSetAttribute(gemm_tf32_kernel, cudaFuncAttributeMaxDynamicSharedMemorySize, GEMM_SMEM);
    cudaFuncSetAttribute(flash_attn_tc_kernel, cudaFuncAttributeMaxDynamicSharedMemorySize, FA_SMEM);

    // transpose weights so B operand is [N,K] K-contiguous
    dim3 tb(32, 8);
    transpose_kernel<<<dim3(E_ / 32, E_ / 32), tb>>>(Wq, wqT, E_, E_);
    transpose_kernel<<<dim3(E_ / 32, E_ / 32), tb>>>(Wk, wkT, E_, E_);
    transpose_kernel<<<dim3(E_ / 32, E_ / 32), tb>>>(Wv, wvT, E_, E_);
    transpose_kernel<<<dim3(E_ / 32, E_ / 32), tb>>>(Wo, woT, E_, E_);
    transpose_kernel<<<dim3(F_ / 32, E_ / 32), tb>>>(W1, w1T, E_, F_);
    transpose_kernel<<<dim3(E_ / 32, F_ / 32), tb>>>(W2, w2T, F_, E_);

    dim3 gE(E_ / 128, M_ / 128);   // (6, 32)
    dim3 gF(F_ / 128, M_ / 128);   // (24, 32)

    // QKV projections (HMMA 3xTF32)
    gemm_tf32_kernel<<<gE, 256, GEMM_SMEM>>>(state, wqT, bq, qp, E_, E_, 0);
    gemm_tf32_kernel<<<gE, 256, GEMM_SMEM>>>(state, wkT, bk, kp, E_, E_, 0);
    gemm_tf32_kernel<<<gE, 256, GEMM_SMEM>>>(state, wvT, bv, vp, E_, E_, 0);

    // attention (tensor-core flash)
    flash_attn_tc_kernel<<<dim3(T_ / 128, B_ * H_), 256, FA_SMEM>>>(qp, kp, vp, mask, ctxp);

    // output projection + LN1
    gemm_tf32_kernel<<<gE, 256, GEMM_SMEM>>>(ctxp, woT, bo, t0p, E_, E_, 0);
    add_ln_kernel<<<M_, 256>>>(t0p, state, ln1g, ln1b, x1p);

    // FFN + LN2
    gemm_tf32_kernel<<<gF, 256, GEMM_SMEM>>>(x1p, w1T, b1, h1p, E_, F_, 1);
    gemm_tf32_kernel<<<gE, 256, GEMM_SMEM>>>(h1p, w2T, b2, t0p, F_, E_, 0);
    add_ln_kernel<<<M_, 256>>>(t0p, x1p, ln2g, ln2b, out);
}

// round 9
// speedup vs baseline: 2.3868x; 1.5513x over previous
#include <cuda_runtime.h>
#include <cuda_bf16.h>
#include <math.h>
#include <stdint.h>

// Problem constants
#define T_ 2048
#define B_ 2
#define E_ 768
#define H_ 12
#define D_ 64
#define F_ 3072
#define M_ (T_ * B_)   // 4096 rows

// ---------------------------------------------------------------------------
// Scratch (device globals — no cudaMalloc allowed)
// ---------------------------------------------------------------------------
__device__ float g_q[M_ * E_];
__device__ float g_k[M_ * E_];
__device__ float g_v[M_ * E_];
__device__ float g_ctx[M_ * E_];
__device__ float g_t0[M_ * E_];
__device__ float g_x1[M_ * E_];
__device__ float g_h1[M_ * F_];
// pre-split transposed weights: packed bf16x2 hi/lo, [N][K/2] u32 (K-pairs)
__device__ uint32_t g_wqTh[E_ * E_ / 2], g_wqTl[E_ * E_ / 2];
__device__ uint32_t g_wkTh[E_ * E_ / 2], g_wkTl[E_ * E_ / 2];
__device__ uint32_t g_wvTh[E_ * E_ / 2], g_wvTl[E_ * E_ / 2];
__device__ uint32_t g_woTh[E_ * E_ / 2], g_woTl[E_ * E_ / 2];
__device__ uint32_t g_w1Th[E_ * F_ / 2], g_w1Tl[E_ * F_ / 2];
__device__ uint32_t g_w2Th[E_ * F_ / 2], g_w2Tl[E_ * F_ / 2];

// ---------------------------------------------------------------------------
// Helpers (baseline PTX only — compute_103 virtual arch)
// ---------------------------------------------------------------------------
__device__ __forceinline__ uint32_t smem_u32(const void* p) {
    uint32_t a;
    asm("{ .reg .u64 t; cvta.to.shared.u64 t, %1; cvt.u32.u64 %0, t; }" : "=r"(a) : "l"(p));
    return a;
}
__device__ __forceinline__ void cp16(uint32_t dst, const void* src) {
    asm volatile("cp.async.cg.shared.global [%0], [%1], 16;" :: "r"(dst), "l"(src));
}
#define CP_COMMIT() asm volatile("cp.async.commit_group;" ::: "memory")
#define CP_WAIT(n)  asm volatile("cp.async.wait_group %0;" :: "n"(n) : "memory")

// split (x,y) into packed bf16x2 hi (rounded) and lo (residual). low half = x.
__device__ __forceinline__ void bsplit(float x, float y, uint32_t& hi, uint32_t& lo) {
    __nv_bfloat162 h = __floats2bfloat162_rn(x, y);
    const float hx = __low2float(h), hy = __high2float(h);
    __nv_bfloat162 l = __floats2bfloat162_rn(x - hx, y - hy);
    hi = *reinterpret_cast<uint32_t*>(&h);
    lo = *reinterpret_cast<uint32_t*>(&l);
}

// mma.sync m16n8k16 bf16: D += A*B, fp32 accumulate
__device__ __forceinline__ void mma_bf16(float* d, const uint32_t* a, const uint32_t* b) {
    asm volatile("mma.sync.aligned.m16n8k16.row.col.f32.bf16.bf16.f32 "
                 "{%0,%1,%2,%3}, {%4,%5,%6,%7}, {%8,%9}, {%0,%1,%2,%3};"
                 : "+f"(d[0]), "+f"(d[1]), "+f"(d[2]), "+f"(d[3])
                 : "r"(a[0]), "r"(a[1]), "r"(a[2]), "r"(a[3]), "r"(b[0]), "r"(b[1]));
}

// ---------------------------------------------------------------------------
// Weight transpose + bf16 hi/lo pack: in = W[K=R][N=C] row-major.
// out[n][kp] = pack(W[2kp][n], W[2kp+1][n]) for hi and lo arrays.
// ---------------------------------------------------------------------------
__global__ void __launch_bounds__(256)
packT_kernel(const float* __restrict__ in, uint32_t* __restrict__ oh,
             uint32_t* __restrict__ ol, int R, int C)
{
    __shared__ float t[32][33];
    const int bx = blockIdx.x * 32;   // n offset
    const int by = blockIdx.y * 32;   // k offset
    const int x = threadIdx.x, y = threadIdx.y;
#pragma unroll
    for (int j = 0; j < 32; j += 8)
        t[y + j][x] = in[(size_t)(by + y + j) * C + bx + x];
    __syncthreads();
    const int id = y * 32 + x;
    const int KH = R >> 1;
#pragma unroll
    for (int i = 0; i < 2; i++) {
        const int n = (id >> 4) + i * 16;
        const int kp = id & 15;
        uint32_t hi, lo;
        bsplit(t[2 * kp][n], t[2 * kp + 1][n], hi, lo);
        oh[(size_t)(bx + n) * KH + (by >> 1) + kp] = hi;
        ol[(size_t)(bx + n) * KH + (by >> 1) + kp] = lo;
    }
}

// ---------------------------------------------------------------------------
// HMMA 3x-bf16-split GEMM: C[M,N] = A[M,K] @ W + bias, optional ReLU.
// B pre-split global (packed bf16x2 hi/lo, [N][K/2]); A fp32 -> split at
// fragment load. CTA tile 128x128x32, 8 warps (2x4), m16n8k16.
// ---------------------------------------------------------------------------
#define GA_STR 36                       // fp32 words per A smem row
#define GB_STR 20                       // u32 per B smem row (16 pairs + 4 pad)
#define GA_TILE (128 * GA_STR)          // 4608 words
#define GB_TILE (128 * GB_STR)          // 2560 words
#define G_STAGE_W (GA_TILE + 2 * GB_TILE)   // 9728 words
#define GEMM_SMEM (2 * G_STAGE_W * 4)       // 77824 bytes

__global__ void __launch_bounds__(256, 2)
gemm_bf16_kernel(const float* __restrict__ A, const uint32_t* __restrict__ Bhg,
                 const uint32_t* __restrict__ Blg, const float* __restrict__ bias,
                 float* __restrict__ C, int Kdim, int Ndim, int relu)
{
    extern __shared__ float sm[];
    const uint32_t sb = smem_u32(sm);
    const int tid = threadIdx.x;
    const int wid = tid >> 5, lane = tid & 31;
    const int by = blockIdx.y * 128, bx = blockIdx.x * 128;
    const int warp_m = (wid >> 2) * 64;
    const int warp_n = (wid & 3) * 32;
    const int g = lane >> 2, c = lane & 3;
    const int KH = Kdim >> 1;

    float acc[4][4][4];
#pragma unroll
    for (int mt = 0; mt < 4; mt++)
#pragma unroll
        for (int nt = 0; nt < 4; nt++)
#pragma unroll
            for (int i = 0; i < 4; i++) acc[mt][nt][i] = 0.f;

    const int NT = Kdim / 32;

    auto load_stage = [&](int buf, int kt) {
        const uint32_t base = sb + (uint32_t)(buf * G_STAGE_W) * 4u;
#pragma unroll
        for (int i = 0; i < 4; i++) {
            const int id = tid + i * 256;
            const int row = id >> 3, c4 = id & 7;
            cp16(base + (uint32_t)(row * GA_STR + c4 * 4) * 4u,
                 &A[(size_t)(by + row) * Kdim + kt * 32 + c4 * 4]);
        }
        const uint32_t bB = base + (uint32_t)GA_TILE * 4u;
#pragma unroll
        for (int i = 0; i < 2; i++) {
            const int id = tid + i * 256;
            const int row = id >> 2, c4 = id & 3;
            const uint32_t so = (uint32_t)(row * GB_STR + c4 * 4) * 4u;
            cp16(bB + so, &Bhg[(size_t)(bx + row) * KH + kt * 16 + c4 * 4]);
            cp16(bB + (uint32_t)GB_TILE * 4u + so, &Blg[(size_t)(bx + row) * KH + kt * 16 + c4 * 4]);
        }
        CP_COMMIT();
    };

    load_stage(0, 0);

    for (int kt = 0; kt < NT; kt++) {
        if (kt + 1 < NT) {
            load_stage((kt + 1) & 1, kt + 1);
            CP_WAIT(1);
        } else {
            CP_WAIT(0);
        }
        __syncthreads();

        const float* As = sm + (kt & 1) * G_STAGE_W;
        const uint32_t* Bh = (const uint32_t*)(As + GA_TILE);
        const uint32_t* Bl = Bh + GB_TILE;

#pragma unroll
        for (int j = 0; j < 2; j++) {
            uint32_t ah[4][4], al[4][4];
#pragma unroll
            for (int mt = 0; mt < 4; mt++) {
                const int r = warp_m + mt * 16 + g;
                const float2 x0 = *(const float2*)&As[r * GA_STR + j * 16 + 2 * c];
                const float2 x1 = *(const float2*)&As[(r + 8) * GA_STR + j * 16 + 2 * c];
                const float2 x2 = *(const float2*)&As[r * GA_STR + j * 16 + 2 * c + 8];
                const float2 x3 = *(const float2*)&As[(r + 8) * GA_STR + j * 16 + 2 * c + 8];
                bsplit(x0.x, x0.y, ah[mt][0], al[mt][0]);
                bsplit(x1.x, x1.y, ah[mt][1], al[mt][1]);
                bsplit(x2.x, x2.y, ah[mt][2], al[mt][2]);
                bsplit(x3.x, x3.y, ah[mt][3], al[mt][3]);
            }
#pragma unroll
            for (int nt = 0; nt < 4; nt++) {
                const int n = warp_n + nt * 8 + g;
                uint32_t bh2[2], bl2[2];
                bh2[0] = Bh[n * GB_STR + j * 8 + c];
                bh2[1] = Bh[n * GB_STR + j * 8 + c + 4];
                bl2[0] = Bl[n * GB_STR + j * 8 + c];
                bl2[1] = Bl[n * GB_STR + j * 8 + c + 4];
#pragma unroll
                for (int mt = 0; mt < 4; mt++) {
                    mma_bf16(acc[mt][nt], ah[mt], bh2);
                    mma_bf16(acc[mt][nt], ah[mt], bl2);
                    mma_bf16(acc[mt][nt], al[mt], bh2);
                }
            }
        }
        __syncthreads();
    }

    // epilogue: registers -> gmem with bias (+ReLU)
#pragma unroll
    for (int mt = 0; mt < 4; mt++) {
        const int r0 = by + warp_m + mt * 16 + g;
#pragma unroll
        for (int nt = 0; nt < 4; nt++) {
            const int c0 = bx + warp_n + nt * 8 + 2 * c;
            const float b0 = bias[c0], b1 = bias[c0 + 1];
            float2 v0, v1;
            v0.x = acc[mt][nt][0] + b0; v0.y = acc[mt][nt][1] + b1;
            v1.x = acc[mt][nt][2] + b0; v1.y = acc[mt][nt][3] + b1;
            if (relu) {
                v0.x = fmaxf(v0.x, 0.f); v0.y = fmaxf(v0.y, 0.f);
                v1.x = fmaxf(v1.x, 0.f); v1.y = fmaxf(v1.y, 0.f);
            }
            *(float2*)&C[(size_t)r0 * Ndim + c0] = v0;
            *(float2*)&C[(size_t)(r0 + 8) * Ndim + c0] = v1;
        }
    }
}

// ---------------------------------------------------------------------------
// Tensor-core flash attention, 3x-bf16-split (m16n8k16). Br=128, Bc=64.
// Q/K/V pre-split into packed bf16x2 hi/lo smem once per tile (all warps
// share); P stays in registers (QK acc fragment == PV A fragment layout).
// Q pre-scaled by 1/sqrt(D). Fully-masked key tiles skipped at runtime.
// smem words (stride 36 u32 per row => conflict-free 4g+c fragment loads)
// ---------------------------------------------------------------------------
#define FP_STR 36
#define FQH 0
#define FQL (FQH + 128 * FP_STR)
#define FKH (FQL + 128 * FP_STR)
#define FKL (FKH + 64 * FP_STR)
#define FVH (FKL + 64 * FP_STR)
#define FVL (FVH + 64 * FP_STR)
#define FMK (FVL + 64 * FP_STR)
#define FA_SMEM ((FMK + 68) * 4)

__global__ void __launch_bounds__(256, 2)
flash_attn_bf16_kernel(const float* __restrict__ Q, const float* __restrict__ K,
                       const float* __restrict__ V, const int* __restrict__ mask,
                       float* __restrict__ ctx)
{
    extern __shared__ float fs[];
    uint32_t* us = (uint32_t*)fs;
    int* mks = (int*)(fs + FMK);
    int* flg = mks + 64;

    const int t0 = blockIdx.x * 128;
    const int b = blockIdx.y / H_;
    const int h = blockIdx.y % H_;
    const int tid = threadIdx.x;
    const int w = tid >> 5, lane = tid & 31;
    const int g = lane >> 2, c = lane & 3;
    const int wm = w * 16;

    // load Q tile [128 x 64], scale by 1/8, split into packed bf16 hi/lo
#pragma unroll
    for (int i = 0; i < 8; i++) {
        const int id = tid + i * 256;
        const int r = id >> 4, c4 = (id & 15) * 4;
        float4 v = *(const float4*)&Q[((size_t)(t0 + r) * B_ + b) * E_ + h * 64 + c4];
        v.x *= 0.125f; v.y *= 0.125f; v.z *= 0.125f; v.w *= 0.125f;
        uint32_t h0, l0, h1, l1;
        bsplit(v.x, v.y, h0, l0);
        bsplit(v.z, v.w, h1, l1);
        const int kp = c4 >> 1;
        us[FQH + r * FP_STR + kp] = h0; us[FQH + r * FP_STR + kp + 1] = h1;
        us[FQL + r * FP_STR + kp] = l0; us[FQL + r * FP_STR + kp + 1] = l1;
    }

    float o[8][4];
#pragma unroll
    for (int nt = 0; nt < 8; nt++)
#pragma unroll
        for (int i = 0; i < 4; i++) o[nt][i] = 0.f;
    float m0 = -INFINITY, m1 = -INFINITY, l0s = 0.f, l1s = 0.f;

    for (int s0 = 0; s0 < T_; s0 += 64) {
        __syncthreads();   // prev iter done with K/V/mask smem (first: Q visible)
        if (tid < 64) mks[tid] = mask[(size_t)b * T_ + s0 + tid];
        __syncthreads();
        if (tid < 32) {
            const int un = (mks[tid] == 0) || (mks[tid + 32] == 0);
            const unsigned bal = __ballot_sync(0xffffffffu, un);
            if (lane == 0) flg[0] = (bal == 0u);
        }
        __syncthreads();
        if (flg[0]) continue;   // whole tile masked -> skip

        // K tile [64 keys x 64 d] -> packed pairs along d
#pragma unroll
        for (int i = 0; i < 4; i++) {
            const int id = tid + i * 256;
            const int r = id >> 4, c4 = (id & 15) * 4;
            const float4 v = *(const float4*)&K[((size_t)(s0 + r) * B_ + b) * E_ + h * 64 + c4];
            uint32_t h0, l0, h1, l1;
            bsplit(v.x, v.y, h0, l0);
            bsplit(v.z, v.w, h1, l1);
            const int kp = c4 >> 1;
            us[FKH + r * FP_STR + kp] = h0; us[FKH + r * FP_STR + kp + 1] = h1;
            us[FKL + r * FP_STR + kp] = l0; us[FKL + r * FP_STR + kp + 1] = l1;
        }
        // V tile transposed: Vt[d][key-pairs]
#pragma unroll
        for (int i = 0; i < 2; i++) {
            const int id = tid + i * 256;
            const int kp = id & 31, dblk = id >> 5;    // dblk 0..15 over 2 iters
            const float4 va = *(const float4*)&V[((size_t)(s0 + 2 * kp) * B_ + b) * E_ + h * 64 + dblk * 4];
            const float4 vb = *(const float4*)&V[((size_t)(s0 + 2 * kp + 1) * B_ + b) * E_ + h * 64 + dblk * 4];
            uint32_t hi, lo;
            bsplit(va.x, vb.x, hi, lo);
            us[FVH + (dblk * 4 + 0) * FP_STR + kp] = hi; us[FVL + (dblk * 4 + 0) * FP_STR + kp] = lo;
            bsplit(va.y, vb.y, hi, lo);
            us[FVH + (dblk * 4 + 1) * FP_STR + kp] = hi; us[FVL + (dblk * 4 + 1) * FP_STR + kp] = lo;
            bsplit(va.z, vb.z, hi, lo);
            us[FVH + (dblk * 4 + 2) * FP_STR + kp] = hi; us[FVL + (dblk * 4 + 2) * FP_STR + kp] = lo;
            bsplit(va.w, vb.w, hi, lo);
            us[FVH + (dblk * 4 + 3) * FP_STR + kp] = hi; us[FVL + (dblk * 4 + 3) * FP_STR + kp] = lo;
        }
        __syncthreads();

        // ---- S = (Q/8) K^T, 16x64 per warp ----
        float sa[8][4];
#pragma unroll
        for (int nt = 0; nt < 8; nt++)
#pragma unroll
            for (int i = 0; i < 4; i++) sa[nt][i] = 0.f;

#pragma unroll
        for (int j = 0; j < 4; j++) {
            uint32_t qh[4], ql[4];
            qh[0] = us[FQH + (wm + g) * FP_STR + j * 8 + c];
            qh[1] = us[FQH + (wm + g + 8) * FP_STR + j * 8 + c];
            qh[2] = us[FQH + (wm + g) * FP_STR + j * 8 + c + 4];
            qh[3] = us[FQH + (wm + g + 8) * FP_STR + j * 8 + c + 4];
            ql[0] = us[FQL + (wm + g) * FP_STR + j * 8 + c];
            ql[1] = us[FQL + (wm + g + 8) * FP_STR + j * 8 + c];
            ql[2] = us[FQL + (wm + g) * FP_STR + j * 8 + c + 4];
            ql[3] = us[FQL + (wm + g + 8) * FP_STR + j * 8 + c + 4];
#pragma unroll
            for (int nt = 0; nt < 8; nt++) {
                const int key = nt * 8 + g;
                uint32_t bh2[2], bl2[2];
                bh2[0] = us[FKH + key * FP_STR + j * 8 + c];
                bh2[1] = us[FKH + key * FP_STR + j * 8 + c + 4];
                bl2[0] = us[FKL + key * FP_STR + j * 8 + c];
                bl2[1] = us[FKL + key * FP_STR + j * 8 + c + 4];
                mma_bf16(sa[nt], qh, bh2);
                mma_bf16(sa[nt], qh, bl2);
                mma_bf16(sa[nt], ql, bh2);
            }
        }

        // ---- online softmax (scores already scaled) ----
        float mx0 = -INFINITY, mx1 = -INFINITY;
#pragma unroll
        for (int nt = 0; nt < 8; nt++) {
            const int col0 = nt * 8 + 2 * c, col1 = col0 + 1;
            const bool k0m = mks[col0] != 0, k1m = mks[col1] != 0;
            float s0v = sa[nt][0]; if (k0m) s0v = -INFINITY;
            float s1v = sa[nt][1]; if (k1m) s1v = -INFINITY;
            float s2v = sa[nt][2]; if (k0m) s2v = -INFINITY;
            float s3v = sa[nt][3]; if (k1m) s3v = -INFINITY;
            sa[nt][0] = s0v; sa[nt][1] = s1v; sa[nt][2] = s2v; sa[nt][3] = s3v;
            mx0 = fmaxf(mx0, fmaxf(s0v, s1v));
            mx1 = fmaxf(mx1, fmaxf(s2v, s3v));
        }
        mx0 = fmaxf(mx0, __shfl_xor_sync(0xffffffffu, mx0, 1));
        mx0 = fmaxf(mx0, __shfl_xor_sync(0xffffffffu, mx0, 2));
        mx1 = fmaxf(mx1, __shfl_xor_sync(0xffffffffu, mx1, 1));
        mx1 = fmaxf(mx1, __shfl_xor_sync(0xffffffffu, mx1, 2));

        const float mn0 = fmaxf(m0, mx0), mn1 = fmaxf(m1, mx1);
        const float al0 = __expf(m0 - mn0), al1 = __expf(m1 - mn1);
        m0 = mn0; m1 = mn1;

        // exp, fp32 row-sums, pack P into bf16 hi/lo registers
        uint32_t phl[8], phh[8], pll[8], plh[8];
        float su0 = 0.f, su1 = 0.f;
#pragma unroll
        for (int nt = 0; nt < 8; nt++) {
            const float p0 = __expf(sa[nt][0] - mn0);
            const float p1 = __expf(sa[nt][1] - mn0);
            const float p2 = __expf(sa[nt][2] - mn1);
            const float p3 = __expf(sa[nt][3] - mn1);
            su0 += p0 + p1; su1 += p2 + p3;
            bsplit(p0, p1, phl[nt], pll[nt]);   // row g,  keys (nt*8+2c, +1)
            bsplit(p2, p3, phh[nt], plh[nt]);   // row g+8
        }
        su0 += __shfl_xor_sync(0xffffffffu, su0, 1);
        su0 += __shfl_xor_sync(0xffffffffu, su0, 2);
        su1 += __shfl_xor_sync(0xffffffffu, su1, 1);
        su1 += __shfl_xor_sync(0xffffffffu, su1, 2);
        l0s = l0s * al0 + su0;
        l1s = l1s * al1 + su1;
#pragma unroll
        for (int nt = 0; nt < 8; nt++) {
            o[nt][0] *= al0; o[nt][1] *= al0;
            o[nt][2] *= al1; o[nt][3] *= al1;
        }

        // ---- O += P V : P A-fragments straight from registers ----
#pragma unroll
        for (int j = 0; j < 4; j++) {
            uint32_t ah[4], al2[4];
            ah[0] = phl[2 * j];     ah[1] = phh[2 * j];
            ah[2] = phl[2 * j + 1]; ah[3] = phh[2 * j + 1];
            al2[0] = pll[2 * j];     al2[1] = plh[2 * j];
            al2[2] = pll[2 * j + 1]; al2[3] = plh[2 * j + 1];
#pragma unroll
            for (int nt = 0; nt < 8; nt++) {
                const int dd = nt * 8 + g;
                uint32_t bh2[2], bl2[2];
                bh2[0] = us[FVH + dd * FP_STR + j * 8 + c];
                bh2[1] = us[FVH + dd * FP_STR + j * 8 + c + 4];
                bl2[0] = us[FVL + dd * FP_STR + j * 8 + c];
                bl2[1] = us[FVL + dd * FP_STR + j * 8 + c + 4];
                mma_bf16(o[nt], ah, bh2);
                mma_bf16(o[nt], ah, bl2);
                mma_bf16(o[nt], al2, bh2);
            }
        }
    }

    // writeout: ctx[(t,b), h*64+d] = O / l
    const float i0 = 1.f / l0s, i1 = 1.f / l1s;
#pragma unroll
    for (int nt = 0; nt < 8; nt++) {
        const int col = h * 64 + nt * 8 + 2 * c;
        float2 a; a.x = o[nt][0] * i0; a.y = o[nt][1] * i0;
        float2 d; d.x = o[nt][2] * i1; d.y = o[nt][3] * i1;
        *(float2*)&ctx[((size_t)(t0 + wm + g) * B_ + b) * E_ + col] = a;
        *(float2*)&ctx[((size_t)(t0 + wm + g + 8) * B_ + b) * E_ + col] = d;
    }
}

// ---------------------------------------------------------------------------
// Fused add-residual + LayerNorm (unchanged)
// ---------------------------------------------------------------------------
__device__ __forceinline__ float warpReduceSum(float v) {
#pragma unroll
    for (int o = 16; o; o >>= 1) v += __shfl_xor_sync(0xffffffffu, v, o);
    return v;
}

__global__ void __launch_bounds__(256)
add_ln_kernel(const float* __restrict__ a, const float* __restrict__ r,
              const float* __restrict__ g, const float* __restrict__ be,
              float* __restrict__ out)
{
    const int row = blockIdx.x;
    const int tid = threadIdx.x;
    const float* pa = a + (size_t)row * E_;
    const float* pr = r + (size_t)row * E_;

    float v0 = pa[tid] + pr[tid];
    float v1 = pa[tid + 256] + pr[tid + 256];
    float v2 = pa[tid + 512] + pr[tid + 512];

    __shared__ float red[8];
    const int wid = tid >> 5, lane = tid & 31;

    float s = warpReduceSum(v0 + v1 + v2);
    if (lane == 0) red[wid] = s;
    __syncthreads();
    float tot = 0.f;
#pragma unroll
    for (int i = 0; i < 8; i++) tot += red[i];
    const float mean = tot * (1.f / (float)E_);

    float d0 = v0 - mean, d1 = v1 - mean, d2 = v2 - mean;
    float sq = warpReduceSum(d0 * d0 + d1 * d1 + d2 * d2);
    __syncthreads();
    if (lane == 0) red[wid] = sq;
    __syncthreads();
    tot = 0.f;
#pragma unroll
    for (int i = 0; i < 8; i++) tot += red[i];
    const float inv = rsqrtf(tot * (1.f / (float)E_) + 1e-5f);

    float* po = out + (size_t)row * E_;
    po[tid]       = d0 * inv * g[tid]       + be[tid];
    po[tid + 256] = d1 * inv * g[tid + 256] + be[tid + 256];
    po[tid + 512] = d2 * inv * g[tid + 512] + be[tid + 512];
}

// ---------------------------------------------------------------------------
// Launch
// ---------------------------------------------------------------------------
extern "C" void kernel_launch(void* const* d_in, const int* in_sizes, int n_in,
                              void* d_out, int out_size)
{
    const float* state = (const float*)d_in[0];
    const int* mask = (const int*)d_in[1];
    const float* Wq = (const float*)d_in[2];
    const float* bq = (const float*)d_in[3];
    const float* Wk = (const float*)d_in[4];
    const float* bk = (const float*)d_in[5];
    const float* Wv = (const float*)d_in[6];
    const float* bv = (const float*)d_in[7];
    const float* Wo = (const float*)d_in[8];
    const float* bo = (const float*)d_in[9];
    const float* ln1g = (const float*)d_in[10];
    const float* ln1b = (const float*)d_in[11];
    const float* W1 = (const float*)d_in[12];
    const float* b1 = (const float*)d_in[13];
    const float* W2 = (const float*)d_in[14];
    const float* b2 = (const float*)d_in[15];
    const float* ln2g = (const float*)d_in[16];
    const float* ln2b = (const float*)d_in[17];
    float* out = (float*)d_out;

    float *qp, *kp, *vp, *ctxp, *t0p, *x1p, *h1p;
    uint32_t *wqh, *wql, *wkh, *wkl, *wvh, *wvl, *woh, *wol, *w1h, *w1l, *w2h, *w2l;
    cudaGetSymbolAddress((void**)&qp,  g_q);
    cudaGetSymbolAddress((void**)&kp,  g_k);
    cudaGetSymbolAddress((void**)&vp,  g_v);
    cudaGetSymbolAddress((void**)&ctxp, g_ctx);
    cudaGetSymbolAddress((void**)&t0p, g_t0);
    cudaGetSymbolAddress((void**)&x1p, g_x1);
    cudaGetSymbolAddress((void**)&h1p, g_h1);
    cudaGetSymbolAddress((void**)&wqh, g_wqTh); cudaGetSymbolAddress((void**)&wql, g_wqTl);
    cudaGetSymbolAddress((void**)&wkh, g_wkTh); cudaGetSymbolAddress((void**)&wkl, g_wkTl);
    cudaGetSymbolAddress((void**)&wvh, g_wvTh); cudaGetSymbolAddress((void**)&wvl, g_wvTl);
    cudaGetSymbolAddress((void**)&woh, g_woTh); cudaGetSymbolAddress((void**)&wol, g_woTl);
    cudaGetSymbolAddress((void**)&w1h, g_w1Th); cudaGetSymbolAddress((void**)&w1l, g_w1Tl);
    cudaGetSymbolAddress((void**)&w2h, g_w2Th); cudaGetSymbolAddress((void**)&w2l, g_w2Tl);

    cudaFuncSetAttribute(gemm_bf16_kernel, cudaFuncAttributeMaxDynamicSharedMemorySize, GEMM_SMEM);
    cudaFuncSetAttribute(flash_attn_bf16_kernel, cudaFuncAttributeMaxDynamicSharedMemorySize, FA_SMEM);

    // transpose + bf16-split pack weights (once per launch; in-graph, cheap)
    dim3 tb(32, 8);
    packT_kernel<<<dim3(E_ / 32, E_ / 32), tb>>>(Wq, wqh, wql, E_, E_);
    packT_kernel<<<dim3(E_ / 32, E_ / 32), tb>>>(Wk, wkh, wkl, E_, E_);
    packT_kernel<<<dim3(E_ / 32, E_ / 32), tb>>>(Wv, wvh, wvl, E_, E_);
    packT_kernel<<<dim3(E_ / 32, E_ / 32), tb>>>(Wo, woh, wol, E_, E_);
    packT_kernel<<<dim3(F_ / 32, E_ / 32), tb>>>(W1, w1h, w1l, E_, F_);
    packT_kernel<<<dim3(E_ / 32, F_ / 32), tb>>>(W2, w2h, w2l, F_, E_);

    dim3 gE(E_ / 128, M_ / 128);   // (6, 32)
    dim3 gF(F_ / 128, M_ / 128);   // (24, 32)

    // QKV projections
    gemm_bf16_kernel<<<gE, 256, GEMM_SMEM>>>(state, wqh, wql, bq, qp, E_, E_, 0);
    gemm_bf16_kernel<<<gE, 256, GEMM_SMEM>>>(state, wkh, wkl, bk, kp, E_, E_, 0);
    gemm_bf16_kernel<<<gE, 256, GEMM_SMEM>>>(state, wvh, wvl, bv, vp, E_, E_, 0);

    // attention
    flash_attn_bf16_kernel<<<dim3(T_ / 128, B_ * H_), 256, FA_SMEM>>>(qp, kp, vp, mask, ctxp);

    // output projection + LN1
    gemm_bf16_kernel<<<gE, 256, GEMM_SMEM>>>(ctxp, woh, wol, bo, t0p, E_, E_, 0);
    add_ln_kernel<<<M_, 256>>>(t0p, state, ln1g, ln1b, x1p);

    // FFN + LN2
    gemm_bf16_kernel<<<gF, 256, GEMM_SMEM>>>(x1p, w1h, w1l, b1, h1p, E_, F_, 1);
    gemm_bf16_kernel<<<gE, 256, GEMM_SMEM>>>(h1p, w2h, w2l, b2, t0p, F_, E_, 0);
    add_ln_kernel<<<M_, 256>>>(t0p, x1p, ln2g, ln2b, out);
}

// round 10
// speedup vs baseline: 2.7596x; 1.1562x over previous
#include <cuda_runtime.h>
#include <cuda_bf16.h>
#include <math.h>
#include <stdint.h>

// Problem constants
#define T_ 2048
#define B_ 2
#define E_ 768
#define H_ 12
#define D_ 64
#define F_ 3072
#define M_ (T_ * B_)   // 4096 rows
#define EH (E_ / 2)
#define FH (F_ / 2)

// ---------------------------------------------------------------------------
// Scratch (device globals — no cudaMalloc allowed)
// Packed activations: bf16x2 hi/lo u32 arrays, [rows][K/2]
// ---------------------------------------------------------------------------
__device__ uint32_t g_sth[M_ * EH], g_stl[M_ * EH];   // packed state
__device__ uint32_t g_qh[M_ * EH],  g_ql[M_ * EH];    // packed Q (pre-scaled 1/8)
__device__ uint32_t g_kh[M_ * EH],  g_kl[M_ * EH];    // packed K
__device__ float    g_v[M_ * E_];                     // V fp32
__device__ uint32_t g_ch[M_ * EH],  g_cl[M_ * EH];    // packed ctx
__device__ float    g_t0[M_ * E_];                    // attn_out / ffn_out fp32
__device__ float    g_x1[M_ * E_];                    // LN1 out fp32 (residual)
__device__ uint32_t g_x1h[M_ * EH], g_x1l[M_ * EH];   // LN1 out packed
__device__ uint32_t g_h1h[M_ * FH], g_h1l[M_ * FH];   // FFN hidden packed (post-relu)
// pre-split transposed weights: [N][K/2]
__device__ uint32_t g_wqTh[E_ * EH], g_wqTl[E_ * EH];
__device__ uint32_t g_wkTh[E_ * EH], g_wkTl[E_ * EH];
__device__ uint32_t g_wvTh[E_ * EH], g_wvTl[E_ * EH];
__device__ uint32_t g_woTh[E_ * EH], g_woTl[E_ * EH];
__device__ uint32_t g_w1Th[F_ * EH], g_w1Tl[F_ * EH];
__device__ uint32_t g_w2Th[E_ * FH], g_w2Tl[E_ * FH];

// ---------------------------------------------------------------------------
// Helpers (baseline PTX only — compute_103 virtual arch)
// ---------------------------------------------------------------------------
__device__ __forceinline__ uint32_t smem_u32(const void* p) {
    uint32_t a;
    asm("{ .reg .u64 t; cvta.to.shared.u64 t, %1; cvt.u32.u64 %0, t; }" : "=r"(a) : "l"(p));
    return a;
}
__device__ __forceinline__ void cp16(uint32_t dst, const void* src) {
    asm volatile("cp.async.cg.shared.global [%0], [%1], 16;" :: "r"(dst), "l"(src));
}
#define CP_COMMIT() asm volatile("cp.async.commit_group;" ::: "memory")
#define CP_WAIT(n)  asm volatile("cp.async.wait_group %0;" :: "n"(n) : "memory")

// split (x,y) into packed bf16x2 hi (rounded) and lo (residual)
__device__ __forceinline__ void bsplit(float x, float y, uint32_t& hi, uint32_t& lo) {
    __nv_bfloat162 h = __floats2bfloat162_rn(x, y);
    const float hx = __low2float(h), hy = __high2float(h);
    __nv_bfloat162 l = __floats2bfloat162_rn(x - hx, y - hy);
    hi = *reinterpret_cast<uint32_t*>(&h);
    lo = *reinterpret_cast<uint32_t*>(&l);
}

// mma.sync m16n8k16 bf16: D += A*B, fp32 accumulate
__device__ __forceinline__ void mma_bf16(float* d, const uint32_t* a, const uint32_t* b) {
    asm volatile("mma.sync.aligned.m16n8k16.row.col.f32.bf16.bf16.f32 "
                 "{%0,%1,%2,%3}, {%4,%5,%6,%7}, {%8,%9}, {%0,%1,%2,%3};"
                 : "+f"(d[0]), "+f"(d[1]), "+f"(d[2]), "+f"(d[3])
                 : "r"(a[0]), "r"(a[1]), "r"(a[2]), "r"(a[3]), "r"(b[0]), "r"(b[1]));
}

// ---------------------------------------------------------------------------
// pack_rows: fp32 [n*2] -> packed bf16 hi/lo [n]
// ---------------------------------------------------------------------------
__global__ void __launch_bounds__(256)
pack_rows_kernel(const float* __restrict__ in, uint32_t* __restrict__ oh,
                 uint32_t* __restrict__ ol, int npairs)
{
    const int i = blockIdx.x * 256 + threadIdx.x;
    if (i < npairs) {
        const float2 v = *(const float2*)&in[2 * i];
        uint32_t hi, lo;
        bsplit(v.x, v.y, hi, lo);
        oh[i] = hi;
        ol[i] = lo;
    }
}

// ---------------------------------------------------------------------------
// Weight transpose + bf16 hi/lo pack: in = W[K=R][N=C] row-major.
// ---------------------------------------------------------------------------
__global__ void __launch_bounds__(256)
packT_kernel(const float* __restrict__ in, uint32_t* __restrict__ oh,
             uint32_t* __restrict__ ol, int R, int C)
{
    __shared__ float t[32][33];
    const int bx = blockIdx.x * 32;   // n offset
    const int by = blockIdx.y * 32;   // k offset
    const int x = threadIdx.x, y = threadIdx.y;
#pragma unroll
    for (int j = 0; j < 32; j += 8)
        t[y + j][x] = in[(size_t)(by + y + j) * C + bx + x];
    __syncthreads();
    const int id = y * 32 + x;
    const int KH2 = R >> 1;
#pragma unroll
    for (int i = 0; i < 2; i++) {
        const int n = (id >> 4) + i * 16;
        const int kp = id & 15;
        uint32_t hi, lo;
        bsplit(t[2 * kp][n], t[2 * kp + 1][n], hi, lo);
        oh[(size_t)(bx + n) * KH2 + (by >> 1) + kp] = hi;
        ol[(size_t)(bx + n) * KH2 + (by >> 1) + kp] = lo;
    }
}

// ---------------------------------------------------------------------------
// HMMA 3x-bf16-split GEMM, fully packed operands.
// A packed [M][KH], B packed [N][KH]. CTA tile 128x128x(16 pairs)=K32.
// Output: fp32 (outF) or packed hi/lo (outH/outL), opt ReLU, opt scale.
// smem per stage: A(hi,lo)+B(hi,lo) each 128 rows x 20 u32 (16+4 pad).
// ---------------------------------------------------------------------------
#define GP_STR 20
#define GP_TILE (128 * GP_STR)          // 2560 u32
#define GP_STAGE (4 * GP_TILE)          // Ah,Al,Bh,Bl = 10240 u32
#define GEMM_SMEM (2 * GP_STAGE * 4)    // 81920 bytes

__global__ void __launch_bounds__(256, 2)
gemm_pk_kernel(const uint32_t* __restrict__ Ah, const uint32_t* __restrict__ Al,
               const uint32_t* __restrict__ Bh, const uint32_t* __restrict__ Bl,
               const float* __restrict__ bias,
               float* __restrict__ outF, uint32_t* __restrict__ outH,
               uint32_t* __restrict__ outL,
               int KH, int Ndim, int packout, int relu, float scale)
{
    extern __shared__ uint32_t smu[];
    const uint32_t sb = smem_u32(smu);
    const int tid = threadIdx.x;
    const int wid = tid >> 5, lane = tid & 31;
    const int by = blockIdx.y * 128, bx = blockIdx.x * 128;
    const int warp_m = (wid >> 2) * 64;
    const int warp_n = (wid & 3) * 32;
    const int g = lane >> 2, c = lane & 3;

    float acc[4][4][4];
#pragma unroll
    for (int mt = 0; mt < 4; mt++)
#pragma unroll
        for (int nt = 0; nt < 4; nt++)
#pragma unroll
            for (int i = 0; i < 4; i++) acc[mt][nt][i] = 0.f;

    const int NT = KH / 16;

    auto load_stage = [&](int buf, int kt) {
        const uint32_t base = sb + (uint32_t)(buf * GP_STAGE) * 4u;
#pragma unroll
        for (int i = 0; i < 2; i++) {
            const int id = tid + i * 256;          // 0..511
            const int row = id >> 2, c4 = id & 3;  // row 0..127, 4x16B per row
            const uint32_t so = (uint32_t)(row * GP_STR + c4 * 4) * 4u;
            const size_t ga = (size_t)(by + row) * KH + kt * 16 + c4 * 4;
            const size_t gb = (size_t)(bx + row) * KH + kt * 16 + c4 * 4;
            cp16(base + so, &Ah[ga]);
            cp16(base + (uint32_t)(GP_TILE * 4) + so, &Al[ga]);
            cp16(base + (uint32_t)(2 * GP_TILE * 4) + so, &Bh[gb]);
            cp16(base + (uint32_t)(3 * GP_TILE * 4) + so, &Bl[gb]);
        }
        CP_COMMIT();
    };

    load_stage(0, 0);

    for (int kt = 0; kt < NT; kt++) {
        if (kt + 1 < NT) {
            load_stage((kt + 1) & 1, kt + 1);
            CP_WAIT(1);
        } else {
            CP_WAIT(0);
        }
        __syncthreads();

        const uint32_t* Sah = smu + (kt & 1) * GP_STAGE;
        const uint32_t* Sal = Sah + GP_TILE;
        const uint32_t* Sbh = Sal + GP_TILE;
        const uint32_t* Sbl = Sbh + GP_TILE;

#pragma unroll
        for (int j = 0; j < 2; j++) {
            uint32_t ah[4][4], al[4][4];
#pragma unroll
            for (int mt = 0; mt < 4; mt++) {
                const int r = warp_m + mt * 16 + g;
                ah[mt][0] = Sah[r * GP_STR + j * 8 + c];
                ah[mt][1] = Sah[(r + 8) * GP_STR + j * 8 + c];
                ah[mt][2] = Sah[r * GP_STR + j * 8 + c + 4];
                ah[mt][3] = Sah[(r + 8) * GP_STR + j * 8 + c + 4];
                al[mt][0] = Sal[r * GP_STR + j * 8 + c];
                al[mt][1] = Sal[(r + 8) * GP_STR + j * 8 + c];
                al[mt][2] = Sal[r * GP_STR + j * 8 + c + 4];
                al[mt][3] = Sal[(r + 8) * GP_STR + j * 8 + c + 4];
            }
#pragma unroll
            for (int nt = 0; nt < 4; nt++) {
                const int n = warp_n + nt * 8 + g;
                uint32_t bh2[2], bl2[2];
                bh2[0] = Sbh[n * GP_STR + j * 8 + c];
                bh2[1] = Sbh[n * GP_STR + j * 8 + c + 4];
                bl2[0] = Sbl[n * GP_STR + j * 8 + c];
                bl2[1] = Sbl[n * GP_STR + j * 8 + c + 4];
#pragma unroll
                for (int mt = 0; mt < 4; mt++) {
                    mma_bf16(acc[mt][nt], ah[mt], bh2);
                    mma_bf16(acc[mt][nt], ah[mt], bl2);
                    mma_bf16(acc[mt][nt], al[mt], bh2);
                }
            }
        }
        __syncthreads();
    }

    // epilogue
    const int NH = Ndim >> 1;
#pragma unroll
    for (int mt = 0; mt < 4; mt++) {
        const int r0 = by + warp_m + mt * 16 + g;
#pragma unroll
        for (int nt = 0; nt < 4; nt++) {
            const int c0 = bx + warp_n + nt * 8 + 2 * c;
            const float b0 = bias[c0], b1 = bias[c0 + 1];
            float v00 = (acc[mt][nt][0] + b0) * scale;
            float v01 = (acc[mt][nt][1] + b1) * scale;
            float v10 = (acc[mt][nt][2] + b0) * scale;
            float v11 = (acc[mt][nt][3] + b1) * scale;
            if (relu) {
                v00 = fmaxf(v00, 0.f); v01 = fmaxf(v01, 0.f);
                v10 = fmaxf(v10, 0.f); v11 = fmaxf(v11, 0.f);
            }
            if (packout) {
                uint32_t hi, lo;
                bsplit(v00, v01, hi, lo);
                outH[(size_t)r0 * NH + (c0 >> 1)] = hi;
                outL[(size_t)r0 * NH + (c0 >> 1)] = lo;
                bsplit(v10, v11, hi, lo);
                outH[(size_t)(r0 + 8) * NH + (c0 >> 1)] = hi;
                outL[(size_t)(r0 + 8) * NH + (c0 >> 1)] = lo;
            } else {
                float2 w0, w1;
                w0.x = v00; w0.y = v01; w1.x = v10; w1.y = v11;
                *(float2*)&outF[(size_t)r0 * Ndim + c0] = w0;
                *(float2*)&outF[(size_t)(r0 + 8) * Ndim + c0] = w1;
            }
        }
    }
}

// ---------------------------------------------------------------------------
// Tensor-core flash attention, packed Q/K (pre-split, Q pre-scaled 1/8),
// fp32 V split in-kernel; ctx written packed. Br=128, Bc=64, m16n8k16 x3.
// ---------------------------------------------------------------------------
#define FP_STR 36
#define FQH 0
#define FQL (FQH + 128 * FP_STR)
#define FKH (FQL + 128 * FP_STR)
#define FKL (FKH + 64 * FP_STR)
#define FVH (FKL + 64 * FP_STR)
#define FVL (FVH + 64 * FP_STR)
#define FMK (FVL + 64 * FP_STR)
#define FA_SMEM ((FMK + 68) * 4)

__global__ void __launch_bounds__(256, 2)
flash_attn_pk_kernel(const uint32_t* __restrict__ Qh, const uint32_t* __restrict__ Ql,
                     const uint32_t* __restrict__ Kh, const uint32_t* __restrict__ Kl,
                     const float* __restrict__ V, const int* __restrict__ mask,
                     uint32_t* __restrict__ ctxh, uint32_t* __restrict__ ctxl)
{
    extern __shared__ uint32_t us[];
    int* mks = (int*)(us + FMK);
    int* flg = mks + 64;

    const int t0 = blockIdx.x * 128;
    const int b = blockIdx.y / H_;
    const int h = blockIdx.y % H_;
    const int tid = threadIdx.x;
    const int w = tid >> 5, lane = tid & 31;
    const int g = lane >> 2, c = lane & 3;
    const int wm = w * 16;

    // load packed Q tile [128 rows x 32 kp] hi+lo
#pragma unroll
    for (int i = 0; i < 4; i++) {
        const int id = tid + i * 256;
        const int r = id >> 3, c4 = (id & 7) * 4;
        const size_t go = ((size_t)(t0 + r) * B_ + b) * EH + h * 32 + c4;
        *(uint4*)&us[FQH + r * FP_STR + c4] = *(const uint4*)&Qh[go];
        *(uint4*)&us[FQL + r * FP_STR + c4] = *(const uint4*)&Ql[go];
    }

    float o[8][4];
#pragma unroll
    for (int nt = 0; nt < 8; nt++)
#pragma unroll
        for (int i = 0; i < 4; i++) o[nt][i] = 0.f;
    float m0 = -INFINITY, m1 = -INFINITY, l0s = 0.f, l1s = 0.f;

    for (int s0 = 0; s0 < T_; s0 += 64) {
        __syncthreads();
        if (tid < 64) mks[tid] = mask[(size_t)b * T_ + s0 + tid];
        __syncthreads();
        if (tid < 32) {
            const int un = (mks[tid] == 0) || (mks[tid + 32] == 0);
            const unsigned bal = __ballot_sync(0xffffffffu, un);
            if (lane == 0) flg[0] = (bal == 0u);
        }
        __syncthreads();
        if (flg[0]) continue;

        // packed K tile [64 x 32 kp] hi+lo
#pragma unroll
        for (int i = 0; i < 2; i++) {
            const int id = tid + i * 256;
            const int r = id >> 3, c4 = (id & 7) * 4;
            const size_t go = ((size_t)(s0 + r) * B_ + b) * EH + h * 32 + c4;
            *(uint4*)&us[FKH + r * FP_STR + c4] = *(const uint4*)&Kh[go];
            *(uint4*)&us[FKL + r * FP_STR + c4] = *(const uint4*)&Kl[go];
        }
        // V tile transposed + split: Vt[d][key-pair]
#pragma unroll
        for (int i = 0; i < 2; i++) {
            const int id = tid + i * 256;
            const int kp = id & 31, dblk = id >> 5;
            const float4 va = *(const float4*)&V[((size_t)(s0 + 2 * kp) * B_ + b) * E_ + h * 64 + dblk * 4];
            const float4 vb = *(const float4*)&V[((size_t)(s0 + 2 * kp + 1) * B_ + b) * E_ + h * 64 + dblk * 4];
            uint32_t hi, lo;
            bsplit(va.x, vb.x, hi, lo);
            us[FVH + (dblk * 4 + 0) * FP_STR + kp] = hi; us[FVL + (dblk * 4 + 0) * FP_STR + kp] = lo;
            bsplit(va.y, vb.y, hi, lo);
            us[FVH + (dblk * 4 + 1) * FP_STR + kp] = hi; us[FVL + (dblk * 4 + 1) * FP_STR + kp] = lo;
            bsplit(va.z, vb.z, hi, lo);
            us[FVH + (dblk * 4 + 2) * FP_STR + kp] = hi; us[FVL + (dblk * 4 + 2) * FP_STR + kp] = lo;
            bsplit(va.w, vb.w, hi, lo);
            us[FVH + (dblk * 4 + 3) * FP_STR + kp] = hi; us[FVL + (dblk * 4 + 3) * FP_STR + kp] = lo;
        }
        __syncthreads();

        // ---- S = (Q/8) K^T, 16x64 per warp ----
        float sa[8][4];
#pragma unroll
        for (int nt = 0; nt < 8; nt++)
#pragma unroll
            for (int i = 0; i < 4; i++) sa[nt][i] = 0.f;

#pragma unroll
        for (int j = 0; j < 4; j++) {
            uint32_t qh[4], ql[4];
            qh[0] = us[FQH + (wm + g) * FP_STR + j * 8 + c];
            qh[1] = us[FQH + (wm + g + 8) * FP_STR + j * 8 + c];
            qh[2] = us[FQH + (wm + g) * FP_STR + j * 8 + c + 4];
            qh[3] = us[FQH + (wm + g + 8) * FP_STR + j * 8 + c + 4];
            ql[0] = us[FQL + (wm + g) * FP_STR + j * 8 + c];
            ql[1] = us[FQL + (wm + g + 8) * FP_STR + j * 8 + c];
            ql[2] = us[FQL + (wm + g) * FP_STR + j * 8 + c + 4];
            ql[3] = us[FQL + (wm + g + 8) * FP_STR + j * 8 + c + 4];
#pragma unroll
            for (int nt = 0; nt < 8; nt++) {
                const int key = nt * 8 + g;
                uint32_t bh2[2], bl2[2];
                bh2[0] = us[FKH + key * FP_STR + j * 8 + c];
                bh2[1] = us[FKH + key * FP_STR + j * 8 + c + 4];
                bl2[0] = us[FKL + key * FP_STR + j * 8 + c];
                bl2[1] = us[FKL + key * FP_STR + j * 8 + c + 4];
                mma_bf16(sa[nt], qh, bh2);
                mma_bf16(sa[nt], qh, bl2);
                mma_bf16(sa[nt], ql, bh2);
            }
        }

        // ---- online softmax ----
        float mx0 = -INFINITY, mx1 = -INFINITY;
#pragma unroll
        for (int nt = 0; nt < 8; nt++) {
            const int col0 = nt * 8 + 2 * c, col1 = col0 + 1;
            const bool k0m = mks[col0] != 0, k1m = mks[col1] != 0;
            float s0v = sa[nt][0]; if (k0m) s0v = -INFINITY;
            float s1v = sa[nt][1]; if (k1m) s1v = -INFINITY;
            float s2v = sa[nt][2]; if (k0m) s2v = -INFINITY;
            float s3v = sa[nt][3]; if (k1m) s3v = -INFINITY;
            sa[nt][0] = s0v; sa[nt][1] = s1v; sa[nt][2] = s2v; sa[nt][3] = s3v;
            mx0 = fmaxf(mx0, fmaxf(s0v, s1v));
            mx1 = fmaxf(mx1, fmaxf(s2v, s3v));
        }
        mx0 = fmaxf(mx0, __shfl_xor_sync(0xffffffffu, mx0, 1));
        mx0 = fmaxf(mx0, __shfl_xor_sync(0xffffffffu, mx0, 2));
        mx1 = fmaxf(mx1, __shfl_xor_sync(0xffffffffu, mx1, 1));
        mx1 = fmaxf(mx1, __shfl_xor_sync(0xffffffffu, mx1, 2));

        const float mn0 = fmaxf(m0, mx0), mn1 = fmaxf(m1, mx1);
        const float al0 = __expf(m0 - mn0), al1 = __expf(m1 - mn1);
        m0 = mn0; m1 = mn1;

        uint32_t phl[8], phh[8], pll[8], plh[8];
        float su0 = 0.f, su1 = 0.f;
#pragma unroll
        for (int nt = 0; nt < 8; nt++) {
            const float p0 = __expf(sa[nt][0] - mn0);
            const float p1 = __expf(sa[nt][1] - mn0);
            const float p2 = __expf(sa[nt][2] - mn1);
            const float p3 = __expf(sa[nt][3] - mn1);
            su0 += p0 + p1; su1 += p2 + p3;
            bsplit(p0, p1, phl[nt], pll[nt]);
            bsplit(p2, p3, phh[nt], plh[nt]);
        }
        su0 += __shfl_xor_sync(0xffffffffu, su0, 1);
        su0 += __shfl_xor_sync(0xffffffffu, su0, 2);
        su1 += __shfl_xor_sync(0xffffffffu, su1, 1);
        su1 += __shfl_xor_sync(0xffffffffu, su1, 2);
        l0s = l0s * al0 + su0;
        l1s = l1s * al1 + su1;
#pragma unroll
        for (int nt = 0; nt < 8; nt++) {
            o[nt][0] *= al0; o[nt][1] *= al0;
            o[nt][2] *= al1; o[nt][3] *= al1;
        }

        // ---- O += P V (P in registers) ----
#pragma unroll
        for (int j = 0; j < 4; j++) {
            uint32_t ah[4], al2[4];
            ah[0] = phl[2 * j];     ah[1] = phh[2 * j];
            ah[2] = phl[2 * j + 1]; ah[3] = phh[2 * j + 1];
            al2[0] = pll[2 * j];     al2[1] = plh[2 * j];
            al2[2] = pll[2 * j + 1]; al2[3] = plh[2 * j + 1];
#pragma unroll
            for (int nt = 0; nt < 8; nt++) {
                const int dd = nt * 8 + g;
                uint32_t bh2[2], bl2[2];
                bh2[0] = us[FVH + dd * FP_STR + j * 8 + c];
                bh2[1] = us[FVH + dd * FP_STR + j * 8 + c + 4];
                bl2[0] = us[FVL + dd * FP_STR + j * 8 + c];
                bl2[1] = us[FVL + dd * FP_STR + j * 8 + c + 4];
                mma_bf16(o[nt], ah, bh2);
                mma_bf16(o[nt], ah, bl2);
                mma_bf16(o[nt], al2, bh2);
            }
        }
    }

    // writeout: packed ctx
    const float i0 = 1.f / l0s, i1 = 1.f / l1s;
#pragma unroll
    for (int nt = 0; nt < 8; nt++) {
        const int kp = h * 32 + nt * 4 + c;
        uint32_t hi, lo;
        bsplit(o[nt][0] * i0, o[nt][1] * i0, hi, lo);
        ctxh[((size_t)(t0 + wm + g) * B_ + b) * EH + kp] = hi;
        ctxl[((size_t)(t0 + wm + g) * B_ + b) * EH + kp] = lo;
        bsplit(o[nt][2] * i1, o[nt][3] * i1, hi, lo);
        ctxh[((size_t)(t0 + wm + g + 8) * B_ + b) * EH + kp] = hi;
        ctxl[((size_t)(t0 + wm + g + 8) * B_ + b) * EH + kp] = lo;
    }
}

// ---------------------------------------------------------------------------
// Fused add-residual + LayerNorm
// ---------------------------------------------------------------------------
__device__ __forceinline__ float warpReduceSum(float v) {
#pragma unroll
    for (int o = 16; o; o >>= 1) v += __shfl_xor_sync(0xffffffffu, v, o);
    return v;
}

// variant A: fp32 out only (256 threads)
__global__ void __launch_bounds__(256)
add_ln_kernel(const float* __restrict__ a, const float* __restrict__ r,
              const float* __restrict__ g, const float* __restrict__ be,
              float* __restrict__ out)
{
    const int row = blockIdx.x;
    const int tid = threadIdx.x;
    const float* pa = a + (size_t)row * E_;
    const float* pr = r + (size_t)row * E_;

    float v0 = pa[tid] + pr[tid];
    float v1 = pa[tid + 256] + pr[tid + 256];
    float v2 = pa[tid + 512] + pr[tid + 512];

    __shared__ float red[8];
    const int wid = tid >> 5, lane = tid & 31;

    float s = warpReduceSum(v0 + v1 + v2);
    if (lane == 0) red[wid] = s;
    __syncthreads();
    float tot = 0.f;
#pragma unroll
    for (int i = 0; i < 8; i++) tot += red[i];
    const float mean = tot * (1.f / (float)E_);

    float d0 = v0 - mean, d1 = v1 - mean, d2 = v2 - mean;
    float sq = warpReduceSum(d0 * d0 + d1 * d1 + d2 * d2);
    __syncthreads();
    if (lane == 0) red[wid] = sq;
    __syncthreads();
    tot = 0.f;
#pragma unroll
    for (int i = 0; i < 8; i++) tot += red[i];
    const float inv = rsqrtf(tot * (1.f / (float)E_) + 1e-5f);

    float* po = out + (size_t)row * E_;
    po[tid]       = d0 * inv * g[tid]       + be[tid];
    po[tid + 256] = d1 * inv * g[tid + 256] + be[tid + 256];
    po[tid + 512] = d2 * inv * g[tid + 512] + be[tid + 512];
}

// variant B: fp32 out + packed hi/lo out (128 threads, float2 lanes)
__global__ void __launch_bounds__(128)
add_ln_pack_kernel(const float* __restrict__ a, const float* __restrict__ r,
                   const float* __restrict__ g, const float* __restrict__ be,
                   float* __restrict__ outF, uint32_t* __restrict__ outH,
                   uint32_t* __restrict__ outL)
{
    const int row = blockIdx.x;
    const int tid = threadIdx.x;
    const float* pa = a + (size_t)row * E_;
    const float* pr = r + (size_t)row * E_;

    float2 v[3];
#pragma unroll
    for (int i = 0; i < 3; i++) {
        const int o = 2 * (tid + i * 128);
        const float2 x = *(const float2*)&pa[o];
        const float2 y = *(const float2*)&pr[o];
        v[i].x = x.x + y.x;
        v[i].y = x.y + y.y;
    }

    __shared__ float red[4];
    const int wid = tid >> 5, lane = tid & 31;

    float s = warpReduceSum(v[0].x + v[0].y + v[1].x + v[1].y + v[2].x + v[2].y);
    if (lane == 0) red[wid] = s;
    __syncthreads();
    float tot = red[0] + red[1] + red[2] + red[3];
    const float mean = tot * (1.f / (float)E_);

    float sq = 0.f;
#pragma unroll
    for (int i = 0; i < 3; i++) {
        v[i].x -= mean; v[i].y -= mean;
        sq += v[i].x * v[i].x + v[i].y * v[i].y;
    }
    sq = warpReduceSum(sq);
    __syncthreads();
    if (lane == 0) red[wid] = sq;
    __syncthreads();
    tot = red[0] + red[1] + red[2] + red[3];
    const float inv = rsqrtf(tot * (1.f / (float)E_) + 1e-5f);

    float* po = outF + (size_t)row * E_;
    uint32_t* ph = outH + (size_t)row * EH;
    uint32_t* pl = outL + (size_t)row * EH;
#pragma unroll
    for (int i = 0; i < 3; i++) {
        const int p = tid + i * 128;
        const float2 gg = *(const float2*)&g[2 * p];
        const float2 bb = *(const float2*)&be[2 * p];
        float2 w;
        w.x = v[i].x * inv * gg.x + bb.x;
        w.y = v[i].y * inv * gg.y + bb.y;
        *(float2*)&po[2 * p] = w;
        uint32_t hi, lo;
        bsplit(w.x, w.y, hi, lo);
        ph[p] = hi;
        pl[p] = lo;
    }
}

// ---------------------------------------------------------------------------
// Launch
// ---------------------------------------------------------------------------
extern "C" void kernel_launch(void* const* d_in, const int* in_sizes, int n_in,
                              void* d_out, int out_size)
{
    const float* state = (const float*)d_in[0];
    const int* mask = (const int*)d_in[1];
    const float* Wq = (const float*)d_in[2];
    const float* bq = (const float*)d_in[3];
    const float* Wk = (const float*)d_in[4];
    const float* bk = (const float*)d_in[5];
    const float* Wv = (const float*)d_in[6];
    const float* bv = (const float*)d_in[7];
    const float* Wo = (const float*)d_in[8];
    const float* bo = (const float*)d_in[9];
    const float* ln1g = (const float*)d_in[10];
    const float* ln1b = (const float*)d_in[11];
    const float* W1 = (const float*)d_in[12];
    const float* b1 = (const float*)d_in[13];
    const float* W2 = (const float*)d_in[14];
    const float* b2 = (const float*)d_in[15];
    const float* ln2g = (const float*)d_in[16];
    const float* ln2b = (const float*)d_in[17];
    float* out = (float*)d_out;

    uint32_t *sth, *stl, *qh, *ql, *kh, *kl, *ch, *cl, *x1h, *x1l, *h1h, *h1l;
    float *vp, *t0p, *x1p;
    uint32_t *wqh, *wql, *wkh, *wkl, *wvh, *wvl, *woh, *wol, *w1h, *w1l, *w2h, *w2l;
    cudaGetSymbolAddress((void**)&sth, g_sth); cudaGetSymbolAddress((void**)&stl, g_stl);
    cudaGetSymbolAddress((void**)&qh, g_qh);   cudaGetSymbolAddress((void**)&ql, g_ql);
    cudaGetSymbolAddress((void**)&kh, g_kh);   cudaGetSymbolAddress((void**)&kl, g_kl);
    cudaGetSymbolAddress((void**)&vp, g_v);
    cudaGetSymbolAddress((void**)&ch, g_ch);   cudaGetSymbolAddress((void**)&cl, g_cl);
    cudaGetSymbolAddress((void**)&t0p, g_t0);
    cudaGetSymbolAddress((void**)&x1p, g_x1);
    cudaGetSymbolAddress((void**)&x1h, g_x1h); cudaGetSymbolAddress((void**)&x1l, g_x1l);
    cudaGetSymbolAddress((void**)&h1h, g_h1h); cudaGetSymbolAddress((void**)&h1l, g_h1l);
    cudaGetSymbolAddress((void**)&wqh, g_wqTh); cudaGetSymbolAddress((void**)&wql, g_wqTl);
    cudaGetSymbolAddress((void**)&wkh, g_wkTh); cudaGetSymbolAddress((void**)&wkl, g_wkTl);
    cudaGetSymbolAddress((void**)&wvh, g_wvTh); cudaGetSymbolAddress((void**)&wvl, g_wvTl);
    cudaGetSymbolAddress((void**)&woh, g_woTh); cudaGetSymbolAddress((void**)&wol, g_woTl);
    cudaGetSymbolAddress((void**)&w1h, g_w1Th); cudaGetSymbolAddress((void**)&w1l, g_w1Tl);
    cudaGetSymbolAddress((void**)&w2h, g_w2Th); cudaGetSymbolAddress((void**)&w2l, g_w2Tl);

    cudaFuncSetAttribute(gemm_pk_kernel, cudaFuncAttributeMaxDynamicSharedMemorySize, GEMM_SMEM);
    cudaFuncSetAttribute(flash_attn_pk_kernel, cudaFuncAttributeMaxDynamicSharedMemorySize, FA_SMEM);

    // pack inputs
    pack_rows_kernel<<<(M_ * EH + 255) / 256, 256>>>(state, sth, stl, M_ * EH);
    dim3 tb(32, 8);
    packT_kernel<<<dim3(E_ / 32, E_ / 32), tb>>>(Wq, wqh, wql, E_, E_);
    packT_kernel<<<dim3(E_ / 32, E_ / 32), tb>>>(Wk, wkh, wkl, E_, E_);
    packT_kernel<<<dim3(E_ / 32, E_ / 32), tb>>>(Wv, wvh, wvl, E_, E_);
    packT_kernel<<<dim3(E_ / 32, E_ / 32), tb>>>(Wo, woh, wol, E_, E_);
    packT_kernel<<<dim3(F_ / 32, E_ / 32), tb>>>(W1, w1h, w1l, E_, F_);
    packT_kernel<<<dim3(E_ / 32, F_ / 32), tb>>>(W2, w2h, w2l, F_, E_);

    dim3 gE(E_ / 128, M_ / 128);   // (6, 32)
    dim3 gF(F_ / 128, M_ / 128);   // (24, 32)

    // QKV projections: Q packed+scaled, K packed, V fp32
    gemm_pk_kernel<<<gE, 256, GEMM_SMEM>>>(sth, stl, wqh, wql, bq, nullptr, qh, ql, EH, E_, 1, 0, 0.125f);
    gemm_pk_kernel<<<gE, 256, GEMM_SMEM>>>(sth, stl, wkh, wkl, bk, nullptr, kh, kl, EH, E_, 1, 0, 1.f);
    gemm_pk_kernel<<<gE, 256, GEMM_SMEM>>>(sth, stl, wvh, wvl, bv, vp, nullptr, nullptr, EH, E_, 0, 0, 1.f);

    // attention -> packed ctx
    flash_attn_pk_kernel<<<dim3(T_ / 128, B_ * H_), 256, FA_SMEM>>>(qh, ql, kh, kl, vp, mask, ch, cl);

    // output projection + LN1 (fp32 + packed x1)
    gemm_pk_kernel<<<gE, 256, GEMM_SMEM>>>(ch, cl, woh, wol, bo, t0p, nullptr, nullptr, EH, E_, 0, 0, 1.f);
    add_ln_pack_kernel<<<M_, 128>>>(t0p, state, ln1g, ln1b, x1p, x1h, x1l);

    // FFN + LN2
    gemm_pk_kernel<<<gF, 256, GEMM_SMEM>>>(x1h, x1l, w1h, w1l, b1, nullptr, h1h, h1l, EH, F_, 1, 1, 1.f);
    gemm_pk_kernel<<<gE, 256, GEMM_SMEM>>>(h1h, h1l, w2h, w2l, b2, t0p, nullptr, nullptr, FH, E_, 0, 0, 1.f);
    add_ln_kernel<<<M_, 256>>>(t0p, x1p, ln2g, ln2b, out);
}

// round 11
// speedup vs baseline: 3.1385x; 1.1373x over previous
#include <cuda_runtime.h>
#include <cuda_bf16.h>
#include <math.h>
#include <stdint.h>

// Problem constants
#define T_ 2048
#define B_ 2
#define E_ 768
#define H_ 12
#define D_ 64
#define F_ 3072
#define M_ (T_ * B_)   // 4096 rows
#define EH (E_ / 2)
#define FH (F_ / 2)

// ---------------------------------------------------------------------------
// Scratch (device globals — no cudaMalloc allowed)
// ---------------------------------------------------------------------------
__device__ uint32_t g_sth[M_ * EH], g_stl[M_ * EH];   // packed state
__device__ uint32_t g_qh[M_ * EH],  g_ql[M_ * EH];    // packed Q (pre-scaled 1/8)
__device__ uint32_t g_kh[M_ * EH],  g_kl[M_ * EH];    // packed K
__device__ float    g_v[M_ * E_];                     // V fp32
__device__ uint32_t g_ch[M_ * EH],  g_cl[M_ * EH];    // packed ctx
__device__ float    g_t0[M_ * E_];                    // attn_out / ffn_out fp32
__device__ float    g_x1[M_ * E_];                    // LN1 out fp32 (residual)
__device__ uint32_t g_x1h[M_ * EH], g_x1l[M_ * EH];   // LN1 out packed
__device__ uint32_t g_h1h[M_ * FH], g_h1l[M_ * FH];   // FFN hidden packed
// pre-split transposed weights: [N][K/2]
__device__ uint32_t g_wqTh[E_ * EH], g_wqTl[E_ * EH];
__device__ uint32_t g_wkTh[E_ * EH], g_wkTl[E_ * EH];
__device__ uint32_t g_wvTh[E_ * EH], g_wvTl[E_ * EH];
__device__ uint32_t g_woTh[E_ * EH], g_woTl[E_ * EH];
__device__ uint32_t g_w1Th[F_ * EH], g_w1Tl[F_ * EH];
__device__ uint32_t g_w2Th[E_ * FH], g_w2Tl[E_ * FH];

// ---------------------------------------------------------------------------
// Helpers (baseline PTX only — compute_103 virtual arch)
// ---------------------------------------------------------------------------
__device__ __forceinline__ uint32_t smem_u32(const void* p) {
    uint32_t a;
    asm("{ .reg .u64 t; cvta.to.shared.u64 t, %1; cvt.u32.u64 %0, t; }" : "=r"(a) : "l"(p));
    return a;
}
__device__ __forceinline__ void cp16(uint32_t dst, const void* src) {
    asm volatile("cp.async.cg.shared.global [%0], [%1], 16;" :: "r"(dst), "l"(src));
}
#define CP_COMMIT() asm volatile("cp.async.commit_group;" ::: "memory")
#define CP_WAIT(n)  asm volatile("cp.async.wait_group %0;" :: "n"(n) : "memory")

__device__ __forceinline__ void bsplit(float x, float y, uint32_t& hi, uint32_t& lo) {
    __nv_bfloat162 h = __floats2bfloat162_rn(x, y);
    const float hx = __low2float(h), hy = __high2float(h);
    __nv_bfloat162 l = __floats2bfloat162_rn(x - hx, y - hy);
    hi = *reinterpret_cast<uint32_t*>(&h);
    lo = *reinterpret_cast<uint32_t*>(&l);
}

__device__ __forceinline__ void mma_bf16(float* d, const uint32_t* a, const uint32_t* b) {
    asm volatile("mma.sync.aligned.m16n8k16.row.col.f32.bf16.bf16.f32 "
                 "{%0,%1,%2,%3}, {%4,%5,%6,%7}, {%8,%9}, {%0,%1,%2,%3};"
                 : "+f"(d[0]), "+f"(d[1]), "+f"(d[2]), "+f"(d[3])
                 : "r"(a[0]), "r"(a[1]), "r"(a[2]), "r"(a[3]), "r"(b[0]), "r"(b[1]));
}

// ldmatrix x4: four 8x8 b16 tiles; per-lane row addresses
__device__ __forceinline__ void ldm4(uint32_t& r0, uint32_t& r1, uint32_t& r2,
                                     uint32_t& r3, uint32_t a) {
    asm volatile("ldmatrix.sync.aligned.m8n8.x4.shared.b16 {%0,%1,%2,%3}, [%4];"
                 : "=r"(r0), "=r"(r1), "=r"(r2), "=r"(r3) : "r"(a));
}

// ---------------------------------------------------------------------------
// pack_rows: fp32 [n*2] -> packed bf16 hi/lo [n]
// ---------------------------------------------------------------------------
__global__ void __launch_bounds__(256)
pack_rows_kernel(const float* __restrict__ in, uint32_t* __restrict__ oh,
                 uint32_t* __restrict__ ol, int npairs)
{
    const int i = blockIdx.x * 256 + threadIdx.x;
    if (i < npairs) {
        const float2 v = *(const float2*)&in[2 * i];
        uint32_t hi, lo;
        bsplit(v.x, v.y, hi, lo);
        oh[i] = hi;
        ol[i] = lo;
    }
}

// ---------------------------------------------------------------------------
// Weight transpose + bf16 hi/lo pack
// ---------------------------------------------------------------------------
__global__ void __launch_bounds__(256)
packT_kernel(const float* __restrict__ in, uint32_t* __restrict__ oh,
             uint32_t* __restrict__ ol, int R, int C)
{
    __shared__ float t[32][33];
    const int bx = blockIdx.x * 32;
    const int by = blockIdx.y * 32;
    const int x = threadIdx.x, y = threadIdx.y;
#pragma unroll
    for (int j = 0; j < 32; j += 8)
        t[y + j][x] = in[(size_t)(by + y + j) * C + bx + x];
    __syncthreads();
    const int id = y * 32 + x;
    const int KH2 = R >> 1;
#pragma unroll
    for (int i = 0; i < 2; i++) {
        const int n = (id >> 4) + i * 16;
        const int kp = id & 15;
        uint32_t hi, lo;
        bsplit(t[2 * kp][n], t[2 * kp + 1][n], hi, lo);
        oh[(size_t)(bx + n) * KH2 + (by >> 1) + kp] = hi;
        ol[(size_t)(bx + n) * KH2 + (by >> 1) + kp] = lo;
    }
}

// ---------------------------------------------------------------------------
// Shared GEMM mainloop core: 128x128xK tile, packed hi/lo operands, ldmatrix
// fragments, 8 warps (2x4), m16n8k16 x 3 split terms. acc in caller regs.
// ---------------------------------------------------------------------------
#define GP_STR 20
#define GP_TILE (128 * GP_STR)          // 2560 u32
#define GP_STAGE (4 * GP_TILE)          // Ah,Al,Bh,Bl
#define GEMM_SMEM (2 * GP_STAGE * 4)    // 81920 bytes

__device__ __forceinline__ void gemm_core(
    const uint32_t* __restrict__ Ah, const uint32_t* __restrict__ Al,
    const uint32_t* __restrict__ Bh, const uint32_t* __restrict__ Bl,
    int KH, int by, int bx, uint32_t sb, int tid, float acc[4][4][4])
{
    const int wid = tid >> 5, lane = tid & 31;
    const int warp_m = (wid >> 2) * 64;
    const int warp_n = (wid & 3) * 32;

    // ldmatrix per-lane addressing
    const int arow_l = warp_m + (lane & 15);
    const int acol_l = (lane >> 4) << 2;
    const int brow_l = warp_n + (lane & 7) + ((lane >> 4) << 3);
    const int bcol_l = ((lane >> 3) & 1) << 2;

    const int NT = KH / 16;

    auto load_stage = [&](int buf, int kt) {
        const uint32_t base = sb + (uint32_t)(buf * GP_STAGE) * 4u;
#pragma unroll
        for (int i = 0; i < 2; i++) {
            const int id = tid + i * 256;
            const int row = id >> 2, c4 = id & 3;
            const uint32_t so = (uint32_t)(row * GP_STR + c4 * 4) * 4u;
            const size_t ga = (size_t)(by + row) * KH + kt * 16 + c4 * 4;
            const size_t gb = (size_t)(bx + row) * KH + kt * 16 + c4 * 4;
            cp16(base + so, &Ah[ga]);
            cp16(base + (uint32_t)(GP_TILE * 4) + so, &Al[ga]);
            cp16(base + (uint32_t)(2 * GP_TILE * 4) + so, &Bh[gb]);
            cp16(base + (uint32_t)(3 * GP_TILE * 4) + so, &Bl[gb]);
        }
        CP_COMMIT();
    };

    load_stage(0, 0);

    for (int kt = 0; kt < NT; kt++) {
        if (kt + 1 < NT) {
            load_stage((kt + 1) & 1, kt + 1);
            CP_WAIT(1);
        } else {
            CP_WAIT(0);
        }
        __syncthreads();

        const uint32_t stg = sb + (uint32_t)((kt & 1) * GP_STAGE) * 4u;

#pragma unroll
        for (int j = 0; j < 2; j++) {
            uint32_t ah[4][4], al[4][4];
#pragma unroll
            for (int mt = 0; mt < 4; mt++) {
                const uint32_t aa = stg +
                    (uint32_t)((arow_l + mt * 16) * GP_STR + j * 8 + acol_l) * 4u;
                ldm4(ah[mt][0], ah[mt][1], ah[mt][2], ah[mt][3], aa);
                ldm4(al[mt][0], al[mt][1], al[mt][2], al[mt][3], aa + GP_TILE * 4);
            }
            uint32_t bh2[4][2], bl2[4][2];
#pragma unroll
            for (int p = 0; p < 2; p++) {
                const uint32_t ba = stg + (uint32_t)(2 * GP_TILE) * 4u +
                    (uint32_t)((brow_l + p * 16) * GP_STR + j * 8 + bcol_l) * 4u;
                ldm4(bh2[2 * p][0], bh2[2 * p][1], bh2[2 * p + 1][0], bh2[2 * p + 1][1], ba);
                ldm4(bl2[2 * p][0], bl2[2 * p][1], bl2[2 * p + 1][0], bl2[2 * p + 1][1],
                     ba + GP_TILE * 4);
            }
#pragma unroll
            for (int nt = 0; nt < 4; nt++)
#pragma unroll
                for (int mt = 0; mt < 4; mt++) {
                    mma_bf16(acc[mt][nt], ah[mt], bh2[nt]);
                    mma_bf16(acc[mt][nt], ah[mt], bl2[nt]);
                    mma_bf16(acc[mt][nt], al[mt], bh2[nt]);
                }
        }
        __syncthreads();
    }
}

// generic GEMM: fp32 or packed output
__global__ void __launch_bounds__(256, 2)
gemm_pk_kernel(const uint32_t* __restrict__ Ah, const uint32_t* __restrict__ Al,
               const uint32_t* __restrict__ Bh, const uint32_t* __restrict__ Bl,
               const float* __restrict__ bias,
               float* __restrict__ outF, uint32_t* __restrict__ outH,
               uint32_t* __restrict__ outL,
               int KH, int Ndim, int packout, int relu, float scale)
{
    extern __shared__ uint32_t smu[];
    const uint32_t sb = smem_u32(smu);
    const int tid = threadIdx.x;
    const int wid = tid >> 5, lane = tid & 31;
    const int by = blockIdx.y * 128, bx = blockIdx.x * 128;
    const int warp_m = (wid >> 2) * 64, warp_n = (wid & 3) * 32;
    const int g = lane >> 2, c = lane & 3;

    float acc[4][4][4];
#pragma unroll
    for (int mt = 0; mt < 4; mt++)
#pragma unroll
        for (int nt = 0; nt < 4; nt++)
#pragma unroll
            for (int i = 0; i < 4; i++) acc[mt][nt][i] = 0.f;

    gemm_core(Ah, Al, Bh, Bl, KH, by, bx, sb, tid, acc);

    const int NH = Ndim >> 1;
#pragma unroll
    for (int mt = 0; mt < 4; mt++) {
        const int r0 = by + warp_m + mt * 16 + g;
#pragma unroll
        for (int nt = 0; nt < 4; nt++) {
            const int c0 = bx + warp_n + nt * 8 + 2 * c;
            const float b0 = bias[c0], b1 = bias[c0 + 1];
            float v00 = (acc[mt][nt][0] + b0) * scale;
            float v01 = (acc[mt][nt][1] + b1) * scale;
            float v10 = (acc[mt][nt][2] + b0) * scale;
            float v11 = (acc[mt][nt][3] + b1) * scale;
            if (relu) {
                v00 = fmaxf(v00, 0.f); v01 = fmaxf(v01, 0.f);
                v10 = fmaxf(v10, 0.f); v11 = fmaxf(v11, 0.f);
            }
            if (packout) {
                uint32_t hi, lo;
                bsplit(v00, v01, hi, lo);
                outH[(size_t)r0 * NH + (c0 >> 1)] = hi;
                outL[(size_t)r0 * NH + (c0 >> 1)] = lo;
                bsplit(v10, v11, hi, lo);
                outH[(size_t)(r0 + 8) * NH + (c0 >> 1)] = hi;
                outL[(size_t)(r0 + 8) * NH + (c0 >> 1)] = lo;
            } else {
                float2 w0, w1;
                w0.x = v00; w0.y = v01; w1.x = v10; w1.y = v11;
                *(float2*)&outF[(size_t)r0 * Ndim + c0] = w0;
                *(float2*)&outF[(size_t)(r0 + 8) * Ndim + c0] = w1;
            }
        }
    }
}

// fused QKV GEMM: blockIdx.x region-dispatch (0..5 Q, 6..11 K, 12..17 V)
__global__ void __launch_bounds__(256, 2)
gemm_qkv_kernel(const uint32_t* __restrict__ Ah, const uint32_t* __restrict__ Al,
                const uint32_t* __restrict__ wqh, const uint32_t* __restrict__ wql,
                const uint32_t* __restrict__ wkh, const uint32_t* __restrict__ wkl,
                const uint32_t* __restrict__ wvh, const uint32_t* __restrict__ wvl,
                const float* __restrict__ bq, const float* __restrict__ bk,
                const float* __restrict__ bv,
                uint32_t* __restrict__ qh, uint32_t* __restrict__ ql,
                uint32_t* __restrict__ kh, uint32_t* __restrict__ kl,
                float* __restrict__ vout)
{
    extern __shared__ uint32_t smu[];
    const uint32_t sb = smem_u32(smu);
    const int region = blockIdx.x / 6;
    const int bx = (blockIdx.x % 6) * 128;
    const int by = blockIdx.y * 128;
    const uint32_t* Bh = (region == 0) ? wqh : (region == 1) ? wkh : wvh;
    const uint32_t* Bl = (region == 0) ? wql : (region == 1) ? wkl : wvl;
    const float* bias = (region == 0) ? bq : (region == 1) ? bk : bv;
    const float scale = (region == 0) ? 0.125f : 1.f;

    const int tid = threadIdx.x;
    const int wid = tid >> 5, lane = tid & 31;
    const int warp_m = (wid >> 2) * 64, warp_n = (wid & 3) * 32;
    const int g = lane >> 2, c = lane & 3;

    float acc[4][4][4];
#pragma unroll
    for (int mt = 0; mt < 4; mt++)
#pragma unroll
        for (int nt = 0; nt < 4; nt++)
#pragma unroll
            for (int i = 0; i < 4; i++) acc[mt][nt][i] = 0.f;

    gemm_core(Ah, Al, Bh, Bl, EH, by, bx, sb, tid, acc);

    uint32_t* outH = (region == 0) ? qh : kh;
    uint32_t* outL = (region == 0) ? ql : kl;
#pragma unroll
    for (int mt = 0; mt < 4; mt++) {
        const int r0 = by + warp_m + mt * 16 + g;
#pragma unroll
        for (int nt = 0; nt < 4; nt++) {
            const int c0 = bx + warp_n + nt * 8 + 2 * c;
            const float b0 = bias[c0], b1 = bias[c0 + 1];
            const float v00 = (acc[mt][nt][0] + b0) * scale;
            const float v01 = (acc[mt][nt][1] + b1) * scale;
            const float v10 = (acc[mt][nt][2] + b0) * scale;
            const float v11 = (acc[mt][nt][3] + b1) * scale;
            if (region < 2) {
                uint32_t hi, lo;
                bsplit(v00, v01, hi, lo);
                outH[(size_t)r0 * EH + (c0 >> 1)] = hi;
                outL[(size_t)r0 * EH + (c0 >> 1)] = lo;
                bsplit(v10, v11, hi, lo);
                outH[(size_t)(r0 + 8) * EH + (c0 >> 1)] = hi;
                outL[(size_t)(r0 + 8) * EH + (c0 >> 1)] = lo;
            } else {
                float2 w0, w1;
                w0.x = v00; w0.y = v01; w1.x = v10; w1.y = v11;
                *(float2*)&vout[(size_t)r0 * E_ + c0] = w0;
                *(float2*)&vout[(size_t)(r0 + 8) * E_ + c0] = w1;
            }
        }
    }
}

// ---------------------------------------------------------------------------
// Tensor-core flash attention, packed Q/K, ldmatrix fragments.
// Br=128, Bc=64, m16n8k16 x3 split. ctx written packed.
// ---------------------------------------------------------------------------
#define FP_STR 36
#define FQH 0
#define FQL (FQH + 128 * FP_STR)
#define FKH (FQL + 128 * FP_STR)
#define FKL (FKH + 64 * FP_STR)
#define FVH (FKL + 64 * FP_STR)
#define FVL (FVH + 64 * FP_STR)
#define FMK (FVL + 64 * FP_STR)
#define FA_SMEM ((FMK + 68) * 4)

__global__ void __launch_bounds__(256, 2)
flash_attn_pk_kernel(const uint32_t* __restrict__ Qh, const uint32_t* __restrict__ Ql,
                     const uint32_t* __restrict__ Kh, const uint32_t* __restrict__ Kl,
                     const float* __restrict__ V, const int* __restrict__ mask,
                     uint32_t* __restrict__ ctxh, uint32_t* __restrict__ ctxl)
{
    extern __shared__ uint32_t us[];
    const uint32_t sbF = smem_u32(us);
    int* mks = (int*)(us + FMK);
    int* flg = mks + 64;

    const int t0 = blockIdx.x * 128;
    const int b = blockIdx.y / H_;
    const int h = blockIdx.y % H_;
    const int tid = threadIdx.x;
    const int w = tid >> 5, lane = tid & 31;
    const int g = lane >> 2, c = lane & 3;
    const int wm = w * 16;

    // ldmatrix lane addressing
    const int qrow_l = wm + (lane & 15);
    const int qcol_l = (lane >> 4) << 2;
    const int krow_l = (lane & 7) + ((lane >> 4) << 3);
    const int kcol_l = ((lane >> 3) & 1) << 2;

    // load packed Q tile [128 rows x 32 kp] hi+lo
#pragma unroll
    for (int i = 0; i < 4; i++) {
        const int id = tid + i * 256;
        const int r = id >> 3, c4 = (id & 7) * 4;
        const size_t go = ((size_t)(t0 + r) * B_ + b) * EH + h * 32 + c4;
        *(uint4*)&us[FQH + r * FP_STR + c4] = *(const uint4*)&Qh[go];
        *(uint4*)&us[FQL + r * FP_STR + c4] = *(const uint4*)&Ql[go];
    }

    float o[8][4];
#pragma unroll
    for (int nt = 0; nt < 8; nt++)
#pragma unroll
        for (int i = 0; i < 4; i++) o[nt][i] = 0.f;
    float m0 = -INFINITY, m1 = -INFINITY, l0s = 0.f, l1s = 0.f;

    for (int s0 = 0; s0 < T_; s0 += 64) {
        __syncthreads();
        if (tid < 64) mks[tid] = mask[(size_t)b * T_ + s0 + tid];
        __syncthreads();
        if (tid < 32) {
            const int un = (mks[tid] == 0) || (mks[tid + 32] == 0);
            const unsigned bal = __ballot_sync(0xffffffffu, un);
            if (lane == 0) flg[0] = (bal == 0u);
        }
        __syncthreads();
        if (flg[0]) continue;

        // packed K tile [64 x 32 kp] hi+lo
#pragma unroll
        for (int i = 0; i < 2; i++) {
            const int id = tid + i * 256;
            const int r = id >> 3, c4 = (id & 7) * 4;
            const size_t go = ((size_t)(s0 + r) * B_ + b) * EH + h * 32 + c4;
            *(uint4*)&us[FKH + r * FP_STR + c4] = *(const uint4*)&Kh[go];
            *(uint4*)&us[FKL + r * FP_STR + c4] = *(const uint4*)&Kl[go];
        }
        // V tile transposed + split: Vt[d][key-pair]
#pragma unroll
        for (int i = 0; i < 2; i++) {
            const int id = tid + i * 256;
            const int kp = id & 31, dblk = id >> 5;
            const float4 va = *(const float4*)&V[((size_t)(s0 + 2 * kp) * B_ + b) * E_ + h * 64 + dblk * 4];
            const float4 vb = *(const float4*)&V[((size_t)(s0 + 2 * kp + 1) * B_ + b) * E_ + h * 64 + dblk * 4];
            uint32_t hi, lo;
            bsplit(va.x, vb.x, hi, lo);
            us[FVH + (dblk * 4 + 0) * FP_STR + kp] = hi; us[FVL + (dblk * 4 + 0) * FP_STR + kp] = lo;
            bsplit(va.y, vb.y, hi, lo);
            us[FVH + (dblk * 4 + 1) * FP_STR + kp] = hi; us[FVL + (dblk * 4 + 1) * FP_STR + kp] = lo;
            bsplit(va.z, vb.z, hi, lo);
            us[FVH + (dblk * 4 + 2) * FP_STR + kp] = hi; us[FVL + (dblk * 4 + 2) * FP_STR + kp] = lo;
            bsplit(va.w, vb.w, hi, lo);
            us[FVH + (dblk * 4 + 3) * FP_STR + kp] = hi; us[FVL + (dblk * 4 + 3) * FP_STR + kp] = lo;
        }
        __syncthreads();

        // ---- S = (Q/8) K^T, 16x64 per warp ----
        float sa[8][4];
#pragma unroll
        for (int nt = 0; nt < 8; nt++)
#pragma unroll
            for (int i = 0; i < 4; i++) sa[nt][i] = 0.f;

#pragma unroll
        for (int j = 0; j < 4; j++) {
            uint32_t qh[4], ql[4];
            const uint32_t qa = sbF + (uint32_t)(FQH + qrow_l * FP_STR + j * 8 + qcol_l) * 4u;
            ldm4(qh[0], qh[1], qh[2], qh[3], qa);
            ldm4(ql[0], ql[1], ql[2], ql[3], qa + (FQL - FQH) * 4);
#pragma unroll
            for (int p = 0; p < 4; p++) {
                uint32_t bh2[2][2], bl2[2][2];
                const uint32_t ka = sbF +
                    (uint32_t)(FKH + (krow_l + p * 16) * FP_STR + j * 8 + kcol_l) * 4u;
                ldm4(bh2[0][0], bh2[0][1], bh2[1][0], bh2[1][1], ka);
                ldm4(bl2[0][0], bl2[0][1], bl2[1][0], bl2[1][1], ka + (FKL - FKH) * 4);
                mma_bf16(sa[2 * p], qh, bh2[0]);
                mma_bf16(sa[2 * p], qh, bl2[0]);
                mma_bf16(sa[2 * p], ql, bh2[0]);
                mma_bf16(sa[2 * p + 1], qh, bh2[1]);
                mma_bf16(sa[2 * p + 1], qh, bl2[1]);
                mma_bf16(sa[2 * p + 1], ql, bh2[1]);
            }
        }

        // ---- online softmax ----
        float mx0 = -INFINITY, mx1 = -INFINITY;
#pragma unroll
        for (int nt = 0; nt < 8; nt++) {
            const int col0 = nt * 8 + 2 * c, col1 = col0 + 1;
            const bool k0m = mks[col0] != 0, k1m = mks[col1] != 0;
            float s0v = sa[nt][0]; if (k0m) s0v = -INFINITY;
            float s1v = sa[nt][1]; if (k1m) s1v = -INFINITY;
            float s2v = sa[nt][2]; if (k0m) s2v = -INFINITY;
            float s3v = sa[nt][3]; if (k1m) s3v = -INFINITY;
            sa[nt][0] = s0v; sa[nt][1] = s1v; sa[nt][2] = s2v; sa[nt][3] = s3v;
            mx0 = fmaxf(mx0, fmaxf(s0v, s1v));
            mx1 = fmaxf(mx1, fmaxf(s2v, s3v));
        }
        mx0 = fmaxf(mx0, __shfl_xor_sync(0xffffffffu, mx0, 1));
        mx0 = fmaxf(mx0, __shfl_xor_sync(0xffffffffu, mx0, 2));
        mx1 = fmaxf(mx1, __shfl_xor_sync(0xffffffffu, mx1, 1));
        mx1 = fmaxf(mx1, __shfl_xor_sync(0xffffffffu, mx1, 2));

        const float mn0 = fmaxf(m0, mx0), mn1 = fmaxf(m1, mx1);
        const float al0 = __expf(m0 - mn0), al1 = __expf(m1 - mn1);
        m0 = mn0; m1 = mn1;

        uint32_t phl[8], phh[8], pll[8], plh[8];
        float su0 = 0.f, su1 = 0.f;
#pragma unroll
        for (int nt = 0; nt < 8; nt++) {
            const float p0 = __expf(sa[nt][0] - mn0);
            const float p1 = __expf(sa[nt][1] - mn0);
            const float p2 = __expf(sa[nt][2] - mn1);
            const float p3 = __expf(sa[nt][3] - mn1);
            su0 += p0 + p1; su1 += p2 + p3;
            bsplit(p0, p1, phl[nt], pll[nt]);
            bsplit(p2, p3, phh[nt], plh[nt]);
        }
        su0 += __shfl_xor_sync(0xffffffffu, su0, 1);
        su0 += __shfl_xor_sync(0xffffffffu, su0, 2);
        su1 += __shfl_xor_sync(0xffffffffu, su1, 1);
        su1 += __shfl_xor_sync(0xffffffffu, su1, 2);
        l0s = l0s * al0 + su0;
        l1s = l1s * al1 + su1;
#pragma unroll
        for (int nt = 0; nt < 8; nt++) {
            o[nt][0] *= al0; o[nt][1] *= al0;
            o[nt][2] *= al1; o[nt][3] *= al1;
        }

        // ---- O += P V (P in registers, V frags via ldmatrix) ----
#pragma unroll
        for (int j = 0; j < 4; j++) {
            uint32_t ah[4], al2[4];
            ah[0] = phl[2 * j];     ah[1] = phh[2 * j];
            ah[2] = phl[2 * j + 1]; ah[3] = phh[2 * j + 1];
            al2[0] = pll[2 * j];     al2[1] = plh[2 * j];
            al2[2] = pll[2 * j + 1]; al2[3] = plh[2 * j + 1];
#pragma unroll
            for (int p = 0; p < 4; p++) {
                uint32_t bh2[2][2], bl2[2][2];
                const uint32_t va = sbF +
                    (uint32_t)(FVH + (krow_l + p * 16) * FP_STR + j * 8 + kcol_l) * 4u;
                ldm4(bh2[0][0], bh2[0][1], bh2[1][0], bh2[1][1], va);
                ldm4(bl2[0][0], bl2[0][1], bl2[1][0], bl2[1][1], va + (FVL - FVH) * 4);
                mma_bf16(o[2 * p], ah, bh2[0]);
                mma_bf16(o[2 * p], ah, bl2[0]);
                mma_bf16(o[2 * p], al2, bh2[0]);
                mma_bf16(o[2 * p + 1], ah, bh2[1]);
                mma_bf16(o[2 * p + 1], ah, bl2[1]);
                mma_bf16(o[2 * p + 1], al2, bh2[1]);
            }
        }
    }

    // writeout: packed ctx
    const float i0 = 1.f / l0s, i1 = 1.f / l1s;
#pragma unroll
    for (int nt = 0; nt < 8; nt++) {
        const int kp = h * 32 + nt * 4 + c;
        uint32_t hi, lo;
        bsplit(o[nt][0] * i0, o[nt][1] * i0, hi, lo);
        ctxh[((size_t)(t0 + wm + g) * B_ + b) * EH + kp] = hi;
        ctxl[((size_t)(t0 + wm + g) * B_ + b) * EH + kp] = lo;
        bsplit(o[nt][2] * i1, o[nt][3] * i1, hi, lo);
        ctxh[((size_t)(t0 + wm + g + 8) * B_ + b) * EH + kp] = hi;
        ctxl[((size_t)(t0 + wm + g + 8) * B_ + b) * EH + kp] = lo;
    }
}

// ---------------------------------------------------------------------------
// Fused add-residual + LayerNorm
// ---------------------------------------------------------------------------
__device__ __forceinline__ float warpReduceSum(float v) {
#pragma unroll
    for (int o = 16; o; o >>= 1) v += __shfl_xor_sync(0xffffffffu, v, o);
    return v;
}

__global__ void __launch_bounds__(256)
add_ln_kernel(const float* __restrict__ a, const float* __restrict__ r,
              const float* __restrict__ g, const float* __restrict__ be,
              float* __restrict__ out)
{
    const int row = blockIdx.x;
    const int tid = threadIdx.x;
    const float* pa = a + (size_t)row * E_;
    const float* pr = r + (size_t)row * E_;

    float v0 = pa[tid] + pr[tid];
    float v1 = pa[tid + 256] + pr[tid + 256];
    float v2 = pa[tid + 512] + pr[tid + 512];

    __shared__ float red[8];
    const int wid = tid >> 5, lane = tid & 31;

    float s = warpReduceSum(v0 + v1 + v2);
    if (lane == 0) red[wid] = s;
    __syncthreads();
    float tot = 0.f;
#pragma unroll
    for (int i = 0; i < 8; i++) tot += red[i];
    const float mean = tot * (1.f / (float)E_);

    float d0 = v0 - mean, d1 = v1 - mean, d2 = v2 - mean;
    float sq = warpReduceSum(d0 * d0 + d1 * d1 + d2 * d2);
    __syncthreads();
    if (lane == 0) red[wid] = sq;
    __syncthreads();
    tot = 0.f;
#pragma unroll
    for (int i = 0; i < 8; i++) tot += red[i];
    const float inv = rsqrtf(tot * (1.f / (float)E_) + 1e-5f);

    float* po = out + (size_t)row * E_;
    po[tid]       = d0 * inv * g[tid]       + be[tid];
    po[tid + 256] = d1 * inv * g[tid + 256] + be[tid + 256];
    po[tid + 512] = d2 * inv * g[tid + 512] + be[tid + 512];
}

__global__ void __launch_bounds__(128)
add_ln_pack_kernel(const float* __restrict__ a, const float* __restrict__ r,
                   const float* __restrict__ g, const float* __restrict__ be,
                   float* __restrict__ outF, uint32_t* __restrict__ outH,
                   uint32_t* __restrict__ outL)
{
    const int row = blockIdx.x;
    const int tid = threadIdx.x;
    const float* pa = a + (size_t)row * E_;
    const float* pr = r + (size_t)row * E_;

    float2 v[3];
#pragma unroll
    for (int i = 0; i < 3; i++) {
        const int o = 2 * (tid + i * 128);
        const float2 x = *(const float2*)&pa[o];
        const float2 y = *(const float2*)&pr[o];
        v[i].x = x.x + y.x;
        v[i].y = x.y + y.y;
    }

    __shared__ float red[4];
    const int wid = tid >> 5, lane = tid & 31;

    float s = warpReduceSum(v[0].x + v[0].y + v[1].x + v[1].y + v[2].x + v[2].y);
    if (lane == 0) red[wid] = s;
    __syncthreads();
    float tot = red[0] + red[1] + red[2] + red[3];
    const float mean = tot * (1.f / (float)E_);

    float sq = 0.f;
#pragma unroll
    for (int i = 0; i < 3; i++) {
        v[i].x -= mean; v[i].y -= mean;
        sq += v[i].x * v[i].x + v[i].y * v[i].y;
    }
    sq = warpReduceSum(sq);
    __syncthreads();
    if (lane == 0) red[wid] = sq;
    __syncthreads();
    tot = red[0] + red[1] + red[2] + red[3];
    const float inv = rsqrtf(tot * (1.f / (float)E_) + 1e-5f);

    float* po = outF + (size_t)row * E_;
    uint32_t* ph = outH + (size_t)row * EH;
    uint32_t* pl = outL + (size_t)row * EH;
#pragma unroll
    for (int i = 0; i < 3; i++) {
        const int p = tid + i * 128;
        const float2 gg = *(const float2*)&g[2 * p];
        const float2 bb = *(const float2*)&be[2 * p];
        float2 w;
        w.x = v[i].x * inv * gg.x + bb.x;
        w.y = v[i].y * inv * gg.y + bb.y;
        *(float2*)&po[2 * p] = w;
        uint32_t hi, lo;
        bsplit(w.x, w.y, hi, lo);
        ph[p] = hi;
        pl[p] = lo;
    }
}

// ---------------------------------------------------------------------------
// Launch
// ---------------------------------------------------------------------------
extern "C" void kernel_launch(void* const* d_in, const int* in_sizes, int n_in,
                              void* d_out, int out_size)
{
    const float* state = (const float*)d_in[0];
    const int* mask = (const int*)d_in[1];
    const float* Wq = (const float*)d_in[2];
    const float* bq = (const float*)d_in[3];
    const float* Wk = (const float*)d_in[4];
    const float* bk = (const float*)d_in[5];
    const float* Wv = (const float*)d_in[6];
    const float* bv = (const float*)d_in[7];
    const float* Wo = (const float*)d_in[8];
    const float* bo = (const float*)d_in[9];
    const float* ln1g = (const float*)d_in[10];
    const float* ln1b = (const float*)d_in[11];
    const float* W1 = (const float*)d_in[12];
    const float* b1 = (const float*)d_in[13];
    const float* W2 = (const float*)d_in[14];
    const float* b2 = (const float*)d_in[15];
    const float* ln2g = (const float*)d_in[16];
    const float* ln2b = (const float*)d_in[17];
    float* out = (float*)d_out;

    uint32_t *sth, *stl, *qh, *ql, *kh, *kl, *ch, *cl, *x1h, *x1l, *h1h, *h1l;
    float *vp, *t0p, *x1p;
    uint32_t *wqh, *wql, *wkh, *wkl, *wvh, *wvl, *woh, *wol, *w1h, *w1l, *w2h, *w2l;
    cudaGetSymbolAddress((void**)&sth, g_sth); cudaGetSymbolAddress((void**)&stl, g_stl);
    cudaGetSymbolAddress((void**)&qh, g_qh);   cudaGetSymbolAddress((void**)&ql, g_ql);
    cudaGetSymbolAddress((void**)&kh, g_kh);   cudaGetSymbolAddress((void**)&kl, g_kl);
    cudaGetSymbolAddress((void**)&vp, g_v);
    cudaGetSymbolAddress((void**)&ch, g_ch);   cudaGetSymbolAddress((void**)&cl, g_cl);
    cudaGetSymbolAddress((void**)&t0p, g_t0);
    cudaGetSymbolAddress((void**)&x1p, g_x1);
    cudaGetSymbolAddress((void**)&x1h, g_x1h); cudaGetSymbolAddress((void**)&x1l, g_x1l);
    cudaGetSymbolAddress((void**)&h1h, g_h1h); cudaGetSymbolAddress((void**)&h1l, g_h1l);
    cudaGetSymbolAddress((void**)&wqh, g_wqTh); cudaGetSymbolAddress((void**)&wql, g_wqTl);
    cudaGetSymbolAddress((void**)&wkh, g_wkTh); cudaGetSymbolAddress((void**)&wkl, g_wkTl);
    cudaGetSymbolAddress((void**)&wvh, g_wvTh); cudaGetSymbolAddress((void**)&wvl, g_wvTl);
    cudaGetSymbolAddress((void**)&woh, g_woTh); cudaGetSymbolAddress((void**)&wol, g_woTl);
    cudaGetSymbolAddress((void**)&w1h, g_w1Th); cudaGetSymbolAddress((void**)&w1l, g_w1Tl);
    cudaGetSymbolAddress((void**)&w2h, g_w2Th); cudaGetSymbolAddress((void**)&w2l, g_w2Tl);

    cudaFuncSetAttribute(gemm_pk_kernel, cudaFuncAttributeMaxDynamicSharedMemorySize, GEMM_SMEM);
    cudaFuncSetAttribute(gemm_qkv_kernel, cudaFuncAttributeMaxDynamicSharedMemorySize, GEMM_SMEM);
    cudaFuncSetAttribute(flash_attn_pk_kernel, cudaFuncAttributeMaxDynamicSharedMemorySize, FA_SMEM);

    // pack inputs
    pack_rows_kernel<<<(M_ * EH + 255) / 256, 256>>>(state, sth, stl, M_ * EH);
    dim3 tb(32, 8);
    packT_kernel<<<dim3(E_ / 32, E_ / 32), tb>>>(Wq, wqh, wql, E_, E_);
    packT_kernel<<<dim3(E_ / 32, E_ / 32), tb>>>(Wk, wkh, wkl, E_, E_);
    packT_kernel<<<dim3(E_ / 32, E_ / 32), tb>>>(Wv, wvh, wvl, E_, E_);
    packT_kernel<<<dim3(E_ / 32, E_ / 32), tb>>>(Wo, woh, wol, E_, E_);
    packT_kernel<<<dim3(F_ / 32, E_ / 32), tb>>>(W1, w1h, w1l, E_, F_);
    packT_kernel<<<dim3(E_ / 32, F_ / 32), tb>>>(W2, w2h, w2l, F_, E_);

    dim3 gQKV(18, M_ / 128);   // fused QKV: 576 CTAs
    dim3 gE(E_ / 128, M_ / 128);
    dim3 gF(F_ / 128, M_ / 128);

    // fused QKV projection
    gemm_qkv_kernel<<<gQKV, 256, GEMM_SMEM>>>(sth, stl, wqh, wql, wkh, wkl, wvh, wvl,
                                              bq, bk, bv, qh, ql, kh, kl, vp);

    // attention -> packed ctx
    flash_attn_pk_kernel<<<dim3(T_ / 128, B_ * H_), 256, FA_SMEM>>>(qh, ql, kh, kl, vp, mask, ch, cl);

    // output projection + LN1
    gemm_pk_kernel<<<gE, 256, GEMM_SMEM>>>(ch, cl, woh, wol, bo, t0p, nullptr, nullptr, EH, E_, 0, 0, 1.f);
    add_ln_pack_kernel<<<M_, 128>>>(t0p, state, ln1g, ln1b, x1p, x1h, x1l);

    // FFN + LN2
    gemm_pk_kernel<<<gF, 256, GEMM_SMEM>>>(x1h, x1l, w1h, w1l, b1, nullptr, h1h, h1l, EH, F_, 1, 1, 1.f);
    gemm_pk_kernel<<<gE, 256, GEMM_SMEM>>>(h1h, h1l, w2h, w2l, b2, t0p, nullptr, nullptr, FH, E_, 0, 0, 1.f);
    add_ln_kernel<<<M_, 256>>>(t0p, x1p, ln2g, ln2b, out);
}

// round 12
// speedup vs baseline: 3.2322x; 1.0298x over previous
#include <cuda_runtime.h>
#include <cuda_bf16.h>
#include <math.h>
#include <stdint.h>

// Problem constants
#define T_ 2048
#define B_ 2
#define E_ 768
#define H_ 12
#define D_ 64
#define F_ 3072
#define M_ (T_ * B_)   // 4096 rows
#define EH (E_ / 2)
#define FH (F_ / 2)

// ---------------------------------------------------------------------------
// Scratch (device globals — no cudaMalloc allowed)
// ---------------------------------------------------------------------------
__device__ uint32_t g_sth[M_ * EH], g_stl[M_ * EH];   // packed state
__device__ uint32_t g_qh[M_ * EH],  g_ql[M_ * EH];    // packed Q (pre-scaled 1/8)
__device__ uint32_t g_kh[M_ * EH],  g_kl[M_ * EH];    // packed K
__device__ float    g_v[M_ * E_];                     // V fp32
__device__ uint32_t g_ch[M_ * EH],  g_cl[M_ * EH];    // packed ctx
__device__ float    g_t0[M_ * E_];                    // attn_out / ffn_out fp32
__device__ float    g_x1[M_ * E_];                    // LN1 out fp32 (residual)
__device__ uint32_t g_x1h[M_ * EH], g_x1l[M_ * EH];   // LN1 out packed
__device__ uint32_t g_h1h[M_ * FH], g_h1l[M_ * FH];   // FFN hidden packed
// pre-split transposed weights: [N][K/2]
__device__ uint32_t g_wqTh[E_ * EH], g_wqTl[E_ * EH];
__device__ uint32_t g_wkTh[E_ * EH], g_wkTl[E_ * EH];
__device__ uint32_t g_wvTh[E_ * EH], g_wvTl[E_ * EH];
__device__ uint32_t g_woTh[E_ * EH], g_woTl[E_ * EH];
__device__ uint32_t g_w1Th[F_ * EH], g_w1Tl[F_ * EH];
__device__ uint32_t g_w2Th[E_ * FH], g_w2Tl[E_ * FH];

// ---------------------------------------------------------------------------
// Helpers (baseline PTX only — compute_103 virtual arch)
// ---------------------------------------------------------------------------
__device__ __forceinline__ uint32_t smem_u32(const void* p) {
    uint32_t a;
    asm("{ .reg .u64 t; cvta.to.shared.u64 t, %1; cvt.u32.u64 %0, t; }" : "=r"(a) : "l"(p));
    return a;
}
__device__ __forceinline__ void cp16(uint32_t dst, const void* src) {
    asm volatile("cp.async.cg.shared.global [%0], [%1], 16;" :: "r"(dst), "l"(src));
}
#define CP_COMMIT() asm volatile("cp.async.commit_group;" ::: "memory")
#define CP_WAIT(n)  asm volatile("cp.async.wait_group %0;" :: "n"(n) : "memory")

__device__ __forceinline__ void bsplit(float x, float y, uint32_t& hi, uint32_t& lo) {
    __nv_bfloat162 h = __floats2bfloat162_rn(x, y);
    const float hx = __low2float(h), hy = __high2float(h);
    __nv_bfloat162 l = __floats2bfloat162_rn(x - hx, y - hy);
    hi = *reinterpret_cast<uint32_t*>(&h);
    lo = *reinterpret_cast<uint32_t*>(&l);
}

__device__ __forceinline__ void mma_bf16(float* d, const uint32_t* a, const uint32_t* b) {
    asm volatile("mma.sync.aligned.m16n8k16.row.col.f32.bf16.bf16.f32 "
                 "{%0,%1,%2,%3}, {%4,%5,%6,%7}, {%8,%9}, {%0,%1,%2,%3};"
                 : "+f"(d[0]), "+f"(d[1]), "+f"(d[2]), "+f"(d[3])
                 : "r"(a[0]), "r"(a[1]), "r"(a[2]), "r"(a[3]), "r"(b[0]), "r"(b[1]));
}

__device__ __forceinline__ void ldm4(uint32_t& r0, uint32_t& r1, uint32_t& r2,
                                     uint32_t& r3, uint32_t a) {
    asm volatile("ldmatrix.sync.aligned.m8n8.x4.shared.b16 {%0,%1,%2,%3}, [%4];"
                 : "=r"(r0), "=r"(r1), "=r"(r2), "=r"(r3) : "r"(a));
}

// ---------------------------------------------------------------------------
// Fused pack kernel: pack_rows (region 0) + 6x transpose-pack (regions 1..6).
// Single launch to avoid per-launch latency of 7 tiny kernels.
// ---------------------------------------------------------------------------
#define PK_ROWS_BLKS (M_ * EH / 256)      // 6144
#define PK_E_BLKS 576                      // 24x24 per ExE weight
#define PK_F_BLKS 2304                     // 96x24 / 24x96

__global__ void __launch_bounds__(256)
pack_all_kernel(const float* __restrict__ state,
                const float* __restrict__ Wq, const float* __restrict__ Wk,
                const float* __restrict__ Wv, const float* __restrict__ Wo,
                const float* __restrict__ W1, const float* __restrict__ W2,
                uint32_t* __restrict__ sth, uint32_t* __restrict__ stl,
                uint32_t* __restrict__ wqh, uint32_t* __restrict__ wql,
                uint32_t* __restrict__ wkh, uint32_t* __restrict__ wkl,
                uint32_t* __restrict__ wvh, uint32_t* __restrict__ wvl,
                uint32_t* __restrict__ woh, uint32_t* __restrict__ wol,
                uint32_t* __restrict__ w1h, uint32_t* __restrict__ w1l,
                uint32_t* __restrict__ w2h, uint32_t* __restrict__ w2l)
{
    __shared__ float t[32][33];
    const int tid = threadIdx.x;
    int bid = blockIdx.x;

    if (bid < PK_ROWS_BLKS) {
        const int i = bid * 256 + tid;
        const float2 v = *(const float2*)&state[2 * i];
        uint32_t hi, lo;
        bsplit(v.x, v.y, hi, lo);
        sth[i] = hi;
        stl[i] = lo;
        return;
    }
    bid -= PK_ROWS_BLKS;

    const float* in;
    uint32_t *oh, *ol;
    int R, gx, C, idx;
    if (bid < PK_E_BLKS)          { in = Wq; oh = wqh; ol = wql; R = E_; C = E_; gx = 24; idx = bid; }
    else if (bid < 2 * PK_E_BLKS) { in = Wk; oh = wkh; ol = wkl; R = E_; C = E_; gx = 24; idx = bid - PK_E_BLKS; }
    else if (bid < 3 * PK_E_BLKS) { in = Wv; oh = wvh; ol = wvl; R = E_; C = E_; gx = 24; idx = bid - 2 * PK_E_BLKS; }
    else if (bid < 4 * PK_E_BLKS) { in = Wo; oh = woh; ol = wol; R = E_; C = E_; gx = 24; idx = bid - 3 * PK_E_BLKS; }
    else if (bid < 4 * PK_E_BLKS + PK_F_BLKS)
                                  { in = W1; oh = w1h; ol = w1l; R = E_; C = F_; gx = 96; idx = bid - 4 * PK_E_BLKS; }
    else                          { in = W2; oh = w2h; ol = w2l; R = F_; C = E_; gx = 24; idx = bid - 4 * PK_E_BLKS - PK_F_BLKS; }

    const int bx = (idx % gx) * 32;   // n offset
    const int by = (idx / gx) * 32;   // k offset
    const int x = tid & 31, y = tid >> 5;
#pragma unroll
    for (int j = 0; j < 32; j += 8)
        t[y + j][x] = in[(size_t)(by + y + j) * C + bx + x];
    __syncthreads();
    const int KH2 = R >> 1;
#pragma unroll
    for (int i = 0; i < 2; i++) {
        const int n = (tid >> 4) + i * 16;
        const int kp = tid & 15;
        uint32_t hi, lo;
        bsplit(t[2 * kp][n], t[2 * kp + 1][n], hi, lo);
        oh[(size_t)(bx + n) * KH2 + (by >> 1) + kp] = hi;
        ol[(size_t)(bx + n) * KH2 + (by >> 1) + kp] = lo;
    }
}

// ---------------------------------------------------------------------------
// Shared GEMM mainloop core, ONE barrier per K-iter.
// ---------------------------------------------------------------------------
#define GP_STR 20
#define GP_TILE (128 * GP_STR)          // 2560 u32
#define GP_STAGE (4 * GP_TILE)          // Ah,Al,Bh,Bl
#define GEMM_SMEM (2 * GP_STAGE * 4)    // 81920 bytes

__device__ __forceinline__ void gemm_core(
    const uint32_t* __restrict__ Ah, const uint32_t* __restrict__ Al,
    const uint32_t* __restrict__ Bh, const uint32_t* __restrict__ Bl,
    int KH, int by, int bx, uint32_t sb, int tid, float acc[4][4][4])
{
    const int wid = tid >> 5, lane = tid & 31;
    const int warp_m = (wid >> 2) * 64;
    const int warp_n = (wid & 3) * 32;

    const int arow_l = warp_m + (lane & 15);
    const int acol_l = (lane >> 4) << 2;
    const int brow_l = warp_n + (lane & 7) + ((lane >> 4) << 3);
    const int bcol_l = ((lane >> 3) & 1) << 2;

    const int NT = KH / 16;

    auto load_stage = [&](int buf, int kt) {
        const uint32_t base = sb + (uint32_t)(buf * GP_STAGE) * 4u;
#pragma unroll
        for (int i = 0; i < 2; i++) {
            const int id = tid + i * 256;
            const int row = id >> 2, c4 = id & 3;
            const uint32_t so = (uint32_t)(row * GP_STR + c4 * 4) * 4u;
            const size_t ga = (size_t)(by + row) * KH + kt * 16 + c4 * 4;
            const size_t gb = (size_t)(bx + row) * KH + kt * 16 + c4 * 4;
            cp16(base + so, &Ah[ga]);
            cp16(base + (uint32_t)(GP_TILE * 4) + so, &Al[ga]);
            cp16(base + (uint32_t)(2 * GP_TILE * 4) + so, &Bh[gb]);
            cp16(base + (uint32_t)(3 * GP_TILE * 4) + so, &Bl[gb]);
        }
        CP_COMMIT();
    };

    load_stage(0, 0);

    for (int kt = 0; kt < NT; kt++) {
        CP_WAIT(0);
        __syncthreads();   // buf[kt&1] visible; all threads done computing buf[kt&1] last round
        if (kt + 1 < NT) load_stage((kt + 1) & 1, kt + 1);   // fills other buffer, overlaps compute

        const uint32_t stg = sb + (uint32_t)((kt & 1) * GP_STAGE) * 4u;

#pragma unroll
        for (int j = 0; j < 2; j++) {
            uint32_t ah[4][4], al[4][4];
#pragma unroll
            for (int mt = 0; mt < 4; mt++) {
                const uint32_t aa = stg +
                    (uint32_t)((arow_l + mt * 16) * GP_STR + j * 8 + acol_l) * 4u;
                ldm4(ah[mt][0], ah[mt][1], ah[mt][2], ah[mt][3], aa);
                ldm4(al[mt][0], al[mt][1], al[mt][2], al[mt][3], aa + GP_TILE * 4);
            }
            uint32_t bh2[4][2], bl2[4][2];
#pragma unroll
            for (int p = 0; p < 2; p++) {
                const uint32_t ba = stg + (uint32_t)(2 * GP_TILE) * 4u +
                    (uint32_t)((brow_l + p * 16) * GP_STR + j * 8 + bcol_l) * 4u;
                ldm4(bh2[2 * p][0], bh2[2 * p][1], bh2[2 * p + 1][0], bh2[2 * p + 1][1], ba);
                ldm4(bl2[2 * p][0], bl2[2 * p][1], bl2[2 * p + 1][0], bl2[2 * p + 1][1],
                     ba + GP_TILE * 4);
            }
#pragma unroll
            for (int nt = 0; nt < 4; nt++)
#pragma unroll
                for (int mt = 0; mt < 4; mt++) {
                    mma_bf16(acc[mt][nt], ah[mt], bh2[nt]);
                    mma_bf16(acc[mt][nt], ah[mt], bl2[nt]);
                    mma_bf16(acc[mt][nt], al[mt], bh2[nt]);
                }
        }
    }
}

// generic GEMM: fp32 or packed output
__global__ void __launch_bounds__(256, 2)
gemm_pk_kernel(const uint32_t* __restrict__ Ah, const uint32_t* __restrict__ Al,
               const uint32_t* __restrict__ Bh, const uint32_t* __restrict__ Bl,
               const float* __restrict__ bias,
               float* __restrict__ outF, uint32_t* __restrict__ outH,
               uint32_t* __restrict__ outL,
               int KH, int Ndim, int packout, int relu, float scale)
{
    extern __shared__ uint32_t smu[];
    const uint32_t sb = smem_u32(smu);
    const int tid = threadIdx.x;
    const int wid = tid >> 5, lane = tid & 31;
    const int by = blockIdx.y * 128, bx = blockIdx.x * 128;
    const int warp_m = (wid >> 2) * 64, warp_n = (wid & 3) * 32;
    const int g = lane >> 2, c = lane & 3;

    float acc[4][4][4];
#pragma unroll
    for (int mt = 0; mt < 4; mt++)
#pragma unroll
        for (int nt = 0; nt < 4; nt++)
#pragma unroll
            for (int i = 0; i < 4; i++) acc[mt][nt][i] = 0.f;

    gemm_core(Ah, Al, Bh, Bl, KH, by, bx, sb, tid, acc);

    const int NH = Ndim >> 1;
#pragma unroll
    for (int mt = 0; mt < 4; mt++) {
        const int r0 = by + warp_m + mt * 16 + g;
#pragma unroll
        for (int nt = 0; nt < 4; nt++) {
            const int c0 = bx + warp_n + nt * 8 + 2 * c;
            const float b0 = bias[c0], b1 = bias[c0 + 1];
            float v00 = (acc[mt][nt][0] + b0) * scale;
            float v01 = (acc[mt][nt][1] + b1) * scale;
            float v10 = (acc[mt][nt][2] + b0) * scale;
            float v11 = (acc[mt][nt][3] + b1) * scale;
            if (relu) {
                v00 = fmaxf(v00, 0.f); v01 = fmaxf(v01, 0.f);
                v10 = fmaxf(v10, 0.f); v11 = fmaxf(v11, 0.f);
            }
            if (packout) {
                uint32_t hi, lo;
                bsplit(v00, v01, hi, lo);
                outH[(size_t)r0 * NH + (c0 >> 1)] = hi;
                outL[(size_t)r0 * NH + (c0 >> 1)] = lo;
                bsplit(v10, v11, hi, lo);
                outH[(size_t)(r0 + 8) * NH + (c0 >> 1)] = hi;
                outL[(size_t)(r0 + 8) * NH + (c0 >> 1)] = lo;
            } else {
                float2 w0, w1;
                w0.x = v00; w0.y = v01; w1.x = v10; w1.y = v11;
                *(float2*)&outF[(size_t)r0 * Ndim + c0] = w0;
                *(float2*)&outF[(size_t)(r0 + 8) * Ndim + c0] = w1;
            }
        }
    }
}

// fused QKV GEMM: blockIdx.x region-dispatch (0..5 Q, 6..11 K, 12..17 V)
__global__ void __launch_bounds__(256, 2)
gemm_qkv_kernel(const uint32_t* __restrict__ Ah, const uint32_t* __restrict__ Al,
                const uint32_t* __restrict__ wqh, const uint32_t* __restrict__ wql,
                const uint32_t* __restrict__ wkh, const uint32_t* __restrict__ wkl,
                const uint32_t* __restrict__ wvh, const uint32_t* __restrict__ wvl,
                const float* __restrict__ bq, const float* __restrict__ bk,
                const float* __restrict__ bv,
                uint32_t* __restrict__ qh, uint32_t* __restrict__ ql,
                uint32_t* __restrict__ kh, uint32_t* __restrict__ kl,
                float* __restrict__ vout)
{
    extern __shared__ uint32_t smu[];
    const uint32_t sb = smem_u32(smu);
    const int region = blockIdx.x / 6;
    const int bx = (blockIdx.x % 6) * 128;
    const int by = blockIdx.y * 128;
    const uint32_t* Bh = (region == 0) ? wqh : (region == 1) ? wkh : wvh;
    const uint32_t* Bl = (region == 0) ? wql : (region == 1) ? wkl : wvl;
    const float* bias = (region == 0) ? bq : (region == 1) ? bk : bv;
    const float scale = (region == 0) ? 0.125f : 1.f;

    const int tid = threadIdx.x;
    const int wid = tid >> 5, lane = tid & 31;
    const int warp_m = (wid >> 2) * 64, warp_n = (wid & 3) * 32;
    const int g = lane >> 2, c = lane & 3;

    float acc[4][4][4];
#pragma unroll
    for (int mt = 0; mt < 4; mt++)
#pragma unroll
        for (int nt = 0; nt < 4; nt++)
#pragma unroll
            for (int i = 0; i < 4; i++) acc[mt][nt][i] = 0.f;

    gemm_core(Ah, Al, Bh, Bl, EH, by, bx, sb, tid, acc);

    uint32_t* outH = (region == 0) ? qh : kh;
    uint32_t* outL = (region == 0) ? ql : kl;
#pragma unroll
    for (int mt = 0; mt < 4; mt++) {
        const int r0 = by + warp_m + mt * 16 + g;
#pragma unroll
        for (int nt = 0; nt < 4; nt++) {
            const int c0 = bx + warp_n + nt * 8 + 2 * c;
            const float b0 = bias[c0], b1 = bias[c0 + 1];
            const float v00 = (acc[mt][nt][0] + b0) * scale;
            const float v01 = (acc[mt][nt][1] + b1) * scale;
            const float v10 = (acc[mt][nt][2] + b0) * scale;
            const float v11 = (acc[mt][nt][3] + b1) * scale;
            if (region < 2) {
                uint32_t hi, lo;
                bsplit(v00, v01, hi, lo);
                outH[(size_t)r0 * EH + (c0 >> 1)] = hi;
                outL[(size_t)r0 * EH + (c0 >> 1)] = lo;
                bsplit(v10, v11, hi, lo);
                outH[(size_t)(r0 + 8) * EH + (c0 >> 1)] = hi;
                outL[(size_t)(r0 + 8) * EH + (c0 >> 1)] = lo;
            } else {
                float2 w0, w1;
                w0.x = v00; w0.y = v01; w1.x = v10; w1.y = v11;
                *(float2*)&vout[(size_t)r0 * E_ + c0] = w0;
                *(float2*)&vout[(size_t)(r0 + 8) * E_ + c0] = w1;
            }
        }
    }
}

// ---------------------------------------------------------------------------
// Tensor-core flash attention. Mask precomputed once (bytes + per-tile skip
// flags in smem); 2 barriers per live key tile, 1 per skipped tile.
// ---------------------------------------------------------------------------
#define FP_STR 36
#define FQH 0
#define FQL (FQH + 128 * FP_STR)
#define FKH (FQL + 128 * FP_STR)
#define FKL (FKH + 64 * FP_STR)
#define FVH (FKL + 64 * FP_STR)
#define FVL (FVH + 64 * FP_STR)
#define FMKB (FVL + 64 * FP_STR)          // 2048 mask bytes = 512 words
#define FSKIP (FMKB + 512)                // 32 skip flags
#define FA_SMEM ((FSKIP + 32) * 4)

__global__ void __launch_bounds__(256, 2)
flash_attn_pk_kernel(const uint32_t* __restrict__ Qh, const uint32_t* __restrict__ Ql,
                     const uint32_t* __restrict__ Kh, const uint32_t* __restrict__ Kl,
                     const float* __restrict__ V, const int* __restrict__ mask,
                     uint32_t* __restrict__ ctxh, uint32_t* __restrict__ ctxl)
{
    extern __shared__ uint32_t us[];
    const uint32_t sbF = smem_u32(us);
    char* mkb = (char*)(us + FMKB);
    int* skip = (int*)(us + FSKIP);

    const int t0 = blockIdx.x * 128;
    const int b = blockIdx.y / H_;
    const int h = blockIdx.y % H_;
    const int tid = threadIdx.x;
    const int w = tid >> 5, lane = tid & 31;
    const int g = lane >> 2, c = lane & 3;
    const int wm = w * 16;

    const int qrow_l = wm + (lane & 15);
    const int qcol_l = (lane >> 4) << 2;
    const int krow_l = (lane & 7) + ((lane >> 4) << 3);
    const int kcol_l = ((lane >> 3) & 1) << 2;

    // ---- one-time: Q tile + mask bytes + per-tile skip flags ----
#pragma unroll
    for (int i = 0; i < 4; i++) {
        const int id = tid + i * 256;
        const int r = id >> 3, c4 = (id & 7) * 4;
        const size_t go = ((size_t)(t0 + r) * B_ + b) * EH + h * 32 + c4;
        *(uint4*)&us[FQH + r * FP_STR + c4] = *(const uint4*)&Qh[go];
        *(uint4*)&us[FQL + r * FP_STR + c4] = *(const uint4*)&Ql[go];
    }
#pragma unroll
    for (int i = 0; i < 8; i++)
        mkb[tid + i * 256] = (char)(mask[(size_t)b * T_ + tid + i * 256] != 0);
    __syncthreads();
    if (tid < 32) {
        int all = 1;
#pragma unroll
        for (int j = 0; j < 64; j++) all &= (int)mkb[tid * 64 + j];
        skip[tid] = all;
    }
    __syncthreads();

    float o[8][4];
#pragma unroll
    for (int nt = 0; nt < 8; nt++)
#pragma unroll
        for (int i = 0; i < 4; i++) o[nt][i] = 0.f;
    float m0 = -INFINITY, m1 = -INFINITY, l0s = 0.f, l1s = 0.f;

    for (int s0 = 0; s0 < T_; s0 += 64) {
        __syncthreads();   // K/V buffer reuse barrier
        if (skip[s0 >> 6]) continue;   // uniform smem read, whole block skips

        // packed K tile [64 x 32 kp] hi+lo
#pragma unroll
        for (int i = 0; i < 2; i++) {
            const int id = tid + i * 256;
            const int r = id >> 3, c4 = (id & 7) * 4;
            const size_t go = ((size_t)(s0 + r) * B_ + b) * EH + h * 32 + c4;
            *(uint4*)&us[FKH + r * FP_STR + c4] = *(const uint4*)&Kh[go];
            *(uint4*)&us[FKL + r * FP_STR + c4] = *(const uint4*)&Kl[go];
        }
        // V tile transposed + split: Vt[d][key-pair]
#pragma unroll
        for (int i = 0; i < 2; i++) {
            const int id = tid + i * 256;
            const int kp = id & 31, dblk = id >> 5;
            const float4 va = *(const float4*)&V[((size_t)(s0 + 2 * kp) * B_ + b) * E_ + h * 64 + dblk * 4];
            const float4 vb = *(const float4*)&V[((size_t)(s0 + 2 * kp + 1) * B_ + b) * E_ + h * 64 + dblk * 4];
            uint32_t hi, lo;
            bsplit(va.x, vb.x, hi, lo);
            us[FVH + (dblk * 4 + 0) * FP_STR + kp] = hi; us[FVL + (dblk * 4 + 0) * FP_STR + kp] = lo;
            bsplit(va.y, vb.y, hi, lo);
            us[FVH + (dblk * 4 + 1) * FP_STR + kp] = hi; us[FVL + (dblk * 4 + 1) * FP_STR + kp] = lo;
            bsplit(va.z, vb.z, hi, lo);
            us[FVH + (dblk * 4 + 2) * FP_STR + kp] = hi; us[FVL + (dblk * 4 + 2) * FP_STR + kp] = lo;
            bsplit(va.w, vb.w, hi, lo);
            us[FVH + (dblk * 4 + 3) * FP_STR + kp] = hi; us[FVL + (dblk * 4 + 3) * FP_STR + kp] = lo;
        }
        __syncthreads();

        // ---- S = (Q/8) K^T ----
        float sa[8][4];
#pragma unroll
        for (int nt = 0; nt < 8; nt++)
#pragma unroll
            for (int i = 0; i < 4; i++) sa[nt][i] = 0.f;

#pragma unroll
        for (int j = 0; j < 4; j++) {
            uint32_t qh[4], ql[4];
            const uint32_t qa = sbF + (uint32_t)(FQH + qrow_l * FP_STR + j * 8 + qcol_l) * 4u;
            ldm4(qh[0], qh[1], qh[2], qh[3], qa);
            ldm4(ql[0], ql[1], ql[2], ql[3], qa + (FQL - FQH) * 4);
#pragma unroll
            for (int p = 0; p < 4; p++) {
                uint32_t bh2[2][2], bl2[2][2];
                const uint32_t ka = sbF +
                    (uint32_t)(FKH + (krow_l + p * 16) * FP_STR + j * 8 + kcol_l) * 4u;
                ldm4(bh2[0][0], bh2[0][1], bh2[1][0], bh2[1][1], ka);
                ldm4(bl2[0][0], bl2[0][1], bl2[1][0], bl2[1][1], ka + (FKL - FKH) * 4);
                mma_bf16(sa[2 * p], qh, bh2[0]);
                mma_bf16(sa[2 * p], qh, bl2[0]);
                mma_bf16(sa[2 * p], ql, bh2[0]);
                mma_bf16(sa[2 * p + 1], qh, bh2[1]);
                mma_bf16(sa[2 * p + 1], qh, bl2[1]);
                mma_bf16(sa[2 * p + 1], ql, bh2[1]);
            }
        }

        // ---- online softmax (mask from precomputed bytes) ----
        float mx0 = -INFINITY, mx1 = -INFINITY;
#pragma unroll
        for (int nt = 0; nt < 8; nt++) {
            const int col0 = s0 + nt * 8 + 2 * c, col1 = col0 + 1;
            const bool k0m = mkb[col0] != 0, k1m = mkb[col1] != 0;
            float s0v = sa[nt][0]; if (k0m) s0v = -INFINITY;
            float s1v = sa[nt][1]; if (k1m) s1v = -INFINITY;
            float s2v = sa[nt][2]; if (k0m) s2v = -INFINITY;
            float s3v = sa[nt][3]; if (k1m) s3v = -INFINITY;
            sa[nt][0] = s0v; sa[nt][1] = s1v; sa[nt][2] = s2v; sa[nt][3] = s3v;
            mx0 = fmaxf(mx0, fmaxf(s0v, s1v));
            mx1 = fmaxf(mx1, fmaxf(s2v, s3v));
        }
        mx0 = fmaxf(mx0, __shfl_xor_sync(0xffffffffu, mx0, 1));
        mx0 = fmaxf(mx0, __shfl_xor_sync(0xffffffffu, mx0, 2));
        mx1 = fmaxf(mx1, __shfl_xor_sync(0xffffffffu, mx1, 1));
        mx1 = fmaxf(mx1, __shfl_xor_sync(0xffffffffu, mx1, 2));

        const float mn0 = fmaxf(m0, mx0), mn1 = fmaxf(m1, mx1);
        const float al0 = __expf(m0 - mn0), al1 = __expf(m1 - mn1);
        m0 = mn0; m1 = mn1;

        uint32_t phl[8], phh[8], pll[8], plh[8];
        float su0 = 0.f, su1 = 0.f;
#pragma unroll
        for (int nt = 0; nt < 8; nt++) {
            const float p0 = __expf(sa[nt][0] - mn0);
            const float p1 = __expf(sa[nt][1] - mn0);
            const float p2 = __expf(sa[nt][2] - mn1);
            const float p3 = __expf(sa[nt][3] - mn1);
            su0 += p0 + p1; su1 += p2 + p3;
            bsplit(p0, p1, phl[nt], pll[nt]);
            bsplit(p2, p3, phh[nt], plh[nt]);
        }
        su0 += __shfl_xor_sync(0xffffffffu, su0, 1);
        su0 += __shfl_xor_sync(0xffffffffu, su0, 2);
        su1 += __shfl_xor_sync(0xffffffffu, su1, 1);
        su1 += __shfl_xor_sync(0xffffffffu, su1, 2);
        l0s = l0s * al0 + su0;
        l1s = l1s * al1 + su1;
#pragma unroll
        for (int nt = 0; nt < 8; nt++) {
            o[nt][0] *= al0; o[nt][1] *= al0;
            o[nt][2] *= al1; o[nt][3] *= al1;
        }

        // ---- O += P V ----
#pragma unroll
        for (int j = 0; j < 4; j++) {
            uint32_t ah[4], al2[4];
            ah[0] = phl[2 * j];     ah[1] = phh[2 * j];
            ah[2] = phl[2 * j + 1]; ah[3] = phh[2 * j + 1];
            al2[0] = pll[2 * j];     al2[1] = plh[2 * j];
            al2[2] = pll[2 * j + 1]; al2[3] = plh[2 * j + 1];
#pragma unroll
            for (int p = 0; p < 4; p++) {
                uint32_t bh2[2][2], bl2[2][2];
                const uint32_t va = sbF +
                    (uint32_t)(FVH + (krow_l + p * 16) * FP_STR + j * 8 + kcol_l) * 4u;
                ldm4(bh2[0][0], bh2[0][1], bh2[1][0], bh2[1][1], va);
                ldm4(bl2[0][0], bl2[0][1], bl2[1][0], bl2[1][1], va + (FVL - FVH) * 4);
                mma_bf16(o[2 * p], ah, bh2[0]);
                mma_bf16(o[2 * p], ah, bl2[0]);
                mma_bf16(o[2 * p], al2, bh2[0]);
                mma_bf16(o[2 * p + 1], ah, bh2[1]);
                mma_bf16(o[2 * p + 1], ah, bl2[1]);
                mma_bf16(o[2 * p + 1], al2, bh2[1]);
            }
        }
    }

    // writeout: packed ctx
    const float i0 = 1.f / l0s, i1 = 1.f / l1s;
#pragma unroll
    for (int nt = 0; nt < 8; nt++) {
        const int kp = h * 32 + nt * 4 + c;
        uint32_t hi, lo;
        bsplit(o[nt][0] * i0, o[nt][1] * i0, hi, lo);
        ctxh[((size_t)(t0 + wm + g) * B_ + b) * EH + kp] = hi;
        ctxl[((size_t)(t0 + wm + g) * B_ + b) * EH + kp] = lo;
        bsplit(o[nt][2] * i1, o[nt][3] * i1, hi, lo);
        ctxh[((size_t)(t0 + wm + g + 8) * B_ + b) * EH + kp] = hi;
        ctxl[((size_t)(t0 + wm + g + 8) * B_ + b) * EH + kp] = lo;
    }
}

// ---------------------------------------------------------------------------
// Fused add-residual + LayerNorm
// ---------------------------------------------------------------------------
__device__ __forceinline__ float warpReduceSum(float v) {
#pragma unroll
    for (int o = 16; o; o >>= 1) v += __shfl_xor_sync(0xffffffffu, v, o);
    return v;
}

__global__ void __launch_bounds__(256)
add_ln_kernel(const float* __restrict__ a, const float* __restrict__ r,
              const float* __restrict__ g, const float* __restrict__ be,
              float* __restrict__ out)
{
    const int row = blockIdx.x;
    const int tid = threadIdx.x;
    const float* pa = a + (size_t)row * E_;
    const float* pr = r + (size_t)row * E_;

    float v0 = pa[tid] + pr[tid];
    float v1 = pa[tid + 256] + pr[tid + 256];
    float v2 = pa[tid + 512] + pr[tid + 512];

    __shared__ float red[8];
    const int wid = tid >> 5, lane = tid & 31;

    float s = warpReduceSum(v0 + v1 + v2);
    if (lane == 0) red[wid] = s;
    __syncthreads();
    float tot = 0.f;
#pragma unroll
    for (int i = 0; i < 8; i++) tot += red[i];
    const float mean = tot * (1.f / (float)E_);

    float d0 = v0 - mean, d1 = v1 - mean, d2 = v2 - mean;
    float sq = warpReduceSum(d0 * d0 + d1 * d1 + d2 * d2);
    __syncthreads();
    if (lane == 0) red[wid] = sq;
    __syncthreads();
    tot = 0.f;
#pragma unroll
    for (int i = 0; i < 8; i++) tot += red[i];
    const float inv = rsqrtf(tot * (1.f / (float)E_) + 1e-5f);

    float* po = out + (size_t)row * E_;
    po[tid]       = d0 * inv * g[tid]       + be[tid];
    po[tid + 256] = d1 * inv * g[tid + 256] + be[tid + 256];
    po[tid + 512] = d2 * inv * g[tid + 512] + be[tid + 512];
}

__global__ void __launch_bounds__(128)
add_ln_pack_kernel(const float* __restrict__ a, const float* __restrict__ r,
                   const float* __restrict__ g, const float* __restrict__ be,
                   float* __restrict__ outF, uint32_t* __restrict__ outH,
                   uint32_t* __restrict__ outL)
{
    const int row = blockIdx.x;
    const int tid = threadIdx.x;
    const float* pa = a + (size_t)row * E_;
    const float* pr = r + (size_t)row * E_;

    float2 v[3];
#pragma unroll
    for (int i = 0; i < 3; i++) {
        const int o = 2 * (tid + i * 128);
        const float2 x = *(const float2*)&pa[o];
        const float2 y = *(const float2*)&pr[o];
        v[i].x = x.x + y.x;
        v[i].y = x.y + y.y;
    }

    __shared__ float red[4];
    const int wid = tid >> 5, lane = tid & 31;

    float s = warpReduceSum(v[0].x + v[0].y + v[1].x + v[1].y + v[2].x + v[2].y);
    if (lane == 0) red[wid] = s;
    __syncthreads();
    float tot = red[0] + red[1] + red[2] + red[3];
    const float mean = tot * (1.f / (float)E_);

    float sq = 0.f;
#pragma unroll
    for (int i = 0; i < 3; i++) {
        v[i].x -= mean; v[i].y -= mean;
        sq += v[i].x * v[i].x + v[i].y * v[i].y;
    }
    sq = warpReduceSum(sq);
    __syncthreads();
    if (lane == 0) red[wid] = sq;
    __syncthreads();
    tot = red[0] + red[1] + red[2] + red[3];
    const float inv = rsqrtf(tot * (1.f / (float)E_) + 1e-5f);

    float* po = outF + (size_t)row * E_;
    uint32_t* ph = outH + (size_t)row * EH;
    uint32_t* pl = outL + (size_t)row * EH;
#pragma unroll
    for (int i = 0; i < 3; i++) {
        const int p = tid + i * 128;
        const float2 gg = *(const float2*)&g[2 * p];
        const float2 bb = *(const float2*)&be[2 * p];
        float2 w;
        w.x = v[i].x * inv * gg.x + bb.x;
        w.y = v[i].y * inv * gg.y + bb.y;
        *(float2*)&po[2 * p] = w;
        uint32_t hi, lo;
        bsplit(w.x, w.y, hi, lo);
        ph[p] = hi;
        pl[p] = lo;
    }
}

// ---------------------------------------------------------------------------
// Launch
// ---------------------------------------------------------------------------
extern "C" void kernel_launch(void* const* d_in, const int* in_sizes, int n_in,
                              void* d_out, int out_size)
{
    const float* state = (const float*)d_in[0];
    const int* mask = (const int*)d_in[1];
    const float* Wq = (const float*)d_in[2];
    const float* bq = (const float*)d_in[3];
    const float* Wk = (const float*)d_in[4];
    const float* bk = (const float*)d_in[5];
    const float* Wv = (const float*)d_in[6];
    const float* bv = (const float*)d_in[7];
    const float* Wo = (const float*)d_in[8];
    const float* bo = (const float*)d_in[9];
    const float* ln1g = (const float*)d_in[10];
    const float* ln1b = (const float*)d_in[11];
    const float* W1 = (const float*)d_in[12];
    const float* b1 = (const float*)d_in[13];
    const float* W2 = (const float*)d_in[14];
    const float* b2 = (const float*)d_in[15];
    const float* ln2g = (const float*)d_in[16];
    const float* ln2b = (const float*)d_in[17];
    float* out = (float*)d_out;

    uint32_t *sth, *stl, *qh, *ql, *kh, *kl, *ch, *cl, *x1h, *x1l, *h1h, *h1l;
    float *vp, *t0p, *x1p;
    uint32_t *wqh, *wql, *wkh, *wkl, *wvh, *wvl, *woh, *wol, *w1h, *w1l, *w2h, *w2l;
    cudaGetSymbolAddress((void**)&sth, g_sth); cudaGetSymbolAddress((void**)&stl, g_stl);
    cudaGetSymbolAddress((void**)&qh, g_qh);   cudaGetSymbolAddress((void**)&ql, g_ql);
    cudaGetSymbolAddress((void**)&kh, g_kh);   cudaGetSymbolAddress((void**)&kl, g_kl);
    cudaGetSymbolAddress((void**)&vp, g_v);
    cudaGetSymbolAddress((void**)&ch, g_ch);   cudaGetSymbolAddress((void**)&cl, g_cl);
    cudaGetSymbolAddress((void**)&t0p, g_t0);
    cudaGetSymbolAddress((void**)&x1p, g_x1);
    cudaGetSymbolAddress((void**)&x1h, g_x1h); cudaGetSymbolAddress((void**)&x1l, g_x1l);
    cudaGetSymbolAddress((void**)&h1h, g_h1h); cudaGetSymbolAddress((void**)&h1l, g_h1l);
    cudaGetSymbolAddress((void**)&wqh, g_wqTh); cudaGetSymbolAddress((void**)&wql, g_wqTl);
    cudaGetSymbolAddress((void**)&wkh, g_wkTh); cudaGetSymbolAddress((void**)&wkl, g_wkTl);
    cudaGetSymbolAddress((void**)&wvh, g_wvTh); cudaGetSymbolAddress((void**)&wvl, g_wvTl);
    cudaGetSymbolAddress((void**)&woh, g_woTh); cudaGetSymbolAddress((void**)&wol, g_woTl);
    cudaGetSymbolAddress((void**)&w1h, g_w1Th); cudaGetSymbolAddress((void**)&w1l, g_w1Tl);
    cudaGetSymbolAddress((void**)&w2h, g_w2Th); cudaGetSymbolAddress((void**)&w2l, g_w2Tl);

    cudaFuncSetAttribute(gemm_pk_kernel, cudaFuncAttributeMaxDynamicSharedMemorySize, GEMM_SMEM);
    cudaFuncSetAttribute(gemm_qkv_kernel, cudaFuncAttributeMaxDynamicSharedMemorySize, GEMM_SMEM);
    cudaFuncSetAttribute(flash_attn_pk_kernel, cudaFuncAttributeMaxDynamicSharedMemorySize, FA_SMEM);

    // single fused pack launch (state + 6 weights)
    const int pack_blocks = PK_ROWS_BLKS + 4 * PK_E_BLKS + 2 * PK_F_BLKS;   // 13056
    pack_all_kernel<<<pack_blocks, 256>>>(state, Wq, Wk, Wv, Wo, W1, W2,
                                          sth, stl, wqh, wql, wkh, wkl, wvh, wvl,
                                          woh, wol, w1h, w1l, w2h, w2l);

    dim3 gQKV(18, M_ / 128);
    dim3 gE(E_ / 128, M_ / 128);
    dim3 gF(F_ / 128, M_ / 128);

    // fused QKV projection
    gemm_qkv_kernel<<<gQKV, 256, GEMM_SMEM>>>(sth, stl, wqh, wql, wkh, wkl, wvh, wvl,
                                              bq, bk, bv, qh, ql, kh, kl, vp);

    // attention -> packed ctx
    flash_attn_pk_kernel<<<dim3(T_ / 128, B_ * H_), 256, FA_SMEM>>>(qh, ql, kh, kl, vp, mask, ch, cl);

    // output projection + LN1
    gemm_pk_kernel<<<gE, 256, GEMM_SMEM>>>(ch, cl, woh, wol, bo, t0p, nullptr, nullptr, EH, E_, 0, 0, 1.f);
    add_ln_pack_kernel<<<M_, 128>>>(t0p, state, ln1g, ln1b, x1p, x1h, x1l);

    // FFN + LN2
    gemm_pk_kernel<<<gF, 256, GEMM_SMEM>>>(x1h, x1l, w1h, w1l, b1, nullptr, h1h, h1l, EH, F_, 1, 1, 1.f);
    gemm_pk_kernel<<<gE, 256, GEMM_SMEM>>>(h1h, h1l, w2h, w2l, b2, t0p, nullptr, nullptr, FH, E_, 0, 0, 1.f);
    add_ln_kernel<<<M_, 256>>>(t0p, x1p, ln2g, ln2b, out);
}

// round 13
// speedup vs baseline: 3.2344x; 1.0007x over previous
#include <cuda_runtime.h>
#include <cuda_bf16.h>
#include <math.h>
#include <stdint.h>

// Problem constants
#define T_ 2048
#define B_ 2
#define E_ 768
#define H_ 12
#define D_ 64
#define F_ 3072
#define M_ (T_ * B_)   // 4096 rows
#define EH (E_ / 2)
#define FH (F_ / 2)

// ---------------------------------------------------------------------------
// Scratch (device globals — no cudaMalloc allowed)
// ---------------------------------------------------------------------------
__device__ uint32_t g_sth[M_ * EH], g_stl[M_ * EH];   // packed state
__device__ uint32_t g_qh[M_ * EH],  g_ql[M_ * EH];    // packed Q (pre-scaled 1/8)
__device__ uint32_t g_kh[M_ * EH],  g_kl[M_ * EH];    // packed K
__device__ float    g_v[M_ * E_];                     // V fp32
__device__ uint32_t g_ch[M_ * EH],  g_cl[M_ * EH];    // packed ctx
__device__ float    g_t0[M_ * E_];                    // attn_out / ffn_out fp32
__device__ float    g_x1[M_ * E_];                    // LN1 out fp32 (residual)
__device__ uint32_t g_x1h[M_ * EH], g_x1l[M_ * EH];   // LN1 out packed
__device__ uint32_t g_h1h[M_ * FH], g_h1l[M_ * FH];   // FFN hidden packed
// pre-split transposed weights: [N][K/2]
__device__ uint32_t g_wqTh[E_ * EH], g_wqTl[E_ * EH];
__device__ uint32_t g_wkTh[E_ * EH], g_wkTl[E_ * EH];
__device__ uint32_t g_wvTh[E_ * EH], g_wvTl[E_ * EH];
__device__ uint32_t g_woTh[E_ * EH], g_woTl[E_ * EH];
__device__ uint32_t g_w1Th[F_ * EH], g_w1Tl[F_ * EH];
__device__ uint32_t g_w2Th[E_ * FH], g_w2Tl[E_ * FH];

// ---------------------------------------------------------------------------
// Helpers (baseline PTX only — compute_103 virtual arch)
// ---------------------------------------------------------------------------
__device__ __forceinline__ uint32_t smem_u32(const void* p) {
    uint32_t a;
    asm("{ .reg .u64 t; cvta.to.shared.u64 t, %1; cvt.u32.u64 %0, t; }" : "=r"(a) : "l"(p));
    return a;
}
__device__ __forceinline__ void cp16(uint32_t dst, const void* src) {
    asm volatile("cp.async.cg.shared.global [%0], [%1], 16;" :: "r"(dst), "l"(src));
}
#define CP_COMMIT() asm volatile("cp.async.commit_group;" ::: "memory")
#define CP_WAIT(n)  asm volatile("cp.async.wait_group %0;" :: "n"(n) : "memory")

__device__ __forceinline__ void bsplit(float x, float y, uint32_t& hi, uint32_t& lo) {
    __nv_bfloat162 h = __floats2bfloat162_rn(x, y);
    const float hx = __low2float(h), hy = __high2float(h);
    __nv_bfloat162 l = __floats2bfloat162_rn(x - hx, y - hy);
    hi = *reinterpret_cast<uint32_t*>(&h);
    lo = *reinterpret_cast<uint32_t*>(&l);
}

__device__ __forceinline__ void mma_bf16(float* d, const uint32_t* a, const uint32_t* b) {
    asm volatile("mma.sync.aligned.m16n8k16.row.col.f32.bf16.bf16.f32 "
                 "{%0,%1,%2,%3}, {%4,%5,%6,%7}, {%8,%9}, {%0,%1,%2,%3};"
                 : "+f"(d[0]), "+f"(d[1]), "+f"(d[2]), "+f"(d[3])
                 : "r"(a[0]), "r"(a[1]), "r"(a[2]), "r"(a[3]), "r"(b[0]), "r"(b[1]));
}

__device__ __forceinline__ void ldm4(uint32_t& r0, uint32_t& r1, uint32_t& r2,
                                     uint32_t& r3, uint32_t a) {
    asm volatile("ldmatrix.sync.aligned.m8n8.x4.shared.b16 {%0,%1,%2,%3}, [%4];"
                 : "=r"(r0), "=r"(r1), "=r"(r2), "=r"(r3) : "r"(a));
}

// ---------------------------------------------------------------------------
// Fused pack kernel: pack_rows (region 0) + 6x transpose-pack (regions 1..6).
// Single launch to avoid per-launch latency of 7 tiny kernels.
// ---------------------------------------------------------------------------
#define PK_ROWS_BLKS (M_ * EH / 256)      // 6144
#define PK_E_BLKS 576                      // 24x24 per ExE weight
#define PK_F_BLKS 2304                     // 96x24 / 24x96

__global__ void __launch_bounds__(256)
pack_all_kernel(const float* __restrict__ state,
                const float* __restrict__ Wq, const float* __restrict__ Wk,
                const float* __restrict__ Wv, const float* __restrict__ Wo,
                const float* __restrict__ W1, const float* __restrict__ W2,
                uint32_t* __restrict__ sth, uint32_t* __restrict__ stl,
                uint32_t* __restrict__ wqh, uint32_t* __restrict__ wql,
                uint32_t* __restrict__ wkh, uint32_t* __restrict__ wkl,
                uint32_t* __restrict__ wvh, uint32_t* __restrict__ wvl,
                uint32_t* __restrict__ woh, uint32_t* __restrict__ wol,
                uint32_t* __restrict__ w1h, uint32_t* __restrict__ w1l,
                uint32_t* __restrict__ w2h, uint32_t* __restrict__ w2l)
{
    __shared__ float t[32][33];
    const int tid = threadIdx.x;
    int bid = blockIdx.x;

    if (bid < PK_ROWS_BLKS) {
        const int i = bid * 256 + tid;
        const float2 v = *(const float2*)&state[2 * i];
        uint32_t hi, lo;
        bsplit(v.x, v.y, hi, lo);
        sth[i] = hi;
        stl[i] = lo;
        return;
    }
    bid -= PK_ROWS_BLKS;

    const float* in;
    uint32_t *oh, *ol;
    int R, gx, C, idx;
    if (bid < PK_E_BLKS)          { in = Wq; oh = wqh; ol = wql; R = E_; C = E_; gx = 24; idx = bid; }
    else if (bid < 2 * PK_E_BLKS) { in = Wk; oh = wkh; ol = wkl; R = E_; C = E_; gx = 24; idx = bid - PK_E_BLKS; }
    else if (bid < 3 * PK_E_BLKS) { in = Wv; oh = wvh; ol = wvl; R = E_; C = E_; gx = 24; idx = bid - 2 * PK_E_BLKS; }
    else if (bid < 4 * PK_E_BLKS) { in = Wo; oh = woh; ol = wol; R = E_; C = E_; gx = 24; idx = bid - 3 * PK_E_BLKS; }
    else if (bid < 4 * PK_E_BLKS + PK_F_BLKS)
                                  { in = W1; oh = w1h; ol = w1l; R = E_; C = F_; gx = 96; idx = bid - 4 * PK_E_BLKS; }
    else                          { in = W2; oh = w2h; ol = w2l; R = F_; C = E_; gx = 24; idx = bid - 4 * PK_E_BLKS - PK_F_BLKS; }

    const int bx = (idx % gx) * 32;   // n offset
    const int by = (idx / gx) * 32;   // k offset
    const int x = tid & 31, y = tid >> 5;
#pragma unroll
    for (int j = 0; j < 32; j += 8)
        t[y + j][x] = in[(size_t)(by + y + j) * C + bx + x];
    __syncthreads();
    const int KH2 = R >> 1;
#pragma unroll
    for (int i = 0; i < 2; i++) {
        const int n = (tid >> 4) + i * 16;
        const int kp = tid & 15;
        uint32_t hi, lo;
        bsplit(t[2 * kp][n], t[2 * kp + 1][n], hi, lo);
        oh[(size_t)(bx + n) * KH2 + (by >> 1) + kp] = hi;
        ol[(size_t)(bx + n) * KH2 + (by >> 1) + kp] = lo;
    }
}

// ---------------------------------------------------------------------------
// Shared GEMM mainloop core, ONE barrier per K-iter.
// ---------------------------------------------------------------------------
#define GP_STR 20
#define GP_TILE (128 * GP_STR)          // 2560 u32
#define GP_STAGE (4 * GP_TILE)          // Ah,Al,Bh,Bl
#define GEMM_SMEM (2 * GP_STAGE * 4)    // 81920 bytes

__device__ __forceinline__ void gemm_core(
    const uint32_t* __restrict__ Ah, const uint32_t* __restrict__ Al,
    const uint32_t* __restrict__ Bh, const uint32_t* __restrict__ Bl,
    int KH, int by, int bx, uint32_t sb, int tid, float acc[4][4][4])
{
    const int wid = tid >> 5, lane = tid & 31;
    const int warp_m = (wid >> 2) * 64;
    const int warp_n = (wid & 3) * 32;

    const int arow_l = warp_m + (lane & 15);
    const int acol_l = (lane >> 4) << 2;
    const int brow_l = warp_n + (lane & 7) + ((lane >> 4) << 3);
    const int bcol_l = ((lane >> 3) & 1) << 2;

    const int NT = KH / 16;

    auto load_stage = [&](int buf, int kt) {
        const uint32_t base = sb + (uint32_t)(buf * GP_STAGE) * 4u;
#pragma unroll
        for (int i = 0; i < 2; i++) {
            const int id = tid + i * 256;
            const int row = id >> 2, c4 = id & 3;
            const uint32_t so = (uint32_t)(row * GP_STR + c4 * 4) * 4u;
            const size_t ga = (size_t)(by + row) * KH + kt * 16 + c4 * 4;
            const size_t gb = (size_t)(bx + row) * KH + kt * 16 + c4 * 4;
            cp16(base + so, &Ah[ga]);
            cp16(base + (uint32_t)(GP_TILE * 4) + so, &Al[ga]);
            cp16(base + (uint32_t)(2 * GP_TILE * 4) + so, &Bh[gb]);
            cp16(base + (uint32_t)(3 * GP_TILE * 4) + so, &Bl[gb]);
        }
        CP_COMMIT();
    };

    load_stage(0, 0);

    for (int kt = 0; kt < NT; kt++) {
        CP_WAIT(0);
        __syncthreads();   // buf[kt&1] visible; all threads done computing buf[kt&1] last round
        if (kt + 1 < NT) load_stage((kt + 1) & 1, kt + 1);   // fills other buffer, overlaps compute

        const uint32_t stg = sb + (uint32_t)((kt & 1) * GP_STAGE) * 4u;

#pragma unroll
        for (int j = 0; j < 2; j++) {
            uint32_t ah[4][4], al[4][4];
#pragma unroll
            for (int mt = 0; mt < 4; mt++) {
                const uint32_t aa = stg +
                    (uint32_t)((arow_l + mt * 16) * GP_STR + j * 8 + acol_l) * 4u;
                ldm4(ah[mt][0], ah[mt][1], ah[mt][2], ah[mt][3], aa);
                ldm4(al[mt][0], al[mt][1], al[mt][2], al[mt][3], aa + GP_TILE * 4);
            }
            uint32_t bh2[4][2], bl2[4][2];
#pragma unroll
            for (int p = 0; p < 2; p++) {
                const uint32_t ba = stg + (uint32_t)(2 * GP_TILE) * 4u +
                    (uint32_t)((brow_l + p * 16) * GP_STR + j * 8 + bcol_l) * 4u;
                ldm4(bh2[2 * p][0], bh2[2 * p][1], bh2[2 * p + 1][0], bh2[2 * p + 1][1], ba);
                ldm4(bl2[2 * p][0], bl2[2 * p][1], bl2[2 * p + 1][0], bl2[2 * p + 1][1],
                     ba + GP_TILE * 4);
            }
#pragma unroll
            for (int nt = 0; nt < 4; nt++)
#pragma unroll
                for (int mt = 0; mt < 4; mt++) {
                    mma_bf16(acc[mt][nt], ah[mt], bh2[nt]);
                    mma_bf16(acc[mt][nt], ah[mt], bl2[nt]);
                    mma_bf16(acc[mt][nt], al[mt], bh2[nt]);
                }
        }
    }
}

// generic GEMM: fp32 or packed output
__global__ void __launch_bounds__(256, 2)
gemm_pk_kernel(const uint32_t* __restrict__ Ah, const uint32_t* __restrict__ Al,
               const uint32_t* __restrict__ Bh, const uint32_t* __restrict__ Bl,
               const float* __restrict__ bias,
               float* __restrict__ outF, uint32_t* __restrict__ outH,
               uint32_t* __restrict__ outL,
               int KH, int Ndim, int packout, int relu, float scale)
{
    extern __shared__ uint32_t smu[];
    const uint32_t sb = smem_u32(smu);
    const int tid = threadIdx.x;
    const int wid = tid >> 5, lane = tid & 31;
    const int by = blockIdx.y * 128, bx = blockIdx.x * 128;
    const int warp_m = (wid >> 2) * 64, warp_n = (wid & 3) * 32;
    const int g = lane >> 2, c = lane & 3;

    float acc[4][4][4];
#pragma unroll
    for (int mt = 0; mt < 4; mt++)
#pragma unroll
        for (int nt = 0; nt < 4; nt++)
#pragma unroll
            for (int i = 0; i < 4; i++) acc[mt][nt][i] = 0.f;

    gemm_core(Ah, Al, Bh, Bl, KH, by, bx, sb, tid, acc);

    const int NH = Ndim >> 1;
#pragma unroll
    for (int mt = 0; mt < 4; mt++) {
        const int r0 = by + warp_m + mt * 16 + g;
#pragma unroll
        for (int nt = 0; nt < 4; nt++) {
            const int c0 = bx + warp_n + nt * 8 + 2 * c;
            const float b0 = bias[c0], b1 = bias[c0 + 1];
            float v00 = (acc[mt][nt][0] + b0) * scale;
            float v01 = (acc[mt][nt][1] + b1) * scale;
            float v10 = (acc[mt][nt][2] + b0) * scale;
            float v11 = (acc[mt][nt][3] + b1) * scale;
            if (relu) {
                v00 = fmaxf(v00, 0.f); v01 = fmaxf(v01, 0.f);
                v10 = fmaxf(v10, 0.f); v11 = fmaxf(v11, 0.f);
            }
            if (packout) {
                uint32_t hi, lo;
                bsplit(v00, v01, hi, lo);
                outH[(size_t)r0 * NH + (c0 >> 1)] = hi;
                outL[(size_t)r0 * NH + (c0 >> 1)] = lo;
                bsplit(v10, v11, hi, lo);
                outH[(size_t)(r0 + 8) * NH + (c0 >> 1)] = hi;
                outL[(size_t)(r0 + 8) * NH + (c0 >> 1)] = lo;
            } else {
                float2 w0, w1;
                w0.x = v00; w0.y = v01; w1.x = v10; w1.y = v11;
                *(float2*)&outF[(size_t)r0 * Ndim + c0] = w0;
                *(float2*)&outF[(size_t)(r0 + 8) * Ndim + c0] = w1;
            }
        }
    }
}

// fused QKV GEMM: blockIdx.x region-dispatch (0..5 Q, 6..11 K, 12..17 V)
__global__ void __launch_bounds__(256, 2)
gemm_qkv_kernel(const uint32_t* __restrict__ Ah, const uint32_t* __restrict__ Al,
                const uint32_t* __restrict__ wqh, const uint32_t* __restrict__ wql,
                const uint32_t* __restrict__ wkh, const uint32_t* __restrict__ wkl,
                const uint32_t* __restrict__ wvh, const uint32_t* __restrict__ wvl,
                const float* __restrict__ bq, const float* __restrict__ bk,
                const float* __restrict__ bv,
                uint32_t* __restrict__ qh, uint32_t* __restrict__ ql,
                uint32_t* __restrict__ kh, uint32_t* __restrict__ kl,
                float* __restrict__ vout)
{
    extern __shared__ uint32_t smu[];
    const uint32_t sb = smem_u32(smu);
    const int region = blockIdx.x / 6;
    const int bx = (blockIdx.x % 6) * 128;
    const int by = blockIdx.y * 128;
    const uint32_t* Bh = (region == 0) ? wqh : (region == 1) ? wkh : wvh;
    const uint32_t* Bl = (region == 0) ? wql : (region == 1) ? wkl : wvl;
    const float* bias = (region == 0) ? bq : (region == 1) ? bk : bv;
    const float scale = (region == 0) ? 0.125f : 1.f;

    const int tid = threadIdx.x;
    const int wid = tid >> 5, lane = tid & 31;
    const int warp_m = (wid >> 2) * 64, warp_n = (wid & 3) * 32;
    const int g = lane >> 2, c = lane & 3;

    float acc[4][4][4];
#pragma unroll
    for (int mt = 0; mt < 4; mt++)
#pragma unroll
        for (int nt = 0; nt < 4; nt++)
#pragma unroll
            for (int i = 0; i < 4; i++) acc[mt][nt][i] = 0.f;

    gemm_core(Ah, Al, Bh, Bl, EH, by, bx, sb, tid, acc);

    uint32_t* outH = (region == 0) ? qh : kh;
    uint32_t* outL = (region == 0) ? ql : kl;
#pragma unroll
    for (int mt = 0; mt < 4; mt++) {
        const int r0 = by + warp_m + mt * 16 + g;
#pragma unroll
        for (int nt = 0; nt < 4; nt++) {
            const int c0 = bx + warp_n + nt * 8 + 2 * c;
            const float b0 = bias[c0], b1 = bias[c0 + 1];
            const float v00 = (acc[mt][nt][0] + b0) * scale;
            const float v01 = (acc[mt][nt][1] + b1) * scale;
            const float v10 = (acc[mt][nt][2] + b0) * scale;
            const float v11 = (acc[mt][nt][3] + b1) * scale;
            if (region < 2) {
                uint32_t hi, lo;
                bsplit(v00, v01, hi, lo);
                outH[(size_t)r0 * EH + (c0 >> 1)] = hi;
                outL[(size_t)r0 * EH + (c0 >> 1)] = lo;
                bsplit(v10, v11, hi, lo);
                outH[(size_t)(r0 + 8) * EH + (c0 >> 1)] = hi;
                outL[(size_t)(r0 + 8) * EH + (c0 >> 1)] = lo;
            } else {
                float2 w0, w1;
                w0.x = v00; w0.y = v01; w1.x = v10; w1.y = v11;
                *(float2*)&vout[(size_t)r0 * E_ + c0] = w0;
                *(float2*)&vout[(size_t)(r0 + 8) * E_ + c0] = w1;
            }
        }
    }
}

// ---------------------------------------------------------------------------
// Tensor-core flash attention. Mask precomputed once (bytes + per-tile skip
// flags in smem); 2 barriers per live key tile, 1 per skipped tile.
// ---------------------------------------------------------------------------
#define FP_STR 36
#define FQH 0
#define FQL (FQH + 128 * FP_STR)
#define FKH (FQL + 128 * FP_STR)
#define FKL (FKH + 64 * FP_STR)
#define FVH (FKL + 64 * FP_STR)
#define FVL (FVH + 64 * FP_STR)
#define FMKB (FVL + 64 * FP_STR)          // 2048 mask bytes = 512 words
#define FSKIP (FMKB + 512)                // 32 skip flags
#define FA_SMEM ((FSKIP + 32) * 4)

__global__ void __launch_bounds__(256, 2)
flash_attn_pk_kernel(const uint32_t* __restrict__ Qh, const uint32_t* __restrict__ Ql,
                     const uint32_t* __restrict__ Kh, const uint32_t* __restrict__ Kl,
                     const float* __restrict__ V, const int* __restrict__ mask,
                     uint32_t* __restrict__ ctxh, uint32_t* __restrict__ ctxl)
{
    extern __shared__ uint32_t us[];
    const uint32_t sbF = smem_u32(us);
    char* mkb = (char*)(us + FMKB);
    int* skip = (int*)(us + FSKIP);

    const int t0 = blockIdx.x * 128;
    const int b = blockIdx.y / H_;
    const int h = blockIdx.y % H_;
    const int tid = threadIdx.x;
    const int w = tid >> 5, lane = tid & 31;
    const int g = lane >> 2, c = lane & 3;
    const int wm = w * 16;

    const int qrow_l = wm + (lane & 15);
    const int qcol_l = (lane >> 4) << 2;
    const int krow_l = (lane & 7) + ((lane >> 4) << 3);
    const int kcol_l = ((lane >> 3) & 1) << 2;

    // ---- one-time: Q tile + mask bytes + per-tile skip flags ----
#pragma unroll
    for (int i = 0; i < 4; i++) {
        const int id = tid + i * 256;
        const int r = id >> 3, c4 = (id & 7) * 4;
        const size_t go = ((size_t)(t0 + r) * B_ + b) * EH + h * 32 + c4;
        *(uint4*)&us[FQH + r * FP_STR + c4] = *(const uint4*)&Qh[go];
        *(uint4*)&us[FQL + r * FP_STR + c4] = *(const uint4*)&Ql[go];
    }
#pragma unroll
    for (int i = 0; i < 8; i++)
        mkb[tid + i * 256] = (char)(mask[(size_t)b * T_ + tid + i * 256] != 0);
    __syncthreads();
    if (tid < 32) {
        int all = 1;
#pragma unroll
        for (int j = 0; j < 64; j++) all &= (int)mkb[tid * 64 + j];
        skip[tid] = all;
    }
    __syncthreads();

    float o[8][4];
#pragma unroll
    for (int nt = 0; nt < 8; nt++)
#pragma unroll
        for (int i = 0; i < 4; i++) o[nt][i] = 0.f;
    float m0 = -INFINITY, m1 = -INFINITY, l0s = 0.f, l1s = 0.f;

    for (int s0 = 0; s0 < T_; s0 += 64) {
        __syncthreads();   // K/V buffer reuse barrier
        if (skip[s0 >> 6]) continue;   // uniform smem read, whole block skips

        // packed K tile [64 x 32 kp] hi+lo
#pragma unroll
        for (int i = 0; i < 2; i++) {
            const int id = tid + i * 256;
            const int r = id >> 3, c4 = (id & 7) * 4;
            const size_t go = ((size_t)(s0 + r) * B_ + b) * EH + h * 32 + c4;
            *(uint4*)&us[FKH + r * FP_STR + c4] = *(const uint4*)&Kh[go];
            *(uint4*)&us[FKL + r * FP_STR + c4] = *(const uint4*)&Kl[go];
        }
        // V tile transposed + split: Vt[d][key-pair]
#pragma unroll
        for (int i = 0; i < 2; i++) {
            const int id = tid + i * 256;
            const int kp = id & 31, dblk = id >> 5;
            const float4 va = *(const float4*)&V[((size_t)(s0 + 2 * kp) * B_ + b) * E_ + h * 64 + dblk * 4];
            const float4 vb = *(const float4*)&V[((size_t)(s0 + 2 * kp + 1) * B_ + b) * E_ + h * 64 + dblk * 4];
            uint32_t hi, lo;
            bsplit(va.x, vb.x, hi, lo);
            us[FVH + (dblk * 4 + 0) * FP_STR + kp] = hi; us[FVL + (dblk * 4 + 0) * FP_STR + kp] = lo;
            bsplit(va.y, vb.y, hi, lo);
            us[FVH + (dblk * 4 + 1) * FP_STR + kp] = hi; us[FVL + (dblk * 4 + 1) * FP_STR + kp] = lo;
            bsplit(va.z, vb.z, hi, lo);
            us[FVH + (dblk * 4 + 2) * FP_STR + kp] = hi; us[FVL + (dblk * 4 + 2) * FP_STR + kp] = lo;
            bsplit(va.w, vb.w, hi, lo);
            us[FVH + (dblk * 4 + 3) * FP_STR + kp] = hi; us[FVL + (dblk * 4 + 3) * FP_STR + kp] = lo;
        }
        __syncthreads();

        // ---- S = (Q/8) K^T ----
        float sa[8][4];
#pragma unroll
        for (int nt = 0; nt < 8; nt++)
#pragma unroll
            for (int i = 0; i < 4; i++) sa[nt][i] = 0.f;

#pragma unroll
        for (int j = 0; j < 4; j++) {
            uint32_t qh[4], ql[4];
            const uint32_t qa = sbF + (uint32_t)(FQH + qrow_l * FP_STR + j * 8 + qcol_l) * 4u;
            ldm4(qh[0], qh[1], qh[2], qh[3], qa);
            ldm4(ql[0], ql[1], ql[2], ql[3], qa + (FQL - FQH) * 4);
#pragma unroll
            for (int p = 0; p < 4; p++) {
                uint32_t bh2[2][2], bl2[2][2];
                const uint32_t ka = sbF +
                    (uint32_t)(FKH + (krow_l + p * 16) * FP_STR + j * 8 + kcol_l) * 4u;
                ldm4(bh2[0][0], bh2[0][1], bh2[1][0], bh2[1][1], ka);
                ldm4(bl2[0][0], bl2[0][1], bl2[1][0], bl2[1][1], ka + (FKL - FKH) * 4);
                mma_bf16(sa[2 * p], qh, bh2[0]);
                mma_bf16(sa[2 * p], qh, bl2[0]);
                mma_bf16(sa[2 * p], ql, bh2[0]);
                mma_bf16(sa[2 * p + 1], qh, bh2[1]);
                mma_bf16(sa[2 * p + 1], qh, bl2[1]);
                mma_bf16(sa[2 * p + 1], ql, bh2[1]);
            }
        }

        // ---- online softmax (mask from precomputed bytes) ----
        float mx0 = -INFINITY, mx1 = -INFINITY;
#pragma unroll
        for (int nt = 0; nt < 8; nt++) {
            const int col0 = s0 + nt * 8 + 2 * c, col1 = col0 + 1;
            const bool k0m = mkb[col0] != 0, k1m = mkb[col1] != 0;
            float s0v = sa[nt][0]; if (k0m) s0v = -INFINITY;
            float s1v = sa[nt][1]; if (k1m) s1v = -INFINITY;
            float s2v = sa[nt][2]; if (k0m) s2v = -INFINITY;
            float s3v = sa[nt][3]; if (k1m) s3v = -INFINITY;
            sa[nt][0] = s0v; sa[nt][1] = s1v; sa[nt][2] = s2v; sa[nt][3] = s3v;
            mx0 = fmaxf(mx0, fmaxf(s0v, s1v));
            mx1 = fmaxf(mx1, fmaxf(s2v, s3v));
        }
        mx0 = fmaxf(mx0, __shfl_xor_sync(0xffffffffu, mx0, 1));
        mx0 = fmaxf(mx0, __shfl_xor_sync(0xffffffffu, mx0, 2));
        mx1 = fmaxf(mx1, __shfl_xor_sync(0xffffffffu, mx1, 1));
        mx1 = fmaxf(mx1, __shfl_xor_sync(0xffffffffu, mx1, 2));

        const float mn0 = fmaxf(m0, mx0), mn1 = fmaxf(m1, mx1);
        const float al0 = __expf(m0 - mn0), al1 = __expf(m1 - mn1);
        m0 = mn0; m1 = mn1;

        uint32_t phl[8], phh[8], pll[8], plh[8];
        float su0 = 0.f, su1 = 0.f;
#pragma unroll
        for (int nt = 0; nt < 8; nt++) {
            const float p0 = __expf(sa[nt][0] - mn0);
            const float p1 = __expf(sa[nt][1] - mn0);
            const float p2 = __expf(sa[nt][2] - mn1);
            const float p3 = __expf(sa[nt][3] - mn1);
            su0 += p0 + p1; su1 += p2 + p3;
            bsplit(p0, p1, phl[nt], pll[nt]);
            bsplit(p2, p3, phh[nt], plh[nt]);
        }
        su0 += __shfl_xor_sync(0xffffffffu, su0, 1);
        su0 += __shfl_xor_sync(0xffffffffu, su0, 2);
        su1 += __shfl_xor_sync(0xffffffffu, su1, 1);
        su1 += __shfl_xor_sync(0xffffffffu, su1, 2);
        l0s = l0s * al0 + su0;
        l1s = l1s * al1 + su1;
#pragma unroll
        for (int nt = 0; nt < 8; nt++) {
            o[nt][0] *= al0; o[nt][1] *= al0;
            o[nt][2] *= al1; o[nt][3] *= al1;
        }

        // ---- O += P V ----
#pragma unroll
        for (int j = 0; j < 4; j++) {
            uint32_t ah[4], al2[4];
            ah[0] = phl[2 * j];     ah[1] = phh[2 * j];
            ah[2] = phl[2 * j + 1]; ah[3] = phh[2 * j + 1];
            al2[0] = pll[2 * j];     al2[1] = plh[2 * j];
            al2[2] = pll[2 * j + 1]; al2[3] = plh[2 * j + 1];
#pragma unroll
            for (int p = 0; p < 4; p++) {
                uint32_t bh2[2][2], bl2[2][2];
                const uint32_t va = sbF +
                    (uint32_t)(FVH + (krow_l + p * 16) * FP_STR + j * 8 + kcol_l) * 4u;
                ldm4(bh2[0][0], bh2[0][1], bh2[1][0], bh2[1][1], va);
                ldm4(bl2[0][0], bl2[0][1], bl2[1][0], bl2[1][1], va + (FVL - FVH) * 4);
                mma_bf16(o[2 * p], ah, bh2[0]);
                mma_bf16(o[2 * p], ah, bl2[0]);
                mma_bf16(o[2 * p], al2, bh2[0]);
                mma_bf16(o[2 * p + 1], ah, bh2[1]);
                mma_bf16(o[2 * p + 1], ah, bl2[1]);
                mma_bf16(o[2 * p + 1], al2, bh2[1]);
            }
        }
    }

    // writeout: packed ctx
    const float i0 = 1.f / l0s, i1 = 1.f / l1s;
#pragma unroll
    for (int nt = 0; nt < 8; nt++) {
        const int kp = h * 32 + nt * 4 + c;
        uint32_t hi, lo;
        bsplit(o[nt][0] * i0, o[nt][1] * i0, hi, lo);
        ctxh[((size_t)(t0 + wm + g) * B_ + b) * EH + kp] = hi;
        ctxl[((size_t)(t0 + wm + g) * B_ + b) * EH + kp] = lo;
        bsplit(o[nt][2] * i1, o[nt][3] * i1, hi, lo);
        ctxh[((size_t)(t0 + wm + g + 8) * B_ + b) * EH + kp] = hi;
        ctxl[((size_t)(t0 + wm + g + 8) * B_ + b) * EH + kp] = lo;
    }
}

// ---------------------------------------------------------------------------
// Fused add-residual + LayerNorm
// ---------------------------------------------------------------------------
__device__ __forceinline__ float warpReduceSum(float v) {
#pragma unroll
    for (int o = 16; o; o >>= 1) v += __shfl_xor_sync(0xffffffffu, v, o);
    return v;
}

__global__ void __launch_bounds__(256)
add_ln_kernel(const float* __restrict__ a, const float* __restrict__ r,
              const float* __restrict__ g, const float* __restrict__ be,
              float* __restrict__ out)
{
    const int row = blockIdx.x;
    const int tid = threadIdx.x;
    const float* pa = a + (size_t)row * E_;
    const float* pr = r + (size_t)row * E_;

    float v0 = pa[tid] + pr[tid];
    float v1 = pa[tid + 256] + pr[tid + 256];
    float v2 = pa[tid + 512] + pr[tid + 512];

    __shared__ float red[8];
    const int wid = tid >> 5, lane = tid & 31;

    float s = warpReduceSum(v0 + v1 + v2);
    if (lane == 0) red[wid] = s;
    __syncthreads();
    float tot = 0.f;
#pragma unroll
    for (int i = 0; i < 8; i++) tot += red[i];
    const float mean = tot * (1.f / (float)E_);

    float d0 = v0 - mean, d1 = v1 - mean, d2 = v2 - mean;
    float sq = warpReduceSum(d0 * d0 + d1 * d1 + d2 * d2);
    __syncthreads();
    if (lane == 0) red[wid] = sq;
    __syncthreads();
    tot = 0.f;
#pragma unroll
    for (int i = 0; i < 8; i++) tot += red[i];
    const float inv = rsqrtf(tot * (1.f / (float)E_) + 1e-5f);

    float* po = out + (size_t)row * E_;
    po[tid]       = d0 * inv * g[tid]       + be[tid];
    po[tid + 256] = d1 * inv * g[tid + 256] + be[tid + 256];
    po[tid + 512] = d2 * inv * g[tid + 512] + be[tid + 512];
}

__global__ void __launch_bounds__(128)
add_ln_pack_kernel(const float* __restrict__ a, const float* __restrict__ r,
                   const float* __restrict__ g, const float* __restrict__ be,
                   float* __restrict__ outF, uint32_t* __restrict__ outH,
                   uint32_t* __restrict__ outL)
{
    const int row = blockIdx.x;
    const int tid = threadIdx.x;
    const float* pa = a + (size_t)row * E_;
    const float* pr = r + (size_t)row * E_;

    float2 v[3];
#pragma unroll
    for (int i = 0; i < 3; i++) {
        const int o = 2 * (tid + i * 128);
        const float2 x = *(const float2*)&pa[o];
        const float2 y = *(const float2*)&pr[o];
        v[i].x = x.x + y.x;
        v[i].y = x.y + y.y;
    }

    __shared__ float red[4];
    const int wid = tid >> 5, lane = tid & 31;

    float s = warpReduceSum(v[0].x + v[0].y + v[1].x + v[1].y + v[2].x + v[2].y);
    if (lane == 0) red[wid] = s;
    __syncthreads();
    float tot = red[0] + red[1] + red[2] + red[3];
    const float mean = tot * (1.f / (float)E_);

    float sq = 0.f;
#pragma unroll
    for (int i = 0; i < 3; i++) {
        v[i].x -= mean; v[i].y -= mean;
        sq += v[i].x * v[i].x + v[i].y * v[i].y;
    }
    sq = warpReduceSum(sq);
    __syncthreads();
    if (lane == 0) red[wid] = sq;
    __syncthreads();
    tot = red[0] + red[1] + red[2] + red[3];
    const float inv = rsqrtf(tot * (1.f / (float)E_) + 1e-5f);

    float* po = outF + (size_t)row * E_;
    uint32_t* ph = outH + (size_t)row * EH;
    uint32_t* pl = outL + (size_t)row * EH;
#pragma unroll
    for (int i = 0; i < 3; i++) {
        const int p = tid + i * 128;
        const float2 gg = *(const float2*)&g[2 * p];
        const float2 bb = *(const float2*)&be[2 * p];
        float2 w;
        w.x = v[i].x * inv * gg.x + bb.x;
        w.y = v[i].y * inv * gg.y + bb.y;
        *(float2*)&po[2 * p] = w;
        uint32_t hi, lo;
        bsplit(w.x, w.y, hi, lo);
        ph[p] = hi;
        pl[p] = lo;
    }
}

// ---------------------------------------------------------------------------
// Launch
// ---------------------------------------------------------------------------
extern "C" void kernel_launch(void* const* d_in, const int* in_sizes, int n_in,
                              void* d_out, int out_size)
{
    const float* state = (const float*)d_in[0];
    const int* mask = (const int*)d_in[1];
    const float* Wq = (const float*)d_in[2];
    const float* bq = (const float*)d_in[3];
    const float* Wk = (const float*)d_in[4];
    const float* bk = (const float*)d_in[5];
    const float* Wv = (const float*)d_in[6];
    const float* bv = (const float*)d_in[7];
    const float* Wo = (const float*)d_in[8];
    const float* bo = (const float*)d_in[9];
    const float* ln1g = (const float*)d_in[10];
    const float* ln1b = (const float*)d_in[11];
    const float* W1 = (const float*)d_in[12];
    const float* b1 = (const float*)d_in[13];
    const float* W2 = (const float*)d_in[14];
    const float* b2 = (const float*)d_in[15];
    const float* ln2g = (const float*)d_in[16];
    const float* ln2b = (const float*)d_in[17];
    float* out = (float*)d_out;

    uint32_t *sth, *stl, *qh, *ql, *kh, *kl, *ch, *cl, *x1h, *x1l, *h1h, *h1l;
    float *vp, *t0p, *x1p;
    uint32_t *wqh, *wql, *wkh, *wkl, *wvh, *wvl, *woh, *wol, *w1h, *w1l, *w2h, *w2l;
    cudaGetSymbolAddress((void**)&sth, g_sth); cudaGetSymbolAddress((void**)&stl, g_stl);
    cudaGetSymbolAddress((void**)&qh, g_qh);   cudaGetSymbolAddress((void**)&ql, g_ql);
    cudaGetSymbolAddress((void**)&kh, g_kh);   cudaGetSymbolAddress((void**)&kl, g_kl);
    cudaGetSymbolAddress((void**)&vp, g_v);
    cudaGetSymbolAddress((void**)&ch, g_ch);   cudaGetSymbolAddress((void**)&cl, g_cl);
    cudaGetSymbolAddress((void**)&t0p, g_t0);
    cudaGetSymbolAddress((void**)&x1p, g_x1);
    cudaGetSymbolAddress((void**)&x1h, g_x1h); cudaGetSymbolAddress((void**)&x1l, g_x1l);
    cudaGetSymbolAddress((void**)&h1h, g_h1h); cudaGetSymbolAddress((void**)&h1l, g_h1l);
    cudaGetSymbolAddress((void**)&wqh, g_wqTh); cudaGetSymbolAddress((void**)&wql, g_wqTl);
    cudaGetSymbolAddress((void**)&wkh, g_wkTh); cudaGetSymbolAddress((void**)&wkl, g_wkTl);
    cudaGetSymbolAddress((void**)&wvh, g_wvTh); cudaGetSymbolAddress((void**)&wvl, g_wvTl);
    cudaGetSymbolAddress((void**)&woh, g_woTh); cudaGetSymbolAddress((void**)&wol, g_woTl);
    cudaGetSymbolAddress((void**)&w1h, g_w1Th); cudaGetSymbolAddress((void**)&w1l, g_w1Tl);
    cudaGetSymbolAddress((void**)&w2h, g_w2Th); cudaGetSymbolAddress((void**)&w2l, g_w2Tl);

    cudaFuncSetAttribute(gemm_pk_kernel, cudaFuncAttributeMaxDynamicSharedMemorySize, GEMM_SMEM);
    cudaFuncSetAttribute(gemm_qkv_kernel, cudaFuncAttributeMaxDynamicSharedMemorySize, GEMM_SMEM);
    cudaFuncSetAttribute(flash_attn_pk_kernel, cudaFuncAttributeMaxDynamicSharedMemorySize, FA_SMEM);

    // single fused pack launch (state + 6 weights)
    const int pack_blocks = PK_ROWS_BLKS + 4 * PK_E_BLKS + 2 * PK_F_BLKS;   // 13056
    pack_all_kernel<<<pack_blocks, 256>>>(state, Wq, Wk, Wv, Wo, W1, W2,
                                          sth, stl, wqh, wql, wkh, wkl, wvh, wvl,
                                          woh, wol, w1h, w1l, w2h, w2l);

    dim3 gQKV(18, M_ / 128);
    dim3 gE(E_ / 128, M_ / 128);
    dim3 gF(F_ / 128, M_ / 128);

    // fused QKV projection
    gemm_qkv_kernel<<<gQKV, 256, GEMM_SMEM>>>(sth, stl, wqh, wql, wkh, wkl, wvh, wvl,
                                              bq, bk, bv, qh, ql, kh, kl, vp);

    // attention -> packed ctx
    flash_attn_pk_kernel<<<dim3(T_ / 128, B_ * H_), 256, FA_SMEM>>>(qh, ql, kh, kl, vp, mask, ch, cl);

    // output projection + LN1
    gemm_pk_kernel<<<gE, 256, GEMM_SMEM>>>(ch, cl, woh, wol, bo, t0p, nullptr, nullptr, EH, E_, 0, 0, 1.f);
    add_ln_pack_kernel<<<M_, 128>>>(t0p, state, ln1g, ln1b, x1p, x1h, x1l);

    // FFN + LN2
    gemm_pk_kernel<<<gF, 256, GEMM_SMEM>>>(x1h, x1l, w1h, w1l, b1, nullptr, h1h, h1l, EH, F_, 1, 1, 1.f);
    gemm_pk_kernel<<<gE, 256, GEMM_SMEM>>>(h1h, h1l, w2h, w2l, b2, t0p, nullptr, nullptr, FH, E_, 0, 0, 1.f);
    add_ln_kernel<<<M_, 256>>>(t0p, x1p, ln2g, ln2b, out);
}

// round 16
// speedup vs baseline: 3.2347x; 1.0001x over previous
#include <cuda_runtime.h>
#include <cuda_bf16.h>
#include <math.h>
#include <stdint.h>

// Problem constants
#define T_ 2048
#define B_ 2
#define E_ 768
#define H_ 12
#define D_ 64
#define F_ 3072
#define M_ (T_ * B_)   // 4096 rows
#define EH (E_ / 2)
#define FH (F_ / 2)

// ---------------------------------------------------------------------------
// Scratch (device globals — no cudaMalloc allowed)
// ---------------------------------------------------------------------------
__device__ uint32_t g_sth[M_ * EH], g_stl[M_ * EH];   // packed state
__device__ uint32_t g_qh[M_ * EH],  g_ql[M_ * EH];    // packed Q (pre-scaled 1/8)
__device__ uint32_t g_kh[M_ * EH],  g_kl[M_ * EH];    // packed K
__device__ float    g_v[M_ * E_];                     // V fp32
__device__ uint32_t g_ch[M_ * EH],  g_cl[M_ * EH];    // packed ctx
__device__ float    g_t0[M_ * E_];                    // attn_out / ffn_out fp32
__device__ float    g_x1[M_ * E_];                    // LN1 out fp32 (residual)
__device__ uint32_t g_x1h[M_ * EH], g_x1l[M_ * EH];   // LN1 out packed
__device__ uint32_t g_h1h[M_ * FH], g_h1l[M_ * FH];   // FFN hidden packed
// pre-split transposed weights: [N][K/2]
__device__ uint32_t g_wqTh[E_ * EH], g_wqTl[E_ * EH];
__device__ uint32_t g_wkTh[E_ * EH], g_wkTl[E_ * EH];
__device__ uint32_t g_wvTh[E_ * EH], g_wvTl[E_ * EH];
__device__ uint32_t g_woTh[E_ * EH], g_woTl[E_ * EH];
__device__ uint32_t g_w1Th[F_ * EH], g_w1Tl[F_ * EH];
__device__ uint32_t g_w2Th[E_ * FH], g_w2Tl[E_ * FH];

// ---------------------------------------------------------------------------
// Helpers (baseline PTX only — compute_103 virtual arch)
// ---------------------------------------------------------------------------
__device__ __forceinline__ uint32_t smem_u32(const void* p) {
    uint32_t a;
    asm("{ .reg .u64 t; cvta.to.shared.u64 t, %1; cvt.u32.u64 %0, t; }" : "=r"(a) : "l"(p));
    return a;
}
__device__ __forceinline__ void cp16(uint32_t dst, const void* src) {
    asm volatile("cp.async.cg.shared.global [%0], [%1], 16;" :: "r"(dst), "l"(src));
}
#define CP_COMMIT() asm volatile("cp.async.commit_group;" ::: "memory")
#define CP_WAIT(n)  asm volatile("cp.async.wait_group %0;" :: "n"(n) : "memory")

__device__ __forceinline__ void bsplit(float x, float y, uint32_t& hi, uint32_t& lo) {
    __nv_bfloat162 h = __floats2bfloat162_rn(x, y);
    const float hx = __low2float(h), hy = __high2float(h);
    __nv_bfloat162 l = __floats2bfloat162_rn(x - hx, y - hy);
    hi = *reinterpret_cast<uint32_t*>(&h);
    lo = *reinterpret_cast<uint32_t*>(&l);
}

__device__ __forceinline__ void mma_bf16(float* d, const uint32_t* a, const uint32_t* b) {
    asm volatile("mma.sync.aligned.m16n8k16.row.col.f32.bf16.bf16.f32 "
                 "{%0,%1,%2,%3}, {%4,%5,%6,%7}, {%8,%9}, {%0,%1,%2,%3};"
                 : "+f"(d[0]), "+f"(d[1]), "+f"(d[2]), "+f"(d[3])
                 : "r"(a[0]), "r"(a[1]), "r"(a[2]), "r"(a[3]), "r"(b[0]), "r"(b[1]));
}

__device__ __forceinline__ void ldm4(uint32_t& r0, uint32_t& r1, uint32_t& r2,
                                     uint32_t& r3, uint32_t a) {
    asm volatile("ldmatrix.sync.aligned.m8n8.x4.shared.b16 {%0,%1,%2,%3}, [%4];"
                 : "=r"(r0), "=r"(r1), "=r"(r2), "=r"(r3) : "r"(a));
}

// ---------------------------------------------------------------------------
// Fused pack kernel: pack_rows (region 0) + 6x transpose-pack (regions 1..6).
// Single launch to avoid per-launch latency of 7 tiny kernels.
// ---------------------------------------------------------------------------
#define PK_ROWS_BLKS (M_ * EH / 256)      // 6144
#define PK_E_BLKS 576                      // 24x24 per ExE weight
#define PK_F_BLKS 2304                     // 96x24 / 24x96

__global__ void __launch_bounds__(256)
pack_all_kernel(const float* __restrict__ state,
                const float* __restrict__ Wq, const float* __restrict__ Wk,
                const float* __restrict__ Wv, const float* __restrict__ Wo,
                const float* __restrict__ W1, const float* __restrict__ W2,
                uint32_t* __restrict__ sth, uint32_t* __restrict__ stl,
                uint32_t* __restrict__ wqh, uint32_t* __restrict__ wql,
                uint32_t* __restrict__ wkh, uint32_t* __restrict__ wkl,
                uint32_t* __restrict__ wvh, uint32_t* __restrict__ wvl,
                uint32_t* __restrict__ woh, uint32_t* __restrict__ wol,
                uint32_t* __restrict__ w1h, uint32_t* __restrict__ w1l,
                uint32_t* __restrict__ w2h, uint32_t* __restrict__ w2l)
{
    __shared__ float t[32][33];
    const int tid = threadIdx.x;
    int bid = blockIdx.x;

    if (bid < PK_ROWS_BLKS) {
        const int i = bid * 256 + tid;
        const float2 v = *(const float2*)&state[2 * i];
        uint32_t hi, lo;
        bsplit(v.x, v.y, hi, lo);
        sth[i] = hi;
        stl[i] = lo;
        return;
    }
    bid -= PK_ROWS_BLKS;

    const float* in;
    uint32_t *oh, *ol;
    int R, gx, C, idx;
    if (bid < PK_E_BLKS)          { in = Wq; oh = wqh; ol = wql; R = E_; C = E_; gx = 24; idx = bid; }
    else if (bid < 2 * PK_E_BLKS) { in = Wk; oh = wkh; ol = wkl; R = E_; C = E_; gx = 24; idx = bid - PK_E_BLKS; }
    else if (bid < 3 * PK_E_BLKS) { in = Wv; oh = wvh; ol = wvl; R = E_; C = E_; gx = 24; idx = bid - 2 * PK_E_BLKS; }
    else if (bid < 4 * PK_E_BLKS) { in = Wo; oh = woh; ol = wol; R = E_; C = E_; gx = 24; idx = bid - 3 * PK_E_BLKS; }
    else if (bid < 4 * PK_E_BLKS + PK_F_BLKS)
                                  { in = W1; oh = w1h; ol = w1l; R = E_; C = F_; gx = 96; idx = bid - 4 * PK_E_BLKS; }
    else                          { in = W2; oh = w2h; ol = w2l; R = F_; C = E_; gx = 24; idx = bid - 4 * PK_E_BLKS - PK_F_BLKS; }

    const int bx = (idx % gx) * 32;   // n offset
    const int by = (idx / gx) * 32;   // k offset
    const int x = tid & 31, y = tid >> 5;
#pragma unroll
    for (int j = 0; j < 32; j += 8)
        t[y + j][x] = in[(size_t)(by + y + j) * C + bx + x];
    __syncthreads();
    const int KH2 = R >> 1;
#pragma unroll
    for (int i = 0; i < 2; i++) {
        const int n = (tid >> 4) + i * 16;
        const int kp = tid & 15;
        uint32_t hi, lo;
        bsplit(t[2 * kp][n], t[2 * kp + 1][n], hi, lo);
        oh[(size_t)(bx + n) * KH2 + (by >> 1) + kp] = hi;
        ol[(size_t)(bx + n) * KH2 + (by >> 1) + kp] = lo;
    }
}

// ---------------------------------------------------------------------------
// Shared GEMM mainloop core, ONE barrier per K-iter.
// ---------------------------------------------------------------------------
#define GP_STR 20
#define GP_TILE (128 * GP_STR)          // 2560 u32
#define GP_STAGE (4 * GP_TILE)          // Ah,Al,Bh,Bl
#define GEMM_SMEM (2 * GP_STAGE * 4)    // 81920 bytes

__device__ __forceinline__ void gemm_core(
    const uint32_t* __restrict__ Ah, const uint32_t* __restrict__ Al,
    const uint32_t* __restrict__ Bh, const uint32_t* __restrict__ Bl,
    int KH, int by, int bx, uint32_t sb, int tid, float acc[4][4][4])
{
    const int wid = tid >> 5, lane = tid & 31;
    const int warp_m = (wid >> 2) * 64;
    const int warp_n = (wid & 3) * 32;

    const int arow_l = warp_m + (lane & 15);
    const int acol_l = (lane >> 4) << 2;
    const int brow_l = warp_n + (lane & 7) + ((lane >> 4) << 3);
    const int bcol_l = ((lane >> 3) & 1) << 2;

    const int NT = KH / 16;

    auto load_stage = [&](int buf, int kt) {
        const uint32_t base = sb + (uint32_t)(buf * GP_STAGE) * 4u;
#pragma unroll
        for (int i = 0; i < 2; i++) {
            const int id = tid + i * 256;
            const int row = id >> 2, c4 = id & 3;
            const uint32_t so = (uint32_t)(row * GP_STR + c4 * 4) * 4u;
            const size_t ga = (size_t)(by + row) * KH + kt * 16 + c4 * 4;
            const size_t gb = (size_t)(bx + row) * KH + kt * 16 + c4 * 4;
            cp16(base + so, &Ah[ga]);
            cp16(base + (uint32_t)(GP_TILE * 4) + so, &Al[ga]);
            cp16(base + (uint32_t)(2 * GP_TILE * 4) + so, &Bh[gb]);
            cp16(base + (uint32_t)(3 * GP_TILE * 4) + so, &Bl[gb]);
        }
        CP_COMMIT();
    };

    load_stage(0, 0);

    for (int kt = 0; kt < NT; kt++) {
        CP_WAIT(0);
        __syncthreads();   // buf[kt&1] visible; all threads done computing buf[kt&1] last round
        if (kt + 1 < NT) load_stage((kt + 1) & 1, kt + 1);   // fills other buffer, overlaps compute

        const uint32_t stg = sb + (uint32_t)((kt & 1) * GP_STAGE) * 4u;

#pragma unroll
        for (int j = 0; j < 2; j++) {
            uint32_t ah[4][4], al[4][4];
#pragma unroll
            for (int mt = 0; mt < 4; mt++) {
                const uint32_t aa = stg +
                    (uint32_t)((arow_l + mt * 16) * GP_STR + j * 8 + acol_l) * 4u;
                ldm4(ah[mt][0], ah[mt][1], ah[mt][2], ah[mt][3], aa);
                ldm4(al[mt][0], al[mt][1], al[mt][2], al[mt][3], aa + GP_TILE * 4);
            }
            uint32_t bh2[4][2], bl2[4][2];
#pragma unroll
            for (int p = 0; p < 2; p++) {
                const uint32_t ba = stg + (uint32_t)(2 * GP_TILE) * 4u +
                    (uint32_t)((brow_l + p * 16) * GP_STR + j * 8 + bcol_l) * 4u;
                ldm4(bh2[2 * p][0], bh2[2 * p][1], bh2[2 * p + 1][0], bh2[2 * p + 1][1], ba);
                ldm4(bl2[2 * p][0], bl2[2 * p][1], bl2[2 * p + 1][0], bl2[2 * p + 1][1],
                     ba + GP_TILE * 4);
            }
#pragma unroll
            for (int nt = 0; nt < 4; nt++)
#pragma unroll
                for (int mt = 0; mt < 4; mt++) {
                    mma_bf16(acc[mt][nt], ah[mt], bh2[nt]);
                    mma_bf16(acc[mt][nt], ah[mt], bl2[nt]);
                    mma_bf16(acc[mt][nt], al[mt], bh2[nt]);
                }
        }
    }
}

// generic GEMM: fp32 or packed output
__global__ void __launch_bounds__(256, 2)
gemm_pk_kernel(const uint32_t* __restrict__ Ah, const uint32_t* __restrict__ Al,
               const uint32_t* __restrict__ Bh, const uint32_t* __restrict__ Bl,
               const float* __restrict__ bias,
               float* __restrict__ outF, uint32_t* __restrict__ outH,
               uint32_t* __restrict__ outL,
               int KH, int Ndim, int packout, int relu, float scale)
{
    extern __shared__ uint32_t smu[];
    const uint32_t sb = smem_u32(smu);
    const int tid = threadIdx.x;
    const int wid = tid >> 5, lane = tid & 31;
    const int by = blockIdx.y * 128, bx = blockIdx.x * 128;
    const int warp_m = (wid >> 2) * 64, warp_n = (wid & 3) * 32;
    const int g = lane >> 2, c = lane & 3;

    float acc[4][4][4];
#pragma unroll
    for (int mt = 0; mt < 4; mt++)
#pragma unroll
        for (int nt = 0; nt < 4; nt++)
#pragma unroll
            for (int i = 0; i < 4; i++) acc[mt][nt][i] = 0.f;

    gemm_core(Ah, Al, Bh, Bl, KH, by, bx, sb, tid, acc);

    const int NH = Ndim >> 1;
#pragma unroll
    for (int mt = 0; mt < 4; mt++) {
        const int r0 = by + warp_m + mt * 16 + g;
#pragma unroll
        for (int nt = 0; nt < 4; nt++) {
            const int c0 = bx + warp_n + nt * 8 + 2 * c;
            const float b0 = bias[c0], b1 = bias[c0 + 1];
            float v00 = (acc[mt][nt][0] + b0) * scale;
            float v01 = (acc[mt][nt][1] + b1) * scale;
            float v10 = (acc[mt][nt][2] + b0) * scale;
            float v11 = (acc[mt][nt][3] + b1) * scale;
            if (relu) {
                v00 = fmaxf(v00, 0.f); v01 = fmaxf(v01, 0.f);
                v10 = fmaxf(v10, 0.f); v11 = fmaxf(v11, 0.f);
            }
            if (packout) {
                uint32_t hi, lo;
                bsplit(v00, v01, hi, lo);
                outH[(size_t)r0 * NH + (c0 >> 1)] = hi;
                outL[(size_t)r0 * NH + (c0 >> 1)] = lo;
                bsplit(v10, v11, hi, lo);
                outH[(size_t)(r0 + 8) * NH + (c0 >> 1)] = hi;
                outL[(size_t)(r0 + 8) * NH + (c0 >> 1)] = lo;
            } else {
                float2 w0, w1;
                w0.x = v00; w0.y = v01; w1.x = v10; w1.y = v11;
                *(float2*)&outF[(size_t)r0 * Ndim + c0] = w0;
                *(float2*)&outF[(size_t)(r0 + 8) * Ndim + c0] = w1;
            }
        }
    }
}

// fused QKV GEMM: blockIdx.x region-dispatch (0..5 Q, 6..11 K, 12..17 V)
__global__ void __launch_bounds__(256, 2)
gemm_qkv_kernel(const uint32_t* __restrict__ Ah, const uint32_t* __restrict__ Al,
                const uint32_t* __restrict__ wqh, const uint32_t* __restrict__ wql,
                const uint32_t* __restrict__ wkh, const uint32_t* __restrict__ wkl,
                const uint32_t* __restrict__ wvh, const uint32_t* __restrict__ wvl,
                const float* __restrict__ bq, const float* __restrict__ bk,
                const float* __restrict__ bv,
                uint32_t* __restrict__ qh, uint32_t* __restrict__ ql,
                uint32_t* __restrict__ kh, uint32_t* __restrict__ kl,
                float* __restrict__ vout)
{
    extern __shared__ uint32_t smu[];
    const uint32_t sb = smem_u32(smu);
    const int region = blockIdx.x / 6;
    const int bx = (blockIdx.x % 6) * 128;
    const int by = blockIdx.y * 128;
    const uint32_t* Bh = (region == 0) ? wqh : (region == 1) ? wkh : wvh;
    const uint32_t* Bl = (region == 0) ? wql : (region == 1) ? wkl : wvl;
    const float* bias = (region == 0) ? bq : (region == 1) ? bk : bv;
    const float scale = (region == 0) ? 0.125f : 1.f;

    const int tid = threadIdx.x;
    const int wid = tid >> 5, lane = tid & 31;
    const int warp_m = (wid >> 2) * 64, warp_n = (wid & 3) * 32;
    const int g = lane >> 2, c = lane & 3;

    float acc[4][4][4];
#pragma unroll
    for (int mt = 0; mt < 4; mt++)
#pragma unroll
        for (int nt = 0; nt < 4; nt++)
#pragma unroll
            for (int i = 0; i < 4; i++) acc[mt][nt][i] = 0.f;

    gemm_core(Ah, Al, Bh, Bl, EH, by, bx, sb, tid, acc);

    uint32_t* outH = (region == 0) ? qh : kh;
    uint32_t* outL = (region == 0) ? ql : kl;
#pragma unroll
    for (int mt = 0; mt < 4; mt++) {
        const int r0 = by + warp_m + mt * 16 + g;
#pragma unroll
        for (int nt = 0; nt < 4; nt++) {
            const int c0 = bx + warp_n + nt * 8 + 2 * c;
            const float b0 = bias[c0], b1 = bias[c0 + 1];
            const float v00 = (acc[mt][nt][0] + b0) * scale;
            const float v01 = (acc[mt][nt][1] + b1) * scale;
            const float v10 = (acc[mt][nt][2] + b0) * scale;
            const float v11 = (acc[mt][nt][3] + b1) * scale;
            if (region < 2) {
                uint32_t hi, lo;
                bsplit(v00, v01, hi, lo);
                outH[(size_t)r0 * EH + (c0 >> 1)] = hi;
                outL[(size_t)r0 * EH + (c0 >> 1)] = lo;
                bsplit(v10, v11, hi, lo);
                outH[(size_t)(r0 + 8) * EH + (c0 >> 1)] = hi;
                outL[(size_t)(r0 + 8) * EH + (c0 >> 1)] = lo;
            } else {
                float2 w0, w1;
                w0.x = v00; w0.y = v01; w1.x = v10; w1.y = v11;
                *(float2*)&vout[(size_t)r0 * E_ + c0] = w0;
                *(float2*)&vout[(size_t)(r0 + 8) * E_ + c0] = w1;
            }
        }
    }
}

// ---------------------------------------------------------------------------
// Tensor-core flash attention. Mask precomputed once (bytes + per-tile skip
// flags in smem); 2 barriers per live key tile, 1 per skipped tile.
// ---------------------------------------------------------------------------
#define FP_STR 36
#define FQH 0
#define FQL (FQH + 128 * FP_STR)
#define FKH (FQL + 128 * FP_STR)
#define FKL (FKH + 64 * FP_STR)
#define FVH (FKL + 64 * FP_STR)
#define FVL (FVH + 64 * FP_STR)
#define FMKB (FVL + 64 * FP_STR)          // 2048 mask bytes = 512 words
#define FSKIP (FMKB + 512)                // 32 skip flags
#define FA_SMEM ((FSKIP + 32) * 4)

__global__ void __launch_bounds__(256, 2)
flash_attn_pk_kernel(const uint32_t* __restrict__ Qh, const uint32_t* __restrict__ Ql,
                     const uint32_t* __restrict__ Kh, const uint32_t* __restrict__ Kl,
                     const float* __restrict__ V, const int* __restrict__ mask,
                     uint32_t* __restrict__ ctxh, uint32_t* __restrict__ ctxl)
{
    extern __shared__ uint32_t us[];
    const uint32_t sbF = smem_u32(us);
    char* mkb = (char*)(us + FMKB);
    int* skip = (int*)(us + FSKIP);

    const int t0 = blockIdx.x * 128;
    const int b = blockIdx.y / H_;
    const int h = blockIdx.y % H_;
    const int tid = threadIdx.x;
    const int w = tid >> 5, lane = tid & 31;
    const int g = lane >> 2, c = lane & 3;
    const int wm = w * 16;

    const int qrow_l = wm + (lane & 15);
    const int qcol_l = (lane >> 4) << 2;
    const int krow_l = (lane & 7) + ((lane >> 4) << 3);
    const int kcol_l = ((lane >> 3) & 1) << 2;

    // ---- one-time: Q tile + mask bytes + per-tile skip flags ----
#pragma unroll
    for (int i = 0; i < 4; i++) {
        const int id = tid + i * 256;
        const int r = id >> 3, c4 = (id & 7) * 4;
        const size_t go = ((size_t)(t0 + r) * B_ + b) * EH + h * 32 + c4;
        *(uint4*)&us[FQH + r * FP_STR + c4] = *(const uint4*)&Qh[go];
        *(uint4*)&us[FQL + r * FP_STR + c4] = *(const uint4*)&Ql[go];
    }
#pragma unroll
    for (int i = 0; i < 8; i++)
        mkb[tid + i * 256] = (char)(mask[(size_t)b * T_ + tid + i * 256] != 0);
    __syncthreads();
    if (tid < 32) {
        int all = 1;
#pragma unroll
        for (int j = 0; j < 64; j++) all &= (int)mkb[tid * 64 + j];
        skip[tid] = all;
    }
    __syncthreads();

    float o[8][4];
#pragma unroll
    for (int nt = 0; nt < 8; nt++)
#pragma unroll
        for (int i = 0; i < 4; i++) o[nt][i] = 0.f;
    float m0 = -INFINITY, m1 = -INFINITY, l0s = 0.f, l1s = 0.f;

    for (int s0 = 0; s0 < T_; s0 += 64) {
        __syncthreads();   // K/V buffer reuse barrier
        if (skip[s0 >> 6]) continue;   // uniform smem read, whole block skips

        // packed K tile [64 x 32 kp] hi+lo
#pragma unroll
        for (int i = 0; i < 2; i++) {
            const int id = tid + i * 256;
            const int r = id >> 3, c4 = (id & 7) * 4;
            const size_t go = ((size_t)(s0 + r) * B_ + b) * EH + h * 32 + c4;
            *(uint4*)&us[FKH + r * FP_STR + c4] = *(const uint4*)&Kh[go];
            *(uint4*)&us[FKL + r * FP_STR + c4] = *(const uint4*)&Kl[go];
        }
        // V tile transposed + split: Vt[d][key-pair]
#pragma unroll
        for (int i = 0; i < 2; i++) {
            const int id = tid + i * 256;
            const int kp = id & 31, dblk = id >> 5;
            const float4 va = *(const float4*)&V[((size_t)(s0 + 2 * kp) * B_ + b) * E_ + h * 64 + dblk * 4];
            const float4 vb = *(const float4*)&V[((size_t)(s0 + 2 * kp + 1) * B_ + b) * E_ + h * 64 + dblk * 4];
            uint32_t hi, lo;
            bsplit(va.x, vb.x, hi, lo);
            us[FVH + (dblk * 4 + 0) * FP_STR + kp] = hi; us[FVL + (dblk * 4 + 0) * FP_STR + kp] = lo;
            bsplit(va.y, vb.y, hi, lo);
            us[FVH + (dblk * 4 + 1) * FP_STR + kp] = hi; us[FVL + (dblk * 4 + 1) * FP_STR + kp] = lo;
            bsplit(va.z, vb.z, hi, lo);
            us[FVH + (dblk * 4 + 2) * FP_STR + kp] = hi; us[FVL + (dblk * 4 + 2) * FP_STR + kp] = lo;
            bsplit(va.w, vb.w, hi, lo);
            us[FVH + (dblk * 4 + 3) * FP_STR + kp] = hi; us[FVL + (dblk * 4 + 3) * FP_STR + kp] = lo;
        }
        __syncthreads();

        // ---- S = (Q/8) K^T ----
        float sa[8][4];
#pragma unroll
        for (int nt = 0; nt < 8; nt++)
#pragma unroll
            for (int i = 0; i < 4; i++) sa[nt][i] = 0.f;

#pragma unroll
        for (int j = 0; j < 4; j++) {
            uint32_t qh[4], ql[4];
            const uint32_t qa = sbF + (uint32_t)(FQH + qrow_l * FP_STR + j * 8 + qcol_l) * 4u;
            ldm4(qh[0], qh[1], qh[2], qh[3], qa);
            ldm4(ql[0], ql[1], ql[2], ql[3], qa + (FQL - FQH) * 4);
#pragma unroll
            for (int p = 0; p < 4; p++) {
                uint32_t bh2[2][2], bl2[2][2];
                const uint32_t ka = sbF +
                    (uint32_t)(FKH + (krow_l + p * 16) * FP_STR + j * 8 + kcol_l) * 4u;
                ldm4(bh2[0][0], bh2[0][1], bh2[1][0], bh2[1][1], ka);
                ldm4(bl2[0][0], bl2[0][1], bl2[1][0], bl2[1][1], ka + (FKL - FKH) * 4);
                mma_bf16(sa[2 * p], qh, bh2[0]);
                mma_bf16(sa[2 * p], qh, bl2[0]);
                mma_bf16(sa[2 * p], ql, bh2[0]);
                mma_bf16(sa[2 * p + 1], qh, bh2[1]);
                mma_bf16(sa[2 * p + 1], qh, bl2[1]);
                mma_bf16(sa[2 * p + 1], ql, bh2[1]);
            }
        }

        // ---- online softmax (mask from precomputed bytes) ----
        float mx0 = -INFINITY, mx1 = -INFINITY;
#pragma unroll
        for (int nt = 0; nt < 8; nt++) {
            const int col0 = s0 + nt * 8 + 2 * c, col1 = col0 + 1;
            const bool k0m = mkb[col0] != 0, k1m = mkb[col1] != 0;
            float s0v = sa[nt][0]; if (k0m) s0v = -INFINITY;
            float s1v = sa[nt][1]; if (k1m) s1v = -INFINITY;
            float s2v = sa[nt][2]; if (k0m) s2v = -INFINITY;
            float s3v = sa[nt][3]; if (k1m) s3v = -INFINITY;
            sa[nt][0] = s0v; sa[nt][1] = s1v; sa[nt][2] = s2v; sa[nt][3] = s3v;
            mx0 = fmaxf(mx0, fmaxf(s0v, s1v));
            mx1 = fmaxf(mx1, fmaxf(s2v, s3v));
        }
        mx0 = fmaxf(mx0, __shfl_xor_sync(0xffffffffu, mx0, 1));
        mx0 = fmaxf(mx0, __shfl_xor_sync(0xffffffffu, mx0, 2));
        mx1 = fmaxf(mx1, __shfl_xor_sync(0xffffffffu, mx1, 1));
        mx1 = fmaxf(mx1, __shfl_xor_sync(0xffffffffu, mx1, 2));

        const float mn0 = fmaxf(m0, mx0), mn1 = fmaxf(m1, mx1);
        const float al0 = __expf(m0 - mn0), al1 = __expf(m1 - mn1);
        m0 = mn0; m1 = mn1;

        uint32_t phl[8], phh[8], pll[8], plh[8];
        float su0 = 0.f, su1 = 0.f;
#pragma unroll
        for (int nt = 0; nt < 8; nt++) {
            const float p0 = __expf(sa[nt][0] - mn0);
            const float p1 = __expf(sa[nt][1] - mn0);
            const float p2 = __expf(sa[nt][2] - mn1);
            const float p3 = __expf(sa[nt][3] - mn1);
            su0 += p0 + p1; su1 += p2 + p3;
            bsplit(p0, p1, phl[nt], pll[nt]);
            bsplit(p2, p3, phh[nt], plh[nt]);
        }
        su0 += __shfl_xor_sync(0xffffffffu, su0, 1);
        su0 += __shfl_xor_sync(0xffffffffu, su0, 2);
        su1 += __shfl_xor_sync(0xffffffffu, su1, 1);
        su1 += __shfl_xor_sync(0xffffffffu, su1, 2);
        l0s = l0s * al0 + su0;
        l1s = l1s * al1 + su1;
#pragma unroll
        for (int nt = 0; nt < 8; nt++) {
            o[nt][0] *= al0; o[nt][1] *= al0;
            o[nt][2] *= al1; o[nt][3] *= al1;
        }

        // ---- O += P V ----
#pragma unroll
        for (int j = 0; j < 4; j++) {
            uint32_t ah[4], al2[4];
            ah[0] = phl[2 * j];     ah[1] = phh[2 * j];
            ah[2] = phl[2 * j + 1]; ah[3] = phh[2 * j + 1];
            al2[0] = pll[2 * j];     al2[1] = plh[2 * j];
            al2[2] = pll[2 * j + 1]; al2[3] = plh[2 * j + 1];
#pragma unroll
            for (int p = 0; p < 4; p++) {
                uint32_t bh2[2][2], bl2[2][2];
                const uint32_t va = sbF +
                    (uint32_t)(FVH + (krow_l + p * 16) * FP_STR + j * 8 + kcol_l) * 4u;
                ldm4(bh2[0][0], bh2[0][1], bh2[1][0], bh2[1][1], va);
                ldm4(bl2[0][0], bl2[0][1], bl2[1][0], bl2[1][1], va + (FVL - FVH) * 4);
                mma_bf16(o[2 * p], ah, bh2[0]);
                mma_bf16(o[2 * p], ah, bl2[0]);
                mma_bf16(o[2 * p], al2, bh2[0]);
                mma_bf16(o[2 * p + 1], ah, bh2[1]);
                mma_bf16(o[2 * p + 1], ah, bl2[1]);
                mma_bf16(o[2 * p + 1], al2, bh2[1]);
            }
        }
    }

    // writeout: packed ctx
    const float i0 = 1.f / l0s, i1 = 1.f / l1s;
#pragma unroll
    for (int nt = 0; nt < 8; nt++) {
        const int kp = h * 32 + nt * 4 + c;
        uint32_t hi, lo;
        bsplit(o[nt][0] * i0, o[nt][1] * i0, hi, lo);
        ctxh[((size_t)(t0 + wm + g) * B_ + b) * EH + kp] = hi;
        ctxl[((size_t)(t0 + wm + g) * B_ + b) * EH + kp] = lo;
        bsplit(o[nt][2] * i1, o[nt][3] * i1, hi, lo);
        ctxh[((size_t)(t0 + wm + g + 8) * B_ + b) * EH + kp] = hi;
        ctxl[((size_t)(t0 + wm + g + 8) * B_ + b) * EH + kp] = lo;
    }
}

// ---------------------------------------------------------------------------
// Fused add-residual + LayerNorm
// ---------------------------------------------------------------------------
__device__ __forceinline__ float warpReduceSum(float v) {
#pragma unroll
    for (int o = 16; o; o >>= 1) v += __shfl_xor_sync(0xffffffffu, v, o);
    return v;
}

__global__ void __launch_bounds__(256)
add_ln_kernel(const float* __restrict__ a, const float* __restrict__ r,
              const float* __restrict__ g, const float* __restrict__ be,
              float* __restrict__ out)
{
    const int row = blockIdx.x;
    const int tid = threadIdx.x;
    const float* pa = a + (size_t)row * E_;
    const float* pr = r + (size_t)row * E_;

    float v0 = pa[tid] + pr[tid];
    float v1 = pa[tid + 256] + pr[tid + 256];
    float v2 = pa[tid + 512] + pr[tid + 512];

    __shared__ float red[8];
    const int wid = tid >> 5, lane = tid & 31;

    float s = warpReduceSum(v0 + v1 + v2);
    if (lane == 0) red[wid] = s;
    __syncthreads();
    float tot = 0.f;
#pragma unroll
    for (int i = 0; i < 8; i++) tot += red[i];
    const float mean = tot * (1.f / (float)E_);

    float d0 = v0 - mean, d1 = v1 - mean, d2 = v2 - mean;
    float sq = warpReduceSum(d0 * d0 + d1 * d1 + d2 * d2);
    __syncthreads();
    if (lane == 0) red[wid] = sq;
    __syncthreads();
    tot = 0.f;
#pragma unroll
    for (int i = 0; i < 8; i++) tot += red[i];
    const float inv = rsqrtf(tot * (1.f / (float)E_) + 1e-5f);

    float* po = out + (size_t)row * E_;
    po[tid]       = d0 * inv * g[tid]       + be[tid];
    po[tid + 256] = d1 * inv * g[tid + 256] + be[tid + 256];
    po[tid + 512] = d2 * inv * g[tid + 512] + be[tid + 512];
}

__global__ void __launch_bounds__(128)
add_ln_pack_kernel(const float* __restrict__ a, const float* __restrict__ r,
                   const float* __restrict__ g, const float* __restrict__ be,
                   float* __restrict__ outF, uint32_t* __restrict__ outH,
                   uint32_t* __restrict__ outL)
{
    const int row = blockIdx.x;
    const int tid = threadIdx.x;
    const float* pa = a + (size_t)row * E_;
    const float* pr = r + (size_t)row * E_;

    float2 v[3];
#pragma unroll
    for (int i = 0; i < 3; i++) {
        const int o = 2 * (tid + i * 128);
        const float2 x = *(const float2*)&pa[o];
        const float2 y = *(const float2*)&pr[o];
        v[i].x = x.x + y.x;
        v[i].y = x.y + y.y;
    }

    __shared__ float red[4];
    const int wid = tid >> 5, lane = tid & 31;

    float s = warpReduceSum(v[0].x + v[0].y + v[1].x + v[1].y + v[2].x + v[2].y);
    if (lane == 0) red[wid] = s;
    __syncthreads();
    float tot = red[0] + red[1] + red[2] + red[3];
    const float mean = tot * (1.f / (float)E_);

    float sq = 0.f;
#pragma unroll
    for (int i = 0; i < 3; i++) {
        v[i].x -= mean; v[i].y -= mean;
        sq += v[i].x * v[i].x + v[i].y * v[i].y;
    }
    sq = warpReduceSum(sq);
    __syncthreads();
    if (lane == 0) red[wid] = sq;
    __syncthreads();
    tot = red[0] + red[1] + red[2] + red[3];
    const float inv = rsqrtf(tot * (1.f / (float)E_) + 1e-5f);

    float* po = outF + (size_t)row * E_;
    uint32_t* ph = outH + (size_t)row * EH;
    uint32_t* pl = outL + (size_t)row * EH;
#pragma unroll
    for (int i = 0; i < 3; i++) {
        const int p = tid + i * 128;
        const float2 gg = *(const float2*)&g[2 * p];
        const float2 bb = *(const float2*)&be[2 * p];
        float2 w;
        w.x = v[i].x * inv * gg.x + bb.x;
        w.y = v[i].y * inv * gg.y + bb.y;
        *(float2*)&po[2 * p] = w;
        uint32_t hi, lo;
        bsplit(w.x, w.y, hi, lo);
        ph[p] = hi;
        pl[p] = lo;
    }
}

// ---------------------------------------------------------------------------
// Launch
// ---------------------------------------------------------------------------
extern "C" void kernel_launch(void* const* d_in, const int* in_sizes, int n_in,
                              void* d_out, int out_size)
{
    const float* state = (const float*)d_in[0];
    const int* mask = (const int*)d_in[1];
    const float* Wq = (const float*)d_in[2];
    const float* bq = (const float*)d_in[3];
    const float* Wk = (const float*)d_in[4];
    const float* bk = (const float*)d_in[5];
    const float* Wv = (const float*)d_in[6];
    const float* bv = (const float*)d_in[7];
    const float* Wo = (const float*)d_in[8];
    const float* bo = (const float*)d_in[9];
    const float* ln1g = (const float*)d_in[10];
    const float* ln1b = (const float*)d_in[11];
    const float* W1 = (const float*)d_in[12];
    const float* b1 = (const float*)d_in[13];
    const float* W2 = (const float*)d_in[14];
    const float* b2 = (const float*)d_in[15];
    const float* ln2g = (const float*)d_in[16];
    const float* ln2b = (const float*)d_in[17];
    float* out = (float*)d_out;

    uint32_t *sth, *stl, *qh, *ql, *kh, *kl, *ch, *cl, *x1h, *x1l, *h1h, *h1l;
    float *vp, *t0p, *x1p;
    uint32_t *wqh, *wql, *wkh, *wkl, *wvh, *wvl, *woh, *wol, *w1h, *w1l, *w2h, *w2l;
    cudaGetSymbolAddress((void**)&sth, g_sth); cudaGetSymbolAddress((void**)&stl, g_stl);
    cudaGetSymbolAddress((void**)&qh, g_qh);   cudaGetSymbolAddress((void**)&ql, g_ql);
    cudaGetSymbolAddress((void**)&kh, g_kh);   cudaGetSymbolAddress((void**)&kl, g_kl);
    cudaGetSymbolAddress((void**)&vp, g_v);
    cudaGetSymbolAddress((void**)&ch, g_ch);   cudaGetSymbolAddress((void**)&cl, g_cl);
    cudaGetSymbolAddress((void**)&t0p, g_t0);
    cudaGetSymbolAddress((void**)&x1p, g_x1);
    cudaGetSymbolAddress((void**)&x1h, g_x1h); cudaGetSymbolAddress((void**)&x1l, g_x1l);
    cudaGetSymbolAddress((void**)&h1h, g_h1h); cudaGetSymbolAddress((void**)&h1l, g_h1l);
    cudaGetSymbolAddress((void**)&wqh, g_wqTh); cudaGetSymbolAddress((void**)&wql, g_wqTl);
    cudaGetSymbolAddress((void**)&wkh, g_wkTh); cudaGetSymbolAddress((void**)&wkl, g_wkTl);
    cudaGetSymbolAddress((void**)&wvh, g_wvTh); cudaGetSymbolAddress((void**)&wvl, g_wvTl);
    cudaGetSymbolAddress((void**)&woh, g_woTh); cudaGetSymbolAddress((void**)&wol, g_woTl);
    cudaGetSymbolAddress((void**)&w1h, g_w1Th); cudaGetSymbolAddress((void**)&w1l, g_w1Tl);
    cudaGetSymbolAddress((void**)&w2h, g_w2Th); cudaGetSymbolAddress((void**)&w2l, g_w2Tl);

    cudaFuncSetAttribute(gemm_pk_kernel, cudaFuncAttributeMaxDynamicSharedMemorySize, GEMM_SMEM);
    cudaFuncSetAttribute(gemm_qkv_kernel, cudaFuncAttributeMaxDynamicSharedMemorySize, GEMM_SMEM);
    cudaFuncSetAttribute(flash_attn_pk_kernel, cudaFuncAttributeMaxDynamicSharedMemorySize, FA_SMEM);

    // single fused pack launch (state + 6 weights)
    const int pack_blocks = PK_ROWS_BLKS + 4 * PK_E_BLKS + 2 * PK_F_BLKS;   // 13056
    pack_all_kernel<<<pack_blocks, 256>>>(state, Wq, Wk, Wv, Wo, W1, W2,
                                          sth, stl, wqh, wql, wkh, wkl, wvh, wvl,
                                          woh, wol, w1h, w1l, w2h, w2l);

    dim3 gQKV(18, M_ / 128);
    dim3 gE(E_ / 128, M_ / 128);
    dim3 gF(F_ / 128, M_ / 128);

    // fused QKV projection
    gemm_qkv_kernel<<<gQKV, 256, GEMM_SMEM>>>(sth, stl, wqh, wql, wkh, wkl, wvh, wvl,
                                              bq, bk, bv, qh, ql, kh, kl, vp);

    // attention -> packed ctx
    flash_attn_pk_kernel<<<dim3(T_ / 128, B_ * H_), 256, FA_SMEM>>>(qh, ql, kh, kl, vp, mask, ch, cl);

    // output projection + LN1
    gemm_pk_kernel<<<gE, 256, GEMM_SMEM>>>(ch, cl, woh, wol, bo, t0p, nullptr, nullptr, EH, E_, 0, 0, 1.f);
    add_ln_pack_kernel<<<M_, 128>>>(t0p, state, ln1g, ln1b, x1p, x1h, x1l);

    // FFN + LN2
    gemm_pk_kernel<<<gF, 256, GEMM_SMEM>>>(x1h, x1l, w1h, w1l, b1, nullptr, h1h, h1l, EH, F_, 1, 1, 1.f);
    gemm_pk_kernel<<<gE, 256, GEMM_SMEM>>>(h1h, h1l, w2h, w2l, b2, t0p, nullptr, nullptr, FH, E_, 0, 0, 1.f);
    add_ln_kernel<<<M_, 256>>>(t0p, x1p, ln2g, ln2b, out);
}